// round 2
// baseline (speedup 1.0000x reference)
#include <cuda_runtime.h>

// Problem dims (fixed by the dataset)
#define NP   8192   // people == regions == N
#define FD   128    // feature dim
#define C0N  256    // hidden channels
#define C1N  128    // output channels
#define BN_EPS 1e-3f

// ---------------- scratch (device globals; no allocation allowed) -----------
__device__ __align__(16) float d_invdeg[NP];
__device__ __align__(16) float d_Rpre[NP * FD];    // A^T @ X
__device__ __align__(16) float d_H[NP * C0N];      // region pre-BN
__device__ __align__(16) float d_Rs[NP * C0N];     // invdeg * BN1(region)
__device__ __align__(16) float d_P[NP * C0N];      // A @ Rs
__device__ __align__(16) float d_O[NP * C1N];      // people pre-BN
__device__ float d_sum1[C0N], d_sq1[C0N], d_sc1[C0N], d_sh1[C0N];
__device__ float d_sum2[C1N], d_sq2[C1N], d_sc2[C1N], d_sh2[C1N];

// ---------------- k0: zero BN accumulators (graph-replay safe) --------------
__global__ void k_zero() {
    int t = threadIdx.x;
    if (t < C0N) { d_sum1[t] = 0.f; d_sq1[t] = 0.f; }
    if (t < C1N) { d_sum2[t] = 0.f; d_sq2[t] = 0.f; }
}

// ---------------- GEMM1: Rpre = A^T @ X, fused deg --------------------------
// M = NP (rows r), N = FD(=128, full), K = NP (p). Tile 64x128, Kt=16.
// A^T[r,k] = adj[k*NP + r] -> coalesced along r.
__global__ void __launch_bounds__(256) k_gemm1(const int* __restrict__ adj,
                                               const float* __restrict__ X) {
    __shared__ float As[16][64];
    __shared__ float Xs[16][128];
    const int r0  = blockIdx.x * 64;
    const int tid = threadIdx.x;
    const int tx  = tid & 15;     // col group (8 cols, stride 16)
    const int ty  = tid >> 4;     // row group (4 rows, stride 16)

    float acc[4][8] = {};
    float deg[4]    = {0.f, 0.f, 0.f, 0.f};

    const int la_k = tid >> 4;          // 16 k-rows
    const int la_r = (tid & 15) * 4;    // 4 consecutive r per thread
    const int lx_k = tid >> 4;
    const int lx_c = (tid & 15) * 8;

    for (int k0 = 0; k0 < NP; k0 += 16) {
        int4 a4 = *(const int4*)(adj + (size_t)(k0 + la_k) * NP + r0 + la_r);
        float4 af = make_float4((float)a4.x, (float)a4.y, (float)a4.z, (float)a4.w);
        *(float4*)&As[la_k][la_r] = af;

        const float* xp = X + (size_t)(k0 + lx_k) * FD + lx_c;
        *(float4*)&Xs[lx_k][lx_c]     = *(const float4*)xp;
        *(float4*)&Xs[lx_k][lx_c + 4] = *(const float4*)(xp + 4);
        __syncthreads();

#pragma unroll
        for (int kk = 0; kk < 16; kk++) {
            float a[4], b[8];
#pragma unroll
            for (int i = 0; i < 4; i++) a[i] = As[kk][ty + i * 16];
#pragma unroll
            for (int j = 0; j < 8; j++) b[j] = Xs[kk][tx + j * 16];
#pragma unroll
            for (int i = 0; i < 4; i++) {
                deg[i] += a[i];
#pragma unroll
                for (int j = 0; j < 8; j++) acc[i][j] = fmaf(a[i], b[j], acc[i][j]);
            }
        }
        __syncthreads();
    }

#pragma unroll
    for (int i = 0; i < 4; i++) {
        int r = r0 + ty + i * 16;
#pragma unroll
        for (int j = 0; j < 8; j++) d_Rpre[(size_t)r * FD + tx + j * 16] = acc[i][j];
        if (tx == 0) d_invdeg[r] = (deg[i] > 0.5f) ? (1.0f / deg[i]) : 0.0f;
    }
}

// ---------------- small GEMMs: H = invdeg*(Rpre@K1)+b1 ; O = P@K2+b2 --------
// Tile 64x64, Kt=16, thread 4x4.  SEL=0: Rpre->H, SEL=1: P->O.
template <int KDIM, int NDIM, bool SCALE, int SEL>
__global__ void __launch_bounds__(256) k_gemm_small(const float* __restrict__ B,
                                                    const float* __restrict__ bias) {
    const float* A    = (SEL == 0) ? d_Rpre : d_P;
    float*       Cout = (SEL == 0) ? d_H    : d_O;

    __shared__ float As[16][65];
    __shared__ float Bs[16][64];
    const int m0  = blockIdx.x * 64;
    const int n0  = blockIdx.y * 64;
    const int tid = threadIdx.x;
    const int tx  = tid & 15;
    const int ty  = tid >> 4;

    float acc[4][4] = {};

    const int la_m = tid >> 2;
    const int la_k = (tid & 3) * 4;
    const int lb_k = tid >> 4;
    const int lb_n = (tid & 15) * 4;

    for (int k0 = 0; k0 < KDIM; k0 += 16) {
        float4 a4 = *(const float4*)(A + (size_t)(m0 + la_m) * KDIM + k0 + la_k);
        As[la_k + 0][la_m] = a4.x;
        As[la_k + 1][la_m] = a4.y;
        As[la_k + 2][la_m] = a4.z;
        As[la_k + 3][la_m] = a4.w;
        *(float4*)&Bs[lb_k][lb_n] = *(const float4*)(B + (size_t)(k0 + lb_k) * NDIM + n0 + lb_n);
        __syncthreads();

#pragma unroll
        for (int kk = 0; kk < 16; kk++) {
            float a[4], b[4];
#pragma unroll
            for (int i = 0; i < 4; i++) a[i] = As[kk][ty + i * 16];
#pragma unroll
            for (int j = 0; j < 4; j++) b[j] = Bs[kk][tx + j * 16];
#pragma unroll
            for (int i = 0; i < 4; i++)
#pragma unroll
                for (int j = 0; j < 4; j++) acc[i][j] = fmaf(a[i], b[j], acc[i][j]);
        }
        __syncthreads();
    }

#pragma unroll
    for (int i = 0; i < 4; i++) {
        int r = m0 + ty + i * 16;
        float sc = SCALE ? d_invdeg[r] : 1.0f;
#pragma unroll
        for (int j = 0; j < 4; j++) {
            int c = n0 + tx + j * 16;
            Cout[(size_t)r * NDIM + c] = acc[i][j] * sc + bias[c];
        }
    }
}

// ---------------- GEMM3: P = A @ Rs  (M=NP, N=C0N, K=NP) --------------------
// Tile 64x128, Kt=16.  A[p,k] = adj[p*NP + k] (row-major, coalesced along k).
__global__ void __launch_bounds__(256) k_gemm3(const int* __restrict__ adj) {
    __shared__ float As[16][65];
    __shared__ float Bs[16][128];
    const int p0  = blockIdx.x * 64;
    const int c0  = blockIdx.y * 128;
    const int tid = threadIdx.x;
    const int tx  = tid & 15;
    const int ty  = tid >> 4;

    float acc[4][8] = {};

    const int la_p = tid >> 2;          // 64 rows, 4 threads each
    const int la_k = (tid & 3) * 4;     // 4 consecutive k
    const int lb_k = tid >> 4;
    const int lb_c = (tid & 15) * 8;

    for (int k0 = 0; k0 < NP; k0 += 16) {
        int4 a4 = *(const int4*)(adj + (size_t)(p0 + la_p) * NP + k0 + la_k);
        As[la_k + 0][la_p] = (float)a4.x;
        As[la_k + 1][la_p] = (float)a4.y;
        As[la_k + 2][la_p] = (float)a4.z;
        As[la_k + 3][la_p] = (float)a4.w;

        const float* bp = d_Rs + (size_t)(k0 + lb_k) * C0N + c0 + lb_c;
        *(float4*)&Bs[lb_k][lb_c]     = *(const float4*)bp;
        *(float4*)&Bs[lb_k][lb_c + 4] = *(const float4*)(bp + 4);
        __syncthreads();

#pragma unroll
        for (int kk = 0; kk < 16; kk++) {
            float a[4], b[8];
#pragma unroll
            for (int i = 0; i < 4; i++) a[i] = As[kk][ty + i * 16];
#pragma unroll
            for (int j = 0; j < 8; j++) b[j] = Bs[kk][tx + j * 16];
#pragma unroll
            for (int i = 0; i < 4; i++)
#pragma unroll
                for (int j = 0; j < 8; j++) acc[i][j] = fmaf(a[i], b[j], acc[i][j]);
        }
        __syncthreads();
    }

#pragma unroll
    for (int i = 0; i < 4; i++) {
        int p = p0 + ty + i * 16;
#pragma unroll
        for (int j = 0; j < 8; j++)
            d_P[(size_t)p * C0N + c0 + tx + j * 16] = acc[i][j];
    }
}

// ---------------- BN stats (channel sums via block partials + atomics) ------
__global__ void k_stats1() {   // grid 64, 256 threads; 128 rows per block
    int c  = threadIdx.x;
    int r0 = blockIdx.x * 128;
    float s = 0.f, q = 0.f;
#pragma unroll 4
    for (int r = r0; r < r0 + 128; r++) {
        float v = d_H[(size_t)r * C0N + c];
        s += v;
        q = fmaf(v, v, q);
    }
    atomicAdd(&d_sum1[c], s);
    atomicAdd(&d_sq1[c], q);
}

__global__ void k_stats2() {   // grid 64, 128 threads; 128 rows per block
    int c  = threadIdx.x;
    int r0 = blockIdx.x * 128;
    float s = 0.f, q = 0.f;
#pragma unroll 4
    for (int r = r0; r < r0 + 128; r++) {
        float v = d_O[(size_t)r * C1N + c];
        s += v;
        q = fmaf(v, v, q);
    }
    atomicAdd(&d_sum2[c], s);
    atomicAdd(&d_sq2[c], q);
}

__global__ void k_fin1(const float* __restrict__ gamma, const float* __restrict__ beta) {
    int c = threadIdx.x;  // 256
    float mean = d_sum1[c] * (1.0f / NP);
    float var  = d_sq1[c] * (1.0f / NP) - mean * mean;
    float sc   = gamma[c] * rsqrtf(var + BN_EPS);
    d_sc1[c] = sc;
    d_sh1[c] = beta[c] - mean * sc;
}

__global__ void k_fin2(const float* __restrict__ gamma, const float* __restrict__ beta) {
    int c = threadIdx.x;  // 128
    float mean = d_sum2[c] * (1.0f / NP);
    float var  = d_sq2[c] * (1.0f / NP) - mean * mean;
    float sc   = gamma[c] * rsqrtf(var + BN_EPS);
    d_sc2[c] = sc;
    d_sh2[c] = beta[c] - mean * sc;
}

// Rs = invdeg[r] * (H*sc1[c] + sh1[c])
__global__ void k_rs() {
    int idx = blockIdx.x * 256 + threadIdx.x;   // NP*C0N total
    int c = idx & (C0N - 1);
    int r = idx >> 8;
    d_Rs[idx] = d_invdeg[r] * fmaf(d_H[idx], d_sc1[c], d_sh1[c]);
}

// out = O*sc2[c] + sh2[c]
__global__ void k_out(float* __restrict__ out) {
    int idx = blockIdx.x * 256 + threadIdx.x;   // NP*C1N total
    int c = idx & (C1N - 1);
    out[idx] = fmaf(d_O[idx], d_sc2[c], d_sh2[c]);
}

// ---------------- launch --------------------------------------------------
extern "C" void kernel_launch(void* const* d_in, const int* in_sizes, int n_in,
                              void* d_out, int out_size) {
    const float* features = (const float*)d_in[0];
    const int*   adj      = (const int*)d_in[1];
    const float* kernel_1 = (const float*)d_in[2];
    const float* bias_1   = (const float*)d_in[3];
    const float* gamma_1  = (const float*)d_in[4];
    const float* beta_1   = (const float*)d_in[5];
    const float* kernel_2 = (const float*)d_in[6];
    const float* bias_2   = (const float*)d_in[7];
    const float* gamma_2  = (const float*)d_in[8];
    const float* beta_2   = (const float*)d_in[9];
    float* out = (float*)d_out;

    k_zero<<<1, 256>>>();
    k_gemm1<<<NP / 64, 256>>>(adj, features);                              // Rpre, invdeg
    k_gemm_small<FD, C0N, true, 0><<<dim3(NP / 64, C0N / 64), 256>>>(kernel_1, bias_1);  // H
    k_stats1<<<64, 256>>>();
    k_fin1<<<1, C0N>>>(gamma_1, beta_1);
    k_rs<<<NP * C0N / 256, 256>>>();                                       // Rs
    k_gemm3<<<dim3(NP / 64, C0N / 128), 256>>>(adj);                       // P
    k_gemm_small<C0N, C1N, false, 1><<<dim3(NP / 64, C1N / 64), 256>>>(kernel_2, bias_2); // O
    k_stats2<<<64, 128>>>();
    k_fin2<<<1, C1N>>>(gamma_2, beta_2);
    k_out<<<NP * C1N / 256, 256>>>(out);
}

// round 3
// speedup vs baseline: 1.7516x; 1.7516x over previous
#include <cuda_runtime.h>
#include <cuda_bf16.h>
#include <mma.h>

using namespace nvcuda;

// Problem dims (fixed by dataset)
#define NP   8192
#define FD   128
#define C0N  256
#define C1N  128
#define BN_EPS 1e-3f

typedef __nv_bfloat16 bf16;

// ---------------- scratch (device globals; no allocation allowed) -----------
__device__ __align__(16) float d_invdeg[NP];
__device__ __align__(16) float d_Rpre[NP * FD];     // A^T @ X (fp32)
__device__ __align__(16) float d_H[NP * C0N];       // region pre-BN
__device__ __align__(16) bf16  d_Rsh[NP * C0N];     // hi(invdeg * BN1(H))
__device__ __align__(16) bf16  d_Rsl[NP * C0N];     // lo(...)
__device__ __align__(16) float d_P[NP * C0N];       // A @ Rs
__device__ __align__(16) float d_O[NP * C1N];       // people pre-BN
__device__ float d_sum1[C0N], d_sq1[C0N], d_sc1[C0N], d_sh1[C0N];
__device__ float d_sum2[C1N], d_sq2[C1N], d_sc2[C1N], d_sh2[C1N];

// ---------------- zero BN accumulators (graph-replay safe) ------------------
__global__ void k_zero() {
    int t = threadIdx.x;
    if (t < C0N) { d_sum1[t] = 0.f; d_sq1[t] = 0.f; }
    if (t < C1N) { d_sum2[t] = 0.f; d_sq2[t] = 0.f; }
}

// ============================================================================
// GEMM1 (tensor core): Rpre = A^T @ X, fused degree.
// M=NP (r), N=FD=128 (full), K=NP. Block 64x128, BK=32, 8 warps (2M x 4N),
// warp tile 32x32 = 2x2 wmma frags. X split into bf16 hi+lo, same fp32 acc.
// A^T[r,k] = adj[k*NP + r] (r contiguous in global -> coalesced).
// ============================================================================
#define G1_BM 64
#define G1_LDA 72     // (64+8) halves, 144B row stride (multiple of 16B)
#define G1_LDX 136    // (128+8) halves, 272B

__global__ void __launch_bounds__(256) k_gemm1(const int* __restrict__ adj,
                                               const float* __restrict__ X) {
    __shared__ bf16 As[32][G1_LDA];   // [k][r]
    __shared__ bf16 Xh[32][G1_LDX];   // [k][f]
    __shared__ bf16 Xl[32][G1_LDX];

    const int r0   = blockIdx.x * G1_BM;
    const int tid  = threadIdx.x;
    const int warp = tid >> 5;
    const int wm   = warp & 1;        // 2 M-warps
    const int wn   = warp >> 1;       // 4 N-warps

    wmma::fragment<wmma::accumulator, 16, 16, 16, float> acc[2][2];
#pragma unroll
    for (int i = 0; i < 2; i++)
#pragma unroll
        for (int j = 0; j < 2; j++) wmma::fill_fragment(acc[i][j], 0.0f);

    const int dr = tid & 63, dq = tid >> 6;   // degree: row, k-quarter
    float degp = 0.f;

    for (int k0 = 0; k0 < NP; k0 += 32) {
        // load adj tile: 512 int4 (32 k-rows x 16 int4)
#pragma unroll
        for (int t = 0; t < 2; t++) {
            int i  = tid + t * 256;
            int kk = i >> 4, rr = (i & 15) * 4;
            int4 a = *(const int4*)(adj + (size_t)(k0 + kk) * NP + r0 + rr);
            As[kk][rr + 0] = __float2bfloat16_rn((float)a.x);
            As[kk][rr + 1] = __float2bfloat16_rn((float)a.y);
            As[kk][rr + 2] = __float2bfloat16_rn((float)a.z);
            As[kk][rr + 3] = __float2bfloat16_rn((float)a.w);
        }
        // load X tile and split hi/lo: 1024 float4 (32 k-rows x 32 float4)
#pragma unroll
        for (int t = 0; t < 4; t++) {
            int i  = tid + t * 256;
            int kk = i >> 5, ff = (i & 31) * 4;
            float4 x = *(const float4*)(X + (size_t)(k0 + kk) * FD + ff);
            bf16 h0 = __float2bfloat16_rn(x.x);
            bf16 h1 = __float2bfloat16_rn(x.y);
            bf16 h2 = __float2bfloat16_rn(x.z);
            bf16 h3 = __float2bfloat16_rn(x.w);
            Xh[kk][ff + 0] = h0; Xl[kk][ff + 0] = __float2bfloat16_rn(x.x - __bfloat162float(h0));
            Xh[kk][ff + 1] = h1; Xl[kk][ff + 1] = __float2bfloat16_rn(x.y - __bfloat162float(h1));
            Xh[kk][ff + 2] = h2; Xl[kk][ff + 2] = __float2bfloat16_rn(x.z - __bfloat162float(h2));
            Xh[kk][ff + 3] = h3; Xl[kk][ff + 3] = __float2bfloat16_rn(x.w - __bfloat162float(h3));
        }
        __syncthreads();

        // degree partial (bf16 0/1 -> exact float sum)
#pragma unroll
        for (int j = 0; j < 8; j++) degp += __bfloat162float(As[dq * 8 + j][dr]);

#pragma unroll
        for (int ks = 0; ks < 2; ks++) {
            wmma::fragment<wmma::matrix_a, 16, 16, 16, bf16, wmma::col_major> af[2];
#pragma unroll
            for (int i = 0; i < 2; i++)
                wmma::load_matrix_sync(af[i], &As[ks * 16][wm * 32 + i * 16], G1_LDA);
#pragma unroll
            for (int j = 0; j < 2; j++) {
                wmma::fragment<wmma::matrix_b, 16, 16, 16, bf16, wmma::row_major> bh, bl;
                wmma::load_matrix_sync(bh, &Xh[ks * 16][wn * 32 + j * 16], G1_LDX);
                wmma::load_matrix_sync(bl, &Xl[ks * 16][wn * 32 + j * 16], G1_LDX);
#pragma unroll
                for (int i = 0; i < 2; i++) {
                    wmma::mma_sync(acc[i][j], af[i], bh, acc[i][j]);
                    wmma::mma_sync(acc[i][j], af[i], bl, acc[i][j]);
                }
            }
        }
        __syncthreads();
    }

    // store
#pragma unroll
    for (int i = 0; i < 2; i++)
#pragma unroll
        for (int j = 0; j < 2; j++)
            wmma::store_matrix_sync(&d_Rpre[(size_t)(r0 + wm * 32 + i * 16) * FD + wn * 32 + j * 16],
                                    acc[i][j], FD, wmma::mem_row_major);

    // degree reduce (reuse As as float buffer)
    float* dbuf = (float*)As;
    dbuf[dq * 64 + dr] = degp;
    __syncthreads();
    if (tid < 64) {
        float d = dbuf[tid] + dbuf[64 + tid] + dbuf[128 + tid] + dbuf[192 + tid];
        d_invdeg[r0 + tid] = (d > 0.5f) ? (1.0f / d) : 0.0f;
    }
}

// ============================================================================
// GEMM3 (tensor core): P = A @ Rs.  M=NP, N=C0N=256, K=NP.
// Block 128x128, BK=32, grid (64,2). 8 warps (4M x 2N), warp 32x64 (2x4 frags).
// A[p,k] = adj[p*NP+k] (k contiguous). Rs pre-split bf16 hi/lo in global.
// ============================================================================
#define G3_LDA 40     // (32+8) halves, 80B
#define G3_LDB 136

__global__ void __launch_bounds__(256) k_gemm3(const int* __restrict__ adj) {
    __shared__ bf16 As[128][G3_LDA];  // [p][k]
    __shared__ bf16 Bh[32][G3_LDB];   // [k][c]
    __shared__ bf16 Bl[32][G3_LDB];

    const int p0   = blockIdx.x * 128;
    const int c0   = blockIdx.y * 128;
    const int tid  = threadIdx.x;
    const int warp = tid >> 5;
    const int wm   = warp & 3;        // 4 M-warps
    const int wn   = warp >> 2;       // 2 N-warps

    wmma::fragment<wmma::accumulator, 16, 16, 16, float> acc[2][4];
#pragma unroll
    for (int i = 0; i < 2; i++)
#pragma unroll
        for (int j = 0; j < 4; j++) wmma::fill_fragment(acc[i][j], 0.0f);

    for (int k0 = 0; k0 < NP; k0 += 32) {
        // adj tile: 1024 int4 (128 rows x 8 int4)
#pragma unroll
        for (int t = 0; t < 4; t++) {
            int i  = tid + t * 256;
            int mm = i >> 3, k4 = (i & 7) * 4;
            int4 a = *(const int4*)(adj + (size_t)(p0 + mm) * NP + k0 + k4);
            As[mm][k4 + 0] = __float2bfloat16_rn((float)a.x);
            As[mm][k4 + 1] = __float2bfloat16_rn((float)a.y);
            As[mm][k4 + 2] = __float2bfloat16_rn((float)a.z);
            As[mm][k4 + 3] = __float2bfloat16_rn((float)a.w);
        }
        // Rs hi/lo tiles: 512 float4-sized (8-half) loads each... combined loop
#pragma unroll
        for (int t = 0; t < 2; t++) {
            int i  = tid + t * 256;
            int kk = i >> 4, c8 = (i & 15) * 8;
            size_t g = (size_t)(k0 + kk) * C0N + c0 + c8;
            float4 vh = *(const float4*)(d_Rsh + g);
            float4 vl = *(const float4*)(d_Rsl + g);
            *(float4*)&Bh[kk][c8] = vh;
            *(float4*)&Bl[kk][c8] = vl;
        }
        __syncthreads();

#pragma unroll
        for (int ks = 0; ks < 2; ks++) {
            wmma::fragment<wmma::matrix_a, 16, 16, 16, bf16, wmma::row_major> af[2];
#pragma unroll
            for (int i = 0; i < 2; i++)
                wmma::load_matrix_sync(af[i], &As[wm * 32 + i * 16][ks * 16], G3_LDA);
#pragma unroll
            for (int j = 0; j < 4; j++) {
                wmma::fragment<wmma::matrix_b, 16, 16, 16, bf16, wmma::row_major> bh, bl;
                wmma::load_matrix_sync(bh, &Bh[ks * 16][wn * 64 + j * 16], G3_LDB);
                wmma::load_matrix_sync(bl, &Bl[ks * 16][wn * 64 + j * 16], G3_LDB);
#pragma unroll
                for (int i = 0; i < 2; i++) {
                    wmma::mma_sync(acc[i][j], af[i], bh, acc[i][j]);
                    wmma::mma_sync(acc[i][j], af[i], bl, acc[i][j]);
                }
            }
        }
        __syncthreads();
    }

#pragma unroll
    for (int i = 0; i < 2; i++)
#pragma unroll
        for (int j = 0; j < 4; j++)
            wmma::store_matrix_sync(&d_P[(size_t)(p0 + wm * 32 + i * 16) * C0N + c0 + wn * 64 + j * 16],
                                    acc[i][j], C0N, wmma::mem_row_major);
}

// ============================================================================
// Small GEMMs with FUSED BN stats.
// SEL=0: H = invdeg*(Rpre@K1)+b1, stats -> d_sum1/d_sq1
// SEL=1: O = P@K2+b2,             stats -> d_sum2/d_sq2
// Tile 64x64, Kt=16, thread 4x4.
// ============================================================================
template <int KDIM, int NDIM, bool SCALE, int SEL>
__global__ void __launch_bounds__(256) k_gemm_small(const float* __restrict__ B,
                                                    const float* __restrict__ bias) {
    const float* A    = (SEL == 0) ? d_Rpre : d_P;
    float*       Cout = (SEL == 0) ? d_H    : d_O;
    float*       Psum = (SEL == 0) ? d_sum1 : d_sum2;
    float*       Psq  = (SEL == 0) ? d_sq1  : d_sq2;

    __shared__ float As[16][65];
    __shared__ float Bs[16][64];
    __shared__ float red[2][16][64];

    const int m0  = blockIdx.x * 64;
    const int n0  = blockIdx.y * 64;
    const int tid = threadIdx.x;
    const int tx  = tid & 15;
    const int ty  = tid >> 4;

    float acc[4][4] = {};

    const int la_m = tid >> 2;
    const int la_k = (tid & 3) * 4;
    const int lb_k = tid >> 4;
    const int lb_n = (tid & 15) * 4;

    for (int k0 = 0; k0 < KDIM; k0 += 16) {
        float4 a4 = *(const float4*)(A + (size_t)(m0 + la_m) * KDIM + k0 + la_k);
        As[la_k + 0][la_m] = a4.x;
        As[la_k + 1][la_m] = a4.y;
        As[la_k + 2][la_m] = a4.z;
        As[la_k + 3][la_m] = a4.w;
        *(float4*)&Bs[lb_k][lb_n] = *(const float4*)(B + (size_t)(k0 + lb_k) * NDIM + n0 + lb_n);
        __syncthreads();

#pragma unroll
        for (int kk = 0; kk < 16; kk++) {
            float a[4], b[4];
#pragma unroll
            for (int i = 0; i < 4; i++) a[i] = As[kk][ty + i * 16];
#pragma unroll
            for (int j = 0; j < 4; j++) b[j] = Bs[kk][tx + j * 16];
#pragma unroll
            for (int i = 0; i < 4; i++)
#pragma unroll
                for (int j = 0; j < 4; j++) acc[i][j] = fmaf(a[i], b[j], acc[i][j]);
        }
        __syncthreads();
    }

    float ps[4] = {}, pq[4] = {};
#pragma unroll
    for (int i = 0; i < 4; i++) {
        int r = m0 + ty + i * 16;
        float sc = SCALE ? d_invdeg[r] : 1.0f;
#pragma unroll
        for (int j = 0; j < 4; j++) {
            int c = n0 + tx + j * 16;
            float v = acc[i][j] * sc + bias[c];
            Cout[(size_t)r * NDIM + c] = v;
            ps[j] += v;
            pq[j] = fmaf(v, v, pq[j]);
        }
    }
#pragma unroll
    for (int j = 0; j < 4; j++) {
        red[0][ty][tx + j * 16] = ps[j];
        red[1][ty][tx + j * 16] = pq[j];
    }
    __syncthreads();
    if (tid < 128) {
        int chl = tid & 63, which = tid >> 6;
        float s = 0.f;
#pragma unroll
        for (int t = 0; t < 16; t++) s += red[which][t][chl];
        atomicAdd((which ? Psq : Psum) + n0 + chl, s);
    }
}

// ---------------- BN finalize ------------------------------------------------
__global__ void k_fin1(const float* __restrict__ gamma, const float* __restrict__ beta) {
    int c = threadIdx.x;  // 256
    float mean = d_sum1[c] * (1.0f / NP);
    float var  = d_sq1[c] * (1.0f / NP) - mean * mean;
    float sc   = gamma[c] * rsqrtf(var + BN_EPS);
    d_sc1[c] = sc;
    d_sh1[c] = beta[c] - mean * sc;
}

__global__ void k_fin2(const float* __restrict__ gamma, const float* __restrict__ beta) {
    int c = threadIdx.x;  // 128
    float mean = d_sum2[c] * (1.0f / NP);
    float var  = d_sq2[c] * (1.0f / NP) - mean * mean;
    float sc   = gamma[c] * rsqrtf(var + BN_EPS);
    d_sc2[c] = sc;
    d_sh2[c] = beta[c] - mean * sc;
}

// Rs = invdeg[r] * BN1(H)  -> split bf16 hi/lo
__global__ void k_rs() {
    int idx = blockIdx.x * 256 + threadIdx.x;   // NP*C0N total
    int c = idx & (C0N - 1);
    int r = idx >> 8;
    float v = d_invdeg[r] * fmaf(d_H[idx], d_sc1[c], d_sh1[c]);
    bf16 h = __float2bfloat16_rn(v);
    d_Rsh[idx] = h;
    d_Rsl[idx] = __float2bfloat16_rn(v - __bfloat162float(h));
}

// out = O*sc2[c] + sh2[c]
__global__ void k_out(float* __restrict__ out) {
    int idx = blockIdx.x * 256 + threadIdx.x;   // NP*C1N total
    int c = idx & (C1N - 1);
    out[idx] = fmaf(d_O[idx], d_sc2[c], d_sh2[c]);
}

// ---------------- launch ----------------------------------------------------
extern "C" void kernel_launch(void* const* d_in, const int* in_sizes, int n_in,
                              void* d_out, int out_size) {
    const float* features = (const float*)d_in[0];
    const int*   adj      = (const int*)d_in[1];
    const float* kernel_1 = (const float*)d_in[2];
    const float* bias_1   = (const float*)d_in[3];
    const float* gamma_1  = (const float*)d_in[4];
    const float* beta_1   = (const float*)d_in[5];
    const float* kernel_2 = (const float*)d_in[6];
    const float* bias_2   = (const float*)d_in[7];
    const float* gamma_2  = (const float*)d_in[8];
    const float* beta_2   = (const float*)d_in[9];
    float* out = (float*)d_out;

    k_zero<<<1, 256>>>();
    k_gemm1<<<NP / G1_BM, 256>>>(adj, features);                                // Rpre, invdeg
    k_gemm_small<FD, C0N, true, 0><<<dim3(NP / 64, C0N / 64), 256>>>(kernel_1, bias_1);   // H + stats1
    k_fin1<<<1, C0N>>>(gamma_1, beta_1);
    k_rs<<<NP * C0N / 256, 256>>>();                                            // Rs hi/lo
    k_gemm3<<<dim3(NP / 128, C0N / 128), 256>>>(adj);                           // P
    k_gemm_small<C0N, C1N, false, 1><<<dim3(NP / 64, C1N / 64), 256>>>(kernel_2, bias_2); // O + stats2
    k_fin2<<<1, C1N>>>(gamma_2, beta_2);
    k_out<<<NP * C1N / 256, 256>>>(out);
}

// round 4
// speedup vs baseline: 3.1013x; 1.7705x over previous
#include <cuda_runtime.h>
#include <cuda_bf16.h>
#include <mma.h>

using namespace nvcuda;

#define NP   8192
#define FD   128
#define C0N  256
#define C1N  128
#define BN_EPS 1e-3f

typedef __nv_bfloat16 bf16;

// ---------------- scratch (device globals; no allocation allowed) -----------
__device__ __align__(16) float d_invdeg[NP];
__device__ __align__(16) float d_Rpre[NP * FD];     // A^T @ X (fp32)
__device__ __align__(16) float d_H[NP * C0N];       // region pre-BN
__device__ __align__(16) bf16  d_R2h[NP * C1N];     // hi(Rs @ K2)
__device__ __align__(16) bf16  d_R2l[NP * C1N];     // lo(Rs @ K2)
__device__ __align__(16) float d_O[NP * C1N];       // people pre-BN (incl bias2)
__device__ float d_sum1[C0N], d_sq1[C0N], d_sc1[C0N], d_sh1[C0N];
__device__ float d_sum2[C1N], d_sq2[C1N], d_sc2[C1N], d_sh2[C1N];

// ---------------- zero BN accumulators (graph-replay safe) ------------------
__global__ void k_zero() {
    int t = threadIdx.x;
    if (t < C0N) { d_sum1[t] = 0.f; d_sq1[t] = 0.f; }
    if (t < C1N) { d_sum2[t] = 0.f; d_sq2[t] = 0.f; }
}

// ============================================================================
// GEMM1 (tensor core, reg-prefetch pipelined): Rpre = A^T @ X, fused degree.
// M=NP, N=FD=128(full), K=NP. Block 64x128, BK=32. 8 warps (2M x 4N),
// warp 32x32 = 2x2 frags. X split bf16 hi+lo into same fp32 acc.
// A^T[r,k] = adj[k*NP + r]  (r contiguous -> coalesced).
// ============================================================================
#define G1_LDA 72
#define G1_LDX 136

__global__ void __launch_bounds__(256) k_gemm1(const int* __restrict__ adj,
                                               const float* __restrict__ X) {
    __shared__ bf16 As[32][G1_LDA];   // [k][r]
    __shared__ bf16 Xh[32][G1_LDX];   // [k][f]
    __shared__ bf16 Xl[32][G1_LDX];

    const int r0   = blockIdx.x * 64;
    const int tid  = threadIdx.x;
    const int warp = tid >> 5;
    const int wm   = warp & 1;
    const int wn   = warp >> 1;

    wmma::fragment<wmma::accumulator, 16, 16, 16, float> acc[2][2];
#pragma unroll
    for (int i = 0; i < 2; i++)
#pragma unroll
        for (int j = 0; j < 2; j++) wmma::fill_fragment(acc[i][j], 0.0f);

    const int a_k = tid >> 4, a_r = (tid & 15) * 4;       // adj: 2 int4/thread
    const int x_k = tid >> 5, x_f = (tid & 31) * 4;       // X: 4 float4/thread
    const int dr = tid & 63, dq = tid >> 6;
    float degp = 0.f;

    int4   ra[2];
    float4 rx[4];
    // prefetch tile 0
#pragma unroll
    for (int t = 0; t < 2; t++)
        ra[t] = *(const int4*)(adj + (size_t)(a_k + t * 16) * NP + r0 + a_r);
#pragma unroll
    for (int t = 0; t < 4; t++)
        rx[t] = *(const float4*)(X + (size_t)(x_k + t * 8) * FD + x_f);

    for (int k0 = 0; k0 < NP; k0 += 32) {
        // commit current tile to smem
#pragma unroll
        for (int t = 0; t < 2; t++) {
            int kk = a_k + t * 16;
            As[kk][a_r + 0] = __float2bfloat16_rn((float)ra[t].x);
            As[kk][a_r + 1] = __float2bfloat16_rn((float)ra[t].y);
            As[kk][a_r + 2] = __float2bfloat16_rn((float)ra[t].z);
            As[kk][a_r + 3] = __float2bfloat16_rn((float)ra[t].w);
        }
#pragma unroll
        for (int t = 0; t < 4; t++) {
            int kk = x_k + t * 8;
            float4 x = rx[t];
            bf16 h0 = __float2bfloat16_rn(x.x), h1 = __float2bfloat16_rn(x.y);
            bf16 h2 = __float2bfloat16_rn(x.z), h3 = __float2bfloat16_rn(x.w);
            Xh[kk][x_f + 0] = h0; Xl[kk][x_f + 0] = __float2bfloat16_rn(x.x - __bfloat162float(h0));
            Xh[kk][x_f + 1] = h1; Xl[kk][x_f + 1] = __float2bfloat16_rn(x.y - __bfloat162float(h1));
            Xh[kk][x_f + 2] = h2; Xl[kk][x_f + 2] = __float2bfloat16_rn(x.z - __bfloat162float(h2));
            Xh[kk][x_f + 3] = h3; Xl[kk][x_f + 3] = __float2bfloat16_rn(x.w - __bfloat162float(h3));
        }
        __syncthreads();

        // prefetch next tile (overlaps with mma below)
        if (k0 + 32 < NP) {
#pragma unroll
            for (int t = 0; t < 2; t++)
                ra[t] = *(const int4*)(adj + (size_t)(k0 + 32 + a_k + t * 16) * NP + r0 + a_r);
#pragma unroll
            for (int t = 0; t < 4; t++)
                rx[t] = *(const float4*)(X + (size_t)(k0 + 32 + x_k + t * 8) * FD + x_f);
        }

        // degree partial (bf16 0/1 exact)
#pragma unroll
        for (int j = 0; j < 8; j++) degp += __bfloat162float(As[dq * 8 + j][dr]);

#pragma unroll
        for (int ks = 0; ks < 2; ks++) {
            wmma::fragment<wmma::matrix_a, 16, 16, 16, bf16, wmma::col_major> af[2];
#pragma unroll
            for (int i = 0; i < 2; i++)
                wmma::load_matrix_sync(af[i], &As[ks * 16][wm * 32 + i * 16], G1_LDA);
#pragma unroll
            for (int j = 0; j < 2; j++) {
                wmma::fragment<wmma::matrix_b, 16, 16, 16, bf16, wmma::row_major> bh, bl;
                wmma::load_matrix_sync(bh, &Xh[ks * 16][wn * 32 + j * 16], G1_LDX);
                wmma::load_matrix_sync(bl, &Xl[ks * 16][wn * 32 + j * 16], G1_LDX);
#pragma unroll
                for (int i = 0; i < 2; i++) {
                    wmma::mma_sync(acc[i][j], af[i], bh, acc[i][j]);
                    wmma::mma_sync(acc[i][j], af[i], bl, acc[i][j]);
                }
            }
        }
        __syncthreads();
    }

#pragma unroll
    for (int i = 0; i < 2; i++)
#pragma unroll
        for (int j = 0; j < 2; j++)
            wmma::store_matrix_sync(&d_Rpre[(size_t)(r0 + wm * 32 + i * 16) * FD + wn * 32 + j * 16],
                                    acc[i][j], FD, wmma::mem_row_major);

    float* dbuf = (float*)As;
    dbuf[dq * 64 + dr] = degp;
    __syncthreads();
    if (tid < 64) {
        float d = dbuf[tid] + dbuf[64 + tid] + dbuf[128 + tid] + dbuf[192 + tid];
        d_invdeg[r0 + tid] = (d > 0.5f) ? (1.0f / d) : 0.0f;
    }
}

// ============================================================================
// GEMM3 (tensor core, reg-prefetch pipelined): O = A @ R2 + b2, fused BN2 stats.
// M=NP, N=C1N=128(full), K=NP. Block 64x128 -> 128 CTAs. BK=32.
// 8 warps (2M x 4N), warp 32x32 = 2x2 frags. R2 pre-split bf16 hi/lo.
// A[p,k] = adj[p*NP+k] (k contiguous).
// ============================================================================
#define G3_LDA 40
#define G3_LDB 136
#define G3_LDC 132

__global__ void __launch_bounds__(256) k_gemm3(const int* __restrict__ adj,
                                               const float* __restrict__ bias2) {
    __shared__ union {
        struct {
            bf16 As[64][G3_LDA];   // [p][k]
            bf16 Bh[32][G3_LDB];   // [k][c]
            bf16 Bl[32][G3_LDB];
        } s;
        float Ct[64][G3_LDC];
    } sm;

    const int p0   = blockIdx.x * 64;
    const int tid  = threadIdx.x;
    const int warp = tid >> 5;
    const int wm   = warp & 1;
    const int wn   = warp >> 1;

    wmma::fragment<wmma::accumulator, 16, 16, 16, float> acc[2][2];
#pragma unroll
    for (int i = 0; i < 2; i++)
#pragma unroll
        for (int j = 0; j < 2; j++) wmma::fill_fragment(acc[i][j], 0.0f);

    const int a_m = tid >> 3, a_k = (tid & 7) * 4;    // adj: 2 int4/thread (64x32)
    const int b_k = tid >> 4, b_c = (tid & 15) * 8;   // B: 2x8 halves/thread per buf

    int4   ra[2];
    float4 rbh[2], rbl[2];
#pragma unroll
    for (int t = 0; t < 2; t++) {
        ra[t]  = *(const int4*)(adj + (size_t)(p0 + a_m + t * 32) * NP + a_k);
        rbh[t] = *(const float4*)(d_R2h + (size_t)(b_k + t * 16) * C1N + b_c);
        rbl[t] = *(const float4*)(d_R2l + (size_t)(b_k + t * 16) * C1N + b_c);
    }

    for (int k0 = 0; k0 < NP; k0 += 32) {
#pragma unroll
        for (int t = 0; t < 2; t++) {
            int mm = a_m + t * 32;
            sm.s.As[mm][a_k + 0] = __float2bfloat16_rn((float)ra[t].x);
            sm.s.As[mm][a_k + 1] = __float2bfloat16_rn((float)ra[t].y);
            sm.s.As[mm][a_k + 2] = __float2bfloat16_rn((float)ra[t].z);
            sm.s.As[mm][a_k + 3] = __float2bfloat16_rn((float)ra[t].w);
            *(float4*)&sm.s.Bh[b_k + t * 16][b_c] = rbh[t];
            *(float4*)&sm.s.Bl[b_k + t * 16][b_c] = rbl[t];
        }
        __syncthreads();

        if (k0 + 32 < NP) {
#pragma unroll
            for (int t = 0; t < 2; t++) {
                ra[t]  = *(const int4*)(adj + (size_t)(p0 + a_m + t * 32) * NP + k0 + 32 + a_k);
                rbh[t] = *(const float4*)(d_R2h + (size_t)(k0 + 32 + b_k + t * 16) * C1N + b_c);
                rbl[t] = *(const float4*)(d_R2l + (size_t)(k0 + 32 + b_k + t * 16) * C1N + b_c);
            }
        }

#pragma unroll
        for (int ks = 0; ks < 2; ks++) {
            wmma::fragment<wmma::matrix_a, 16, 16, 16, bf16, wmma::row_major> af[2];
#pragma unroll
            for (int i = 0; i < 2; i++)
                wmma::load_matrix_sync(af[i], &sm.s.As[wm * 32 + i * 16][ks * 16], G3_LDA);
#pragma unroll
            for (int j = 0; j < 2; j++) {
                wmma::fragment<wmma::matrix_b, 16, 16, 16, bf16, wmma::row_major> bh, bl;
                wmma::load_matrix_sync(bh, &sm.s.Bh[ks * 16][wn * 32 + j * 16], G3_LDB);
                wmma::load_matrix_sync(bl, &sm.s.Bl[ks * 16][wn * 32 + j * 16], G3_LDB);
#pragma unroll
                for (int i = 0; i < 2; i++) {
                    wmma::mma_sync(acc[i][j], af[i], bh, acc[i][j]);
                    wmma::mma_sync(acc[i][j], af[i], bl, acc[i][j]);
                }
            }
        }
        __syncthreads();
    }

    // epilogue: frags -> smem C tile, add bias, write O, fused BN2 partial stats
#pragma unroll
    for (int i = 0; i < 2; i++)
#pragma unroll
        for (int j = 0; j < 2; j++)
            wmma::store_matrix_sync(&sm.Ct[wm * 32 + i * 16][wn * 32 + j * 16],
                                    acc[i][j], G3_LDC, wmma::mem_row_major);
    __syncthreads();

    {
        const int c    = tid & 127;
        const int half = tid >> 7;          // 2 threads per column, 32 rows each
        const float b  = bias2[c];
        float s = 0.f, q = 0.f;
#pragma unroll 8
        for (int r = half * 32; r < half * 32 + 32; r++) {
            float v = sm.Ct[r][c] + b;
            d_O[(size_t)(p0 + r) * C1N + c] = v;
            s += v;
            q = fmaf(v, v, q);
        }
        atomicAdd(&d_sum2[c], s);
        atomicAdd(&d_sq2[c], q);
    }
}

// ============================================================================
// Small GEMM A: H = invdeg*(Rpre@K1)+b1, fused BN1 stats. 64x64 tile, Kt=16.
// ============================================================================
__global__ void __launch_bounds__(256) k_small_h(const float* __restrict__ B,
                                                 const float* __restrict__ bias) {
    __shared__ float As[16][65];
    __shared__ float Bs[16][64];
    __shared__ float red[2][16][64];

    const int m0 = blockIdx.x * 64, n0 = blockIdx.y * 64;
    const int tid = threadIdx.x, tx = tid & 15, ty = tid >> 4;

    float acc[4][4] = {};
    const int la_m = tid >> 2, la_k = (tid & 3) * 4;
    const int lb_k = tid >> 4, lb_n = (tid & 15) * 4;

    for (int k0 = 0; k0 < FD; k0 += 16) {
        float4 a4 = *(const float4*)(d_Rpre + (size_t)(m0 + la_m) * FD + k0 + la_k);
        As[la_k + 0][la_m] = a4.x; As[la_k + 1][la_m] = a4.y;
        As[la_k + 2][la_m] = a4.z; As[la_k + 3][la_m] = a4.w;
        *(float4*)&Bs[lb_k][lb_n] = *(const float4*)(B + (size_t)(k0 + lb_k) * C0N + n0 + lb_n);
        __syncthreads();
#pragma unroll
        for (int kk = 0; kk < 16; kk++) {
            float a[4], b[4];
#pragma unroll
            for (int i = 0; i < 4; i++) a[i] = As[kk][ty + i * 16];
#pragma unroll
            for (int j = 0; j < 4; j++) b[j] = Bs[kk][tx + j * 16];
#pragma unroll
            for (int i = 0; i < 4; i++)
#pragma unroll
                for (int j = 0; j < 4; j++) acc[i][j] = fmaf(a[i], b[j], acc[i][j]);
        }
        __syncthreads();
    }

    float ps[4] = {}, pq[4] = {};
#pragma unroll
    for (int i = 0; i < 4; i++) {
        int r = m0 + ty + i * 16;
        float sc = d_invdeg[r];
#pragma unroll
        for (int j = 0; j < 4; j++) {
            int c = n0 + tx + j * 16;
            float v = acc[i][j] * sc + bias[c];
            d_H[(size_t)r * C0N + c] = v;
            ps[j] += v;
            pq[j] = fmaf(v, v, pq[j]);
        }
    }
#pragma unroll
    for (int j = 0; j < 4; j++) {
        red[0][ty][tx + j * 16] = ps[j];
        red[1][ty][tx + j * 16] = pq[j];
    }
    __syncthreads();
    if (tid < 128) {
        int chl = tid & 63, which = tid >> 6;
        float s = 0.f;
#pragma unroll
        for (int t = 0; t < 16; t++) s += red[which][t][chl];
        atomicAdd((which ? d_sq1 : d_sum1) + n0 + chl, s);
    }
}

// ============================================================================
// Small GEMM B: R2 = [invdeg ⊙ BN1(H)] @ K2, output split bf16 hi/lo.
// Affine+invdeg applied on A-load (no Rs materialization). M=NP,K=256,N=128.
// ============================================================================
__global__ void __launch_bounds__(256) k_small_r2(const float* __restrict__ K2) {
    __shared__ float As[16][65];
    __shared__ float Bs[16][64];

    const int m0 = blockIdx.x * 64, n0 = blockIdx.y * 64;
    const int tid = threadIdx.x, tx = tid & 15, ty = tid >> 4;

    float acc[4][4] = {};
    const int la_m = tid >> 2, la_k = (tid & 3) * 4;
    const int lb_k = tid >> 4, lb_n = (tid & 15) * 4;
    const float idg = d_invdeg[m0 + la_m];

    for (int k0 = 0; k0 < C0N; k0 += 16) {
        float4 a4 = *(const float4*)(d_H + (size_t)(m0 + la_m) * C0N + k0 + la_k);
        float4 sc = *(const float4*)(d_sc1 + k0 + la_k);
        float4 sh = *(const float4*)(d_sh1 + k0 + la_k);
        As[la_k + 0][la_m] = idg * fmaf(a4.x, sc.x, sh.x);
        As[la_k + 1][la_m] = idg * fmaf(a4.y, sc.y, sh.y);
        As[la_k + 2][la_m] = idg * fmaf(a4.z, sc.z, sh.z);
        As[la_k + 3][la_m] = idg * fmaf(a4.w, sc.w, sh.w);
        *(float4*)&Bs[lb_k][lb_n] = *(const float4*)(K2 + (size_t)(k0 + lb_k) * C1N + n0 + lb_n);
        __syncthreads();
#pragma unroll
        for (int kk = 0; kk < 16; kk++) {
            float a[4], b[4];
#pragma unroll
            for (int i = 0; i < 4; i++) a[i] = As[kk][ty + i * 16];
#pragma unroll
            for (int j = 0; j < 4; j++) b[j] = Bs[kk][tx + j * 16];
#pragma unroll
            for (int i = 0; i < 4; i++)
#pragma unroll
                for (int j = 0; j < 4; j++) acc[i][j] = fmaf(a[i], b[j], acc[i][j]);
        }
        __syncthreads();
    }

#pragma unroll
    for (int i = 0; i < 4; i++) {
        int r = m0 + ty + i * 16;
#pragma unroll
        for (int j = 0; j < 4; j++) {
            int c = n0 + tx + j * 16;
            float v = acc[i][j];
            bf16 h = __float2bfloat16_rn(v);
            d_R2h[(size_t)r * C1N + c] = h;
            d_R2l[(size_t)r * C1N + c] = __float2bfloat16_rn(v - __bfloat162float(h));
        }
    }
}

// ---------------- BN finalize + output --------------------------------------
__global__ void k_fin1(const float* __restrict__ gamma, const float* __restrict__ beta) {
    int c = threadIdx.x;  // 256
    float mean = d_sum1[c] * (1.0f / NP);
    float var  = d_sq1[c] * (1.0f / NP) - mean * mean;
    float sc   = gamma[c] * rsqrtf(var + BN_EPS);
    d_sc1[c] = sc;
    d_sh1[c] = beta[c] - mean * sc;
}

__global__ void k_fin2(const float* __restrict__ gamma, const float* __restrict__ beta) {
    int c = threadIdx.x;  // 128
    float mean = d_sum2[c] * (1.0f / NP);
    float var  = d_sq2[c] * (1.0f / NP) - mean * mean;
    float sc   = gamma[c] * rsqrtf(var + BN_EPS);
    d_sc2[c] = sc;
    d_sh2[c] = beta[c] - mean * sc;
}

__global__ void k_out(float* __restrict__ out) {
    int idx = blockIdx.x * 256 + threadIdx.x;   // NP*C1N
    int c = idx & (C1N - 1);
    out[idx] = fmaf(d_O[idx], d_sc2[c], d_sh2[c]);
}

// ---------------- launch ----------------------------------------------------
extern "C" void kernel_launch(void* const* d_in, const int* in_sizes, int n_in,
                              void* d_out, int out_size) {
    const float* features = (const float*)d_in[0];
    const int*   adj      = (const int*)d_in[1];
    const float* kernel_1 = (const float*)d_in[2];
    const float* bias_1   = (const float*)d_in[3];
    const float* gamma_1  = (const float*)d_in[4];
    const float* beta_1   = (const float*)d_in[5];
    const float* kernel_2 = (const float*)d_in[6];
    const float* bias_2   = (const float*)d_in[7];
    const float* gamma_2  = (const float*)d_in[8];
    const float* beta_2   = (const float*)d_in[9];
    float* out = (float*)d_out;

    k_zero<<<1, 256>>>();
    k_gemm1<<<NP / 64, 256>>>(adj, features);                          // Rpre + invdeg
    k_small_h<<<dim3(NP / 64, C0N / 64), 256>>>(kernel_1, bias_1);     // H + stats1
    k_fin1<<<1, C0N>>>(gamma_1, beta_1);
    k_small_r2<<<dim3(NP / 64, C1N / 64), 256>>>(kernel_2);            // R2 hi/lo
    k_gemm3<<<NP / 64, 256>>>(adj, bias_2);                            // O + stats2
    k_fin2<<<1, C1N>>>(gamma_2, beta_2);
    k_out<<<NP * C1N / 256, 256>>>(out);
}

// round 6
// speedup vs baseline: 4.1277x; 1.3310x over previous
#include <cuda_runtime.h>
#include <cuda_bf16.h>
#include <mma.h>
#include <cstdint>

using namespace nvcuda;

#define NP   8192
#define FD   128
#define C0N  256
#define C1N  128
#define BN_EPS 1e-3f

typedef __nv_bfloat16 bf16;

// ---------------- cp.async helpers ------------------------------------------
__device__ __forceinline__ void cp16(void* dst_smem, const void* src) {
    unsigned int d = (unsigned int)__cvta_generic_to_shared(dst_smem);
    asm volatile("cp.async.cg.shared.global [%0], [%1], 16;\n" :: "r"(d), "l"(src));
}
__device__ __forceinline__ void cp_commit() {
    asm volatile("cp.async.commit_group;\n");
}
template <int N> __device__ __forceinline__ void cp_wait() {
    asm volatile("cp.async.wait_group %0;\n" :: "n"(N));
}

// ---------------- scratch (device globals; no allocation allowed) -----------
__device__ __align__(16) bf16  d_Adjb[(size_t)NP * NP];  // bf16 copy of adj
__device__ __align__(16) bf16  d_Xh[NP * FD];            // hi(X)
__device__ __align__(16) bf16  d_Xl[NP * FD];            // lo(X)
__device__ __align__(16) float d_invdeg[NP];
__device__ __align__(16) float d_Rpre[NP * FD];          // A^T @ X (fp32)
__device__ __align__(16) float d_H[NP * C0N];            // region pre-BN
__device__ __align__(16) bf16  d_R2h[NP * C1N];          // hi(Rs @ K2)
__device__ __align__(16) bf16  d_R2l[NP * C1N];          // lo(Rs @ K2)
__device__ __align__(16) float d_O[NP * C1N];            // people pre-BN (+bias2)
__device__ float d_sum1[C0N], d_sq1[C0N], d_sc1[C0N], d_sh1[C0N];
__device__ float d_sum2[C1N], d_sq2[C1N], d_sc2[C1N], d_sh2[C1N];

// ---------------- zero BN accumulators (graph-replay safe) ------------------
__global__ void k_zero() {
    int t = threadIdx.x;
    if (t < C0N) { d_sum1[t] = 0.f; d_sq1[t] = 0.f; }
    if (t < C1N) { d_sum2[t] = 0.f; d_sq2[t] = 0.f; }
}

// ---------------- prep: adj int32 -> bf16 (one pass, memory-bound) ----------
__global__ void __launch_bounds__(256) k_prep_adj(const int* __restrict__ adj) {
    size_t i = ((size_t)blockIdx.x * 256 + threadIdx.x) * 8;
    int4 a = *(const int4*)(adj + i);
    int4 b = *(const int4*)(adj + i + 4);
    bf16 o[8];
    o[0] = __float2bfloat16_rn((float)a.x);
    o[1] = __float2bfloat16_rn((float)a.y);
    o[2] = __float2bfloat16_rn((float)a.z);
    o[3] = __float2bfloat16_rn((float)a.w);
    o[4] = __float2bfloat16_rn((float)b.x);
    o[5] = __float2bfloat16_rn((float)b.y);
    o[6] = __float2bfloat16_rn((float)b.z);
    o[7] = __float2bfloat16_rn((float)b.w);
    *(uint4*)(d_Adjb + i) = *(uint4*)o;
}

// ---------------- prep: X -> (Xh, Xl) bf16 ----------------------------------
__global__ void __launch_bounds__(256) k_prep_x(const float* __restrict__ X) {
    size_t i = ((size_t)blockIdx.x * 256 + threadIdx.x) * 4;
    float4 x = *(const float4*)(X + i);
    bf16 h[4], l[4];
    h[0] = __float2bfloat16_rn(x.x); l[0] = __float2bfloat16_rn(x.x - __bfloat162float(h[0]));
    h[1] = __float2bfloat16_rn(x.y); l[1] = __float2bfloat16_rn(x.y - __bfloat162float(h[1]));
    h[2] = __float2bfloat16_rn(x.z); l[2] = __float2bfloat16_rn(x.z - __bfloat162float(h[2]));
    h[3] = __float2bfloat16_rn(x.w); l[3] = __float2bfloat16_rn(x.w - __bfloat162float(h[3]));
    *(uint2*)(d_Xh + i) = *(uint2*)h;
    *(uint2*)(d_Xl + i) = *(uint2*)l;
}

// ============================================================================
// GEMM1: Rpre = A^T @ X, fused degree.  cp.async 2-stage pipeline.
// M=NP, N=FD=128(full), K=NP. Block 64x128, BK=32, 8 warps (2M x 4N).
// A^T[r,k] = Adjb[k*NP + r] (r contiguous).
// ============================================================================
#define G1_LDA 72     // halves; 144B row stride (16B multiple)
#define G1_LDX 136    // halves; 272B

__global__ void __launch_bounds__(256) k_gemm1() {
    __shared__ bf16 As[2][32][G1_LDA];   // [k][r]
    __shared__ bf16 Xh[2][32][G1_LDX];   // [k][f]
    __shared__ bf16 Xl[2][32][G1_LDX];

    const int r0   = blockIdx.x * 64;
    const int tid  = threadIdx.x;
    const int warp = tid >> 5;
    const int wm   = warp & 1;
    const int wn   = warp >> 1;

    wmma::fragment<wmma::accumulator, 16, 16, 16, float> acc[2][2];
#pragma unroll
    for (int i = 0; i < 2; i++)
#pragma unroll
        for (int j = 0; j < 2; j++) wmma::fill_fragment(acc[i][j], 0.0f);

    const int a_k = tid >> 3, a_r = (tid & 7) * 8;      // 1 cp16: 32x64 tile
    const int x_k = tid >> 4, x_f = (tid & 15) * 8;     // 2 cp16 per matrix
    const int dr = tid & 63, dq = tid >> 6;
    float degp = 0.f;

    // prefetch stage 0
    {
        cp16(&As[0][a_k][a_r], d_Adjb + (size_t)a_k * NP + r0 + a_r);
#pragma unroll
        for (int t = 0; t < 2; t++) {
            cp16(&Xh[0][x_k + t * 16][x_f], d_Xh + (size_t)(x_k + t * 16) * FD + x_f);
            cp16(&Xl[0][x_k + t * 16][x_f], d_Xl + (size_t)(x_k + t * 16) * FD + x_f);
        }
        cp_commit();
    }

    const int T = NP / 32;
    for (int t = 0; t < T; t++) {
        const int buf = t & 1;
        if (t + 1 < T) {
            const int nb = buf ^ 1;
            const int k1 = (t + 1) * 32;
            cp16(&As[nb][a_k][a_r], d_Adjb + (size_t)(k1 + a_k) * NP + r0 + a_r);
#pragma unroll
            for (int u = 0; u < 2; u++) {
                cp16(&Xh[nb][x_k + u * 16][x_f], d_Xh + (size_t)(k1 + x_k + u * 16) * FD + x_f);
                cp16(&Xl[nb][x_k + u * 16][x_f], d_Xl + (size_t)(k1 + x_k + u * 16) * FD + x_f);
            }
            cp_commit();
            cp_wait<1>();
        } else {
            cp_wait<0>();
        }
        __syncthreads();

        // degree partial (bf16 0/1 exact)
#pragma unroll
        for (int j = 0; j < 8; j++) degp += __bfloat162float(As[buf][dq * 8 + j][dr]);

#pragma unroll
        for (int ks = 0; ks < 2; ks++) {
            wmma::fragment<wmma::matrix_a, 16, 16, 16, bf16, wmma::col_major> af[2];
#pragma unroll
            for (int i = 0; i < 2; i++)
                wmma::load_matrix_sync(af[i], &As[buf][ks * 16][wm * 32 + i * 16], G1_LDA);
#pragma unroll
            for (int j = 0; j < 2; j++) {
                wmma::fragment<wmma::matrix_b, 16, 16, 16, bf16, wmma::row_major> bh, bl;
                wmma::load_matrix_sync(bh, &Xh[buf][ks * 16][wn * 32 + j * 16], G1_LDX);
                wmma::load_matrix_sync(bl, &Xl[buf][ks * 16][wn * 32 + j * 16], G1_LDX);
#pragma unroll
                for (int i = 0; i < 2; i++) {
                    wmma::mma_sync(acc[i][j], af[i], bh, acc[i][j]);
                    wmma::mma_sync(acc[i][j], af[i], bl, acc[i][j]);
                }
            }
        }
        __syncthreads();
    }

#pragma unroll
    for (int i = 0; i < 2; i++)
#pragma unroll
        for (int j = 0; j < 2; j++)
            wmma::store_matrix_sync(&d_Rpre[(size_t)(r0 + wm * 32 + i * 16) * FD + wn * 32 + j * 16],
                                    acc[i][j], FD, wmma::mem_row_major);

    float* dbuf = (float*)As;
    dbuf[dq * 64 + dr] = degp;
    __syncthreads();
    if (tid < 64) {
        float d = dbuf[tid] + dbuf[64 + tid] + dbuf[128 + tid] + dbuf[192 + tid];
        d_invdeg[r0 + tid] = (d > 0.5f) ? (1.0f / d) : 0.0f;
    }
}

// ============================================================================
// GEMM3: O = A @ R2 + b2, fused BN2 stats.  cp.async 2-stage pipeline.
// M=NP, N=C1N=128(full), K=NP. Block 64x128, BK=32, 8 warps (2M x 4N).
// A[p,k] = Adjb[p*NP + k] (k contiguous).
// ============================================================================
#define G3_LDA 40     // halves; 80B (16B multiple)
#define G3_LDB 136
#define G3_LDC 132

__global__ void __launch_bounds__(256) k_gemm3(const float* __restrict__ bias2) {
    __shared__ union {
        struct {
            bf16 As[2][64][G3_LDA];   // [p][k]
            bf16 Bh[2][32][G3_LDB];   // [k][c]
            bf16 Bl[2][32][G3_LDB];
        } s;
        float Ct[64][G3_LDC];
    } sm;

    const int p0   = blockIdx.x * 64;
    const int tid  = threadIdx.x;
    const int warp = tid >> 5;
    const int wm   = warp & 1;
    const int wn   = warp >> 1;

    wmma::fragment<wmma::accumulator, 16, 16, 16, float> acc[2][2];
#pragma unroll
    for (int i = 0; i < 2; i++)
#pragma unroll
        for (int j = 0; j < 2; j++) wmma::fill_fragment(acc[i][j], 0.0f);

    const int a_m = tid >> 2, a_c = (tid & 3) * 8;      // 1 cp16: 64x32 tile
    const int b_k = tid >> 4, b_c = (tid & 15) * 8;     // 2 cp16 per matrix

    {
        cp16(&sm.s.As[0][a_m][a_c], d_Adjb + (size_t)(p0 + a_m) * NP + a_c);
#pragma unroll
        for (int t = 0; t < 2; t++) {
            cp16(&sm.s.Bh[0][b_k + t * 16][b_c], d_R2h + (size_t)(b_k + t * 16) * C1N + b_c);
            cp16(&sm.s.Bl[0][b_k + t * 16][b_c], d_R2l + (size_t)(b_k + t * 16) * C1N + b_c);
        }
        cp_commit();
    }

    const int T = NP / 32;
    for (int t = 0; t < T; t++) {
        const int buf = t & 1;
        if (t + 1 < T) {
            const int nb = buf ^ 1;
            const int k1 = (t + 1) * 32;
            cp16(&sm.s.As[nb][a_m][a_c], d_Adjb + (size_t)(p0 + a_m) * NP + k1 + a_c);
#pragma unroll
            for (int u = 0; u < 2; u++) {
                cp16(&sm.s.Bh[nb][b_k + u * 16][b_c], d_R2h + (size_t)(k1 + b_k + u * 16) * C1N + b_c);
                cp16(&sm.s.Bl[nb][b_k + u * 16][b_c], d_R2l + (size_t)(k1 + b_k + u * 16) * C1N + b_c);
            }
            cp_commit();
            cp_wait<1>();
        } else {
            cp_wait<0>();
        }
        __syncthreads();

#pragma unroll
        for (int ks = 0; ks < 2; ks++) {
            wmma::fragment<wmma::matrix_a, 16, 16, 16, bf16, wmma::row_major> af[2];
#pragma unroll
            for (int i = 0; i < 2; i++)
                wmma::load_matrix_sync(af[i], &sm.s.As[buf][wm * 32 + i * 16][ks * 16], G3_LDA);
#pragma unroll
            for (int j = 0; j < 2; j++) {
                wmma::fragment<wmma::matrix_b, 16, 16, 16, bf16, wmma::row_major> bh, bl;
                wmma::load_matrix_sync(bh, &sm.s.Bh[buf][ks * 16][wn * 32 + j * 16], G3_LDB);
                wmma::load_matrix_sync(bl, &sm.s.Bl[buf][ks * 16][wn * 32 + j * 16], G3_LDB);
#pragma unroll
                for (int i = 0; i < 2; i++) {
                    wmma::mma_sync(acc[i][j], af[i], bh, acc[i][j]);
                    wmma::mma_sync(acc[i][j], af[i], bl, acc[i][j]);
                }
            }
        }
        __syncthreads();
    }

    // epilogue: frags -> smem, add bias, write O, fused BN2 partial stats
#pragma unroll
    for (int i = 0; i < 2; i++)
#pragma unroll
        for (int j = 0; j < 2; j++)
            wmma::store_matrix_sync(&sm.Ct[wm * 32 + i * 16][wn * 32 + j * 16],
                                    acc[i][j], G3_LDC, wmma::mem_row_major);
    __syncthreads();

    {
        const int c    = tid & 127;
        const int half = tid >> 7;
        const float b  = bias2[c];
        float s = 0.f, q = 0.f;
#pragma unroll 8
        for (int r = half * 32; r < half * 32 + 32; r++) {
            float v = sm.Ct[r][c] + b;
            d_O[(size_t)(p0 + r) * C1N + c] = v;
            s += v;
            q = fmaf(v, v, q);
        }
        atomicAdd(&d_sum2[c], s);
        atomicAdd(&d_sq2[c], q);
    }
}

// ============================================================================
// Small GEMM A: H = invdeg*(Rpre@K1)+b1, fused BN1 stats. 64x64, Kt=16.
// ============================================================================
__global__ void __launch_bounds__(256) k_small_h(const float* __restrict__ B,
                                                 const float* __restrict__ bias) {
    __shared__ float As[16][65];
    __shared__ float Bs[16][64];
    __shared__ float red[2][16][64];

    const int m0 = blockIdx.x * 64, n0 = blockIdx.y * 64;
    const int tid = threadIdx.x, tx = tid & 15, ty = tid >> 4;

    float acc[4][4] = {};
    const int la_m = tid >> 2, la_k = (tid & 3) * 4;
    const int lb_k = tid >> 4, lb_n = (tid & 15) * 4;

    for (int k0 = 0; k0 < FD; k0 += 16) {
        float4 a4 = *(const float4*)(d_Rpre + (size_t)(m0 + la_m) * FD + k0 + la_k);
        As[la_k + 0][la_m] = a4.x; As[la_k + 1][la_m] = a4.y;
        As[la_k + 2][la_m] = a4.z; As[la_k + 3][la_m] = a4.w;
        *(float4*)&Bs[lb_k][lb_n] = *(const float4*)(B + (size_t)(k0 + lb_k) * C0N + n0 + lb_n);
        __syncthreads();
#pragma unroll
        for (int kk = 0; kk < 16; kk++) {
            float a[4], b[4];
#pragma unroll
            for (int i = 0; i < 4; i++) a[i] = As[kk][ty + i * 16];
#pragma unroll
            for (int j = 0; j < 4; j++) b[j] = Bs[kk][tx + j * 16];
#pragma unroll
            for (int i = 0; i < 4; i++)
#pragma unroll
                for (int j = 0; j < 4; j++) acc[i][j] = fmaf(a[i], b[j], acc[i][j]);
        }
        __syncthreads();
    }

    float ps[4] = {}, pq[4] = {};
#pragma unroll
    for (int i = 0; i < 4; i++) {
        int r = m0 + ty + i * 16;
        float sc = d_invdeg[r];
#pragma unroll
        for (int j = 0; j < 4; j++) {
            int c = n0 + tx + j * 16;
            float v = acc[i][j] * sc + bias[c];
            d_H[(size_t)r * C0N + c] = v;
            ps[j] += v;
            pq[j] = fmaf(v, v, pq[j]);
        }
    }
#pragma unroll
    for (int j = 0; j < 4; j++) {
        red[0][ty][tx + j * 16] = ps[j];
        red[1][ty][tx + j * 16] = pq[j];
    }
    __syncthreads();
    if (tid < 128) {
        int chl = tid & 63, which = tid >> 6;
        float s = 0.f;
#pragma unroll
        for (int t = 0; t < 16; t++) s += red[which][t][chl];
        atomicAdd((which ? d_sq1 : d_sum1) + n0 + chl, s);
    }
}

// ============================================================================
// Small GEMM B: R2 = [invdeg ⊙ BN1(H)] @ K2, output split bf16 hi/lo.
// ============================================================================
__global__ void __launch_bounds__(256) k_small_r2(const float* __restrict__ K2) {
    __shared__ float As[16][65];
    __shared__ float Bs[16][64];

    const int m0 = blockIdx.x * 64, n0 = blockIdx.y * 64;
    const int tid = threadIdx.x, tx = tid & 15, ty = tid >> 4;

    float acc[4][4] = {};
    const int la_m = tid >> 2, la_k = (tid & 3) * 4;
    const int lb_k = tid >> 4, lb_n = (tid & 15) * 4;
    const float idg = d_invdeg[m0 + la_m];

    for (int k0 = 0; k0 < C0N; k0 += 16) {
        float4 a4 = *(const float4*)(d_H + (size_t)(m0 + la_m) * C0N + k0 + la_k);
        float4 sc = *(const float4*)(d_sc1 + k0 + la_k);
        float4 sh = *(const float4*)(d_sh1 + k0 + la_k);
        As[la_k + 0][la_m] = idg * fmaf(a4.x, sc.x, sh.x);
        As[la_k + 1][la_m] = idg * fmaf(a4.y, sc.y, sh.y);
        As[la_k + 2][la_m] = idg * fmaf(a4.z, sc.z, sh.z);
        As[la_k + 3][la_m] = idg * fmaf(a4.w, sc.w, sh.w);
        *(float4*)&Bs[lb_k][lb_n] = *(const float4*)(K2 + (size_t)(k0 + lb_k) * C1N + n0 + lb_n);
        __syncthreads();
#pragma unroll
        for (int kk = 0; kk < 16; kk++) {
            float a[4], b[4];
#pragma unroll
            for (int i = 0; i < 4; i++) a[i] = As[kk][ty + i * 16];
#pragma unroll
            for (int j = 0; j < 4; j++) b[j] = Bs[kk][tx + j * 16];
#pragma unroll
            for (int i = 0; i < 4; i++)
#pragma unroll
                for (int j = 0; j < 4; j++) acc[i][j] = fmaf(a[i], b[j], acc[i][j]);
        }
        __syncthreads();
    }

#pragma unroll
    for (int i = 0; i < 4; i++) {
        int r = m0 + ty + i * 16;
#pragma unroll
        for (int j = 0; j < 4; j++) {
            int c = n0 + tx + j * 16;
            float v = acc[i][j];
            bf16 h = __float2bfloat16_rn(v);
            d_R2h[(size_t)r * C1N + c] = h;
            d_R2l[(size_t)r * C1N + c] = __float2bfloat16_rn(v - __bfloat162float(h));
        }
    }
}

// ---------------- BN finalize + output --------------------------------------
__global__ void k_fin1(const float* __restrict__ gamma, const float* __restrict__ beta) {
    int c = threadIdx.x;  // 256
    float mean = d_sum1[c] * (1.0f / NP);
    float var  = d_sq1[c] * (1.0f / NP) - mean * mean;
    float sc   = gamma[c] * rsqrtf(var + BN_EPS);
    d_sc1[c] = sc;
    d_sh1[c] = beta[c] - mean * sc;
}

__global__ void k_fin2(const float* __restrict__ gamma, const float* __restrict__ beta) {
    int c = threadIdx.x;  // 128
    float mean = d_sum2[c] * (1.0f / NP);
    float var  = d_sq2[c] * (1.0f / NP) - mean * mean;
    float sc   = gamma[c] * rsqrtf(var + BN_EPS);
    d_sc2[c] = sc;
    d_sh2[c] = beta[c] - mean * sc;
}

__global__ void k_out(float* __restrict__ out) {
    int idx = blockIdx.x * 256 + threadIdx.x;   // NP*C1N
    int c = idx & (C1N - 1);
    out[idx] = fmaf(d_O[idx], d_sc2[c], d_sh2[c]);
}

// ---------------- launch ----------------------------------------------------
extern "C" void kernel_launch(void* const* d_in, const int* in_sizes, int n_in,
                              void* d_out, int out_size) {
    const float* features = (const float*)d_in[0];
    const int*   adj      = (const int*)d_in[1];
    const float* kernel_1 = (const float*)d_in[2];
    const float* bias_1   = (const float*)d_in[3];
    const float* gamma_1  = (const float*)d_in[4];
    const float* beta_1   = (const float*)d_in[5];
    const float* kernel_2 = (const float*)d_in[6];
    const float* bias_2   = (const float*)d_in[7];
    const float* gamma_2  = (const float*)d_in[8];
    const float* beta_2   = (const float*)d_in[9];
    float* out = (float*)d_out;

    k_zero<<<1, 256>>>();
    k_prep_adj<<<(int)(((size_t)NP * NP) / (256 * 8)), 256>>>(adj);     // adj -> bf16
    k_prep_x<<<NP * FD / (256 * 4), 256>>>(features);                   // X -> hi/lo
    k_gemm1<<<NP / 64, 256>>>();                                        // Rpre + invdeg
    k_small_h<<<dim3(NP / 64, C0N / 64), 256>>>(kernel_1, bias_1);      // H + stats1
    k_fin1<<<1, C0N>>>(gamma_1, beta_1);
    k_small_r2<<<dim3(NP / 64, C1N / 64), 256>>>(kernel_2);             // R2 hi/lo
    k_gemm3<<<NP / 64, 256>>>(bias_2);                                  // O + stats2
    k_fin2<<<1, C1N>>>(gamma_2, beta_2);
    k_out<<<NP * C1N / 256, 256>>>(out);
}

// round 7
// speedup vs baseline: 4.3421x; 1.0519x over previous
#include <cuda_runtime.h>
#include <cuda_bf16.h>
#include <mma.h>
#include <cstdint>

using namespace nvcuda;

#define NP   8192
#define FD   128
#define C0N  256
#define C1N  128
#define BN_EPS 1e-3f

typedef __nv_bfloat16 bf16;

// ---------------- cp.async helpers ------------------------------------------
__device__ __forceinline__ void cp16(void* dst_smem, const void* src) {
    unsigned int d = (unsigned int)__cvta_generic_to_shared(dst_smem);
    asm volatile("cp.async.cg.shared.global [%0], [%1], 16;\n" :: "r"(d), "l"(src));
}
__device__ __forceinline__ void cp_commit() {
    asm volatile("cp.async.commit_group;\n");
}
template <int N> __device__ __forceinline__ void cp_wait() {
    asm volatile("cp.async.wait_group %0;\n" :: "n"(N));
}

// ---------------- scratch (device globals; no allocation allowed) -----------
__device__ __align__(16) bf16  d_Adjb[(size_t)NP * NP];  // bf16 copy of adj
__device__ __align__(16) bf16  d_Xh[NP * FD];            // hi(X)
__device__ __align__(16) bf16  d_Xl[NP * FD];            // lo(X)
__device__ __align__(16) float d_invdeg[NP];
__device__ __align__(16) float d_Rpre[NP * FD];          // A^T @ X (fp32)
__device__ __align__(16) float d_H[NP * C0N];            // region pre-BN
__device__ __align__(16) bf16  d_R2h[NP * C1N];          // hi(Rs @ K2)
__device__ __align__(16) bf16  d_R2l[NP * C1N];          // lo(Rs @ K2)
__device__ __align__(16) float d_O[NP * C1N];            // people pre-BN (+bias2)
__device__ float d_sum1[C0N], d_sq1[C0N], d_sc1[C0N], d_sh1[C0N];
__device__ float d_sum2[C1N], d_sq2[C1N], d_sc2[C1N], d_sh2[C1N];

// ---------------- prep: adj int32 -> bf16 (one pass, memory-bound) ----------
__global__ void __launch_bounds__(256) k_prep_adj(const int* __restrict__ adj) {
    size_t i = ((size_t)blockIdx.x * 256 + threadIdx.x) * 8;
    int4 a = *(const int4*)(adj + i);
    int4 b = *(const int4*)(adj + i + 4);
    bf16 o[8];
    o[0] = __float2bfloat16_rn((float)a.x);
    o[1] = __float2bfloat16_rn((float)a.y);
    o[2] = __float2bfloat16_rn((float)a.z);
    o[3] = __float2bfloat16_rn((float)a.w);
    o[4] = __float2bfloat16_rn((float)b.x);
    o[5] = __float2bfloat16_rn((float)b.y);
    o[6] = __float2bfloat16_rn((float)b.z);
    o[7] = __float2bfloat16_rn((float)b.w);
    *(uint4*)(d_Adjb + i) = *(uint4*)o;
}

// ---------------- prep: X -> (Xh, Xl) bf16, fused BN-accum zeroing ----------
__global__ void __launch_bounds__(256) k_prep_x(const float* __restrict__ X) {
    if (blockIdx.x == 0) {
        int t = threadIdx.x;
        if (t < C0N) { d_sum1[t] = 0.f; d_sq1[t] = 0.f; }
        if (t < C1N) { d_sum2[t] = 0.f; d_sq2[t] = 0.f; }
    }
    size_t i = ((size_t)blockIdx.x * 256 + threadIdx.x) * 4;
    float4 x = *(const float4*)(X + i);
    bf16 h[4], l[4];
    h[0] = __float2bfloat16_rn(x.x); l[0] = __float2bfloat16_rn(x.x - __bfloat162float(h[0]));
    h[1] = __float2bfloat16_rn(x.y); l[1] = __float2bfloat16_rn(x.y - __bfloat162float(h[1]));
    h[2] = __float2bfloat16_rn(x.z); l[2] = __float2bfloat16_rn(x.z - __bfloat162float(h[2]));
    h[3] = __float2bfloat16_rn(x.w); l[3] = __float2bfloat16_rn(x.w - __bfloat162float(h[3]));
    *(uint2*)(d_Xh + i) = *(uint2*)h;
    *(uint2*)(d_Xl + i) = *(uint2*)l;
}

// ============================================================================
// GEMM1: Rpre = A^T @ X, fused degree.  cp.async 2-stage, BK=64.
// M=NP, N=FD=128(full), K=NP. Block 64x128, 8 warps (2M x 4N), warp 32x32.
// A^T[r,k] = Adjb[k*NP + r] (r contiguous). Dynamic smem 88KB.
// ============================================================================
#define G1_LDA 72     // halves; 144B row stride
#define G1_LDX 136    // halves; 272B
#define G1_AS_BYTES  (2 * 64 * G1_LDA * 2)     // 18432
#define G1_XH_BYTES  (2 * 64 * G1_LDX * 2)     // 34816
#define G1_SMEM      (G1_AS_BYTES + 2 * G1_XH_BYTES)   // 88064

__global__ void __launch_bounds__(256) k_gemm1() {
    extern __shared__ __align__(16) char smem_raw[];
    bf16 (*As)[64][G1_LDA] = (bf16(*)[64][G1_LDA])smem_raw;                       // [2][k][r]
    bf16 (*Xh)[64][G1_LDX] = (bf16(*)[64][G1_LDX])(smem_raw + G1_AS_BYTES);       // [2][k][f]
    bf16 (*Xl)[64][G1_LDX] = (bf16(*)[64][G1_LDX])(smem_raw + G1_AS_BYTES + G1_XH_BYTES);

    const int r0   = blockIdx.x * 64;
    const int tid  = threadIdx.x;
    const int warp = tid >> 5;
    const int wm   = warp & 1;
    const int wn   = warp >> 1;

    wmma::fragment<wmma::accumulator, 16, 16, 16, float> acc[2][2];
#pragma unroll
    for (int i = 0; i < 2; i++)
#pragma unroll
        for (int j = 0; j < 2; j++) wmma::fill_fragment(acc[i][j], 0.0f);

    const int a_k = tid >> 3, a_r = (tid & 7) * 8;      // 2 cp16 (rows +0,+32)
    const int x_k = tid >> 4, x_f = (tid & 15) * 8;     // 4 cp16/matrix (rows +16t)
    const int dr = tid & 63, dq = tid >> 6;
    float degp = 0.f;

    // prefetch stage 0
    {
#pragma unroll
        for (int t = 0; t < 2; t++)
            cp16(&As[0][a_k + t * 32][a_r], d_Adjb + (size_t)(a_k + t * 32) * NP + r0 + a_r);
#pragma unroll
        for (int t = 0; t < 4; t++) {
            cp16(&Xh[0][x_k + t * 16][x_f], d_Xh + (size_t)(x_k + t * 16) * FD + x_f);
            cp16(&Xl[0][x_k + t * 16][x_f], d_Xl + (size_t)(x_k + t * 16) * FD + x_f);
        }
        cp_commit();
    }

    const int T = NP / 64;
    for (int t = 0; t < T; t++) {
        const int buf = t & 1;
        if (t + 1 < T) {
            const int nb = buf ^ 1;
            const int k1 = (t + 1) * 64;
#pragma unroll
            for (int u = 0; u < 2; u++)
                cp16(&As[nb][a_k + u * 32][a_r], d_Adjb + (size_t)(k1 + a_k + u * 32) * NP + r0 + a_r);
#pragma unroll
            for (int u = 0; u < 4; u++) {
                cp16(&Xh[nb][x_k + u * 16][x_f], d_Xh + (size_t)(k1 + x_k + u * 16) * FD + x_f);
                cp16(&Xl[nb][x_k + u * 16][x_f], d_Xl + (size_t)(k1 + x_k + u * 16) * FD + x_f);
            }
            cp_commit();
            cp_wait<1>();
        } else {
            cp_wait<0>();
        }
        __syncthreads();

        // degree partial (bf16 0/1 exact): 16 k-slices per dq group
#pragma unroll
        for (int j = 0; j < 16; j++) degp += __bfloat162float(As[buf][dq * 16 + j][dr]);

#pragma unroll
        for (int ks = 0; ks < 4; ks++) {
            wmma::fragment<wmma::matrix_a, 16, 16, 16, bf16, wmma::col_major> af[2];
#pragma unroll
            for (int i = 0; i < 2; i++)
                wmma::load_matrix_sync(af[i], &As[buf][ks * 16][wm * 32 + i * 16], G1_LDA);
#pragma unroll
            for (int j = 0; j < 2; j++) {
                wmma::fragment<wmma::matrix_b, 16, 16, 16, bf16, wmma::row_major> bh, bl;
                wmma::load_matrix_sync(bh, &Xh[buf][ks * 16][wn * 32 + j * 16], G1_LDX);
                wmma::load_matrix_sync(bl, &Xl[buf][ks * 16][wn * 32 + j * 16], G1_LDX);
#pragma unroll
                for (int i = 0; i < 2; i++) {
                    wmma::mma_sync(acc[i][j], af[i], bh, acc[i][j]);
                    wmma::mma_sync(acc[i][j], af[i], bl, acc[i][j]);
                }
            }
        }
        __syncthreads();
    }

#pragma unroll
    for (int i = 0; i < 2; i++)
#pragma unroll
        for (int j = 0; j < 2; j++)
            wmma::store_matrix_sync(&d_Rpre[(size_t)(r0 + wm * 32 + i * 16) * FD + wn * 32 + j * 16],
                                    acc[i][j], FD, wmma::mem_row_major);

    float* dbuf = (float*)smem_raw;
    dbuf[dq * 64 + dr] = degp;
    __syncthreads();
    if (tid < 64) {
        float d = dbuf[tid] + dbuf[64 + tid] + dbuf[128 + tid] + dbuf[192 + tid];
        d_invdeg[r0 + tid] = (d > 0.5f) ? (1.0f / d) : 0.0f;
    }
}

// ============================================================================
// GEMM3: O = A @ R2 + b2, fused BN2 stats.  cp.async 2-stage, BK=64.
// M=NP, N=C1N=128(full), K=NP. Block 64x128, 8 warps (2M x 4N), warp 32x32.
// A[p,k] = Adjb[p*NP + k] (k contiguous). Dynamic smem 88KB.
// ============================================================================
#define G3_LDA 72     // halves; BK=64 + 8 pad
#define G3_LDB 136
#define G3_LDC 132
#define G3_AS_BYTES (2 * 64 * G3_LDA * 2)      // 18432
#define G3_BH_BYTES (2 * 64 * G3_LDB * 2)      // 34816
#define G3_SMEM     (G3_AS_BYTES + 2 * G3_BH_BYTES)    // 88064

__global__ void __launch_bounds__(256) k_gemm3(const float* __restrict__ bias2) {
    extern __shared__ __align__(16) char smem_raw[];
    bf16 (*As)[64][G3_LDA] = (bf16(*)[64][G3_LDA])smem_raw;                       // [2][p][k]
    bf16 (*Bh)[64][G3_LDB] = (bf16(*)[64][G3_LDB])(smem_raw + G3_AS_BYTES);       // [2][k][c]
    bf16 (*Bl)[64][G3_LDB] = (bf16(*)[64][G3_LDB])(smem_raw + G3_AS_BYTES + G3_BH_BYTES);
    float (*Ct)[G3_LDC]    = (float(*)[G3_LDC])smem_raw;                          // epilogue reuse

    const int p0   = blockIdx.x * 64;
    const int tid  = threadIdx.x;
    const int warp = tid >> 5;
    const int wm   = warp & 1;
    const int wn   = warp >> 1;

    wmma::fragment<wmma::accumulator, 16, 16, 16, float> acc[2][2];
#pragma unroll
    for (int i = 0; i < 2; i++)
#pragma unroll
        for (int j = 0; j < 2; j++) wmma::fill_fragment(acc[i][j], 0.0f);

    const int a_m = tid >> 3, a_c = (tid & 7) * 8;      // 2 cp16 (rows +0,+32)
    const int b_k = tid >> 4, b_c = (tid & 15) * 8;     // 4 cp16/matrix

    {
#pragma unroll
        for (int t = 0; t < 2; t++)
            cp16(&As[0][a_m + t * 32][a_c], d_Adjb + (size_t)(p0 + a_m + t * 32) * NP + a_c);
#pragma unroll
        for (int t = 0; t < 4; t++) {
            cp16(&Bh[0][b_k + t * 16][b_c], d_R2h + (size_t)(b_k + t * 16) * C1N + b_c);
            cp16(&Bl[0][b_k + t * 16][b_c], d_R2l + (size_t)(b_k + t * 16) * C1N + b_c);
        }
        cp_commit();
    }

    const int T = NP / 64;
    for (int t = 0; t < T; t++) {
        const int buf = t & 1;
        if (t + 1 < T) {
            const int nb = buf ^ 1;
            const int k1 = (t + 1) * 64;
#pragma unroll
            for (int u = 0; u < 2; u++)
                cp16(&As[nb][a_m + u * 32][a_c], d_Adjb + (size_t)(p0 + a_m + u * 32) * NP + k1 + a_c);
#pragma unroll
            for (int u = 0; u < 4; u++) {
                cp16(&Bh[nb][b_k + u * 16][b_c], d_R2h + (size_t)(k1 + b_k + u * 16) * C1N + b_c);
                cp16(&Bl[nb][b_k + u * 16][b_c], d_R2l + (size_t)(k1 + b_k + u * 16) * C1N + b_c);
            }
            cp_commit();
            cp_wait<1>();
        } else {
            cp_wait<0>();
        }
        __syncthreads();

#pragma unroll
        for (int ks = 0; ks < 4; ks++) {
            wmma::fragment<wmma::matrix_a, 16, 16, 16, bf16, wmma::row_major> af[2];
#pragma unroll
            for (int i = 0; i < 2; i++)
                wmma::load_matrix_sync(af[i], &As[buf][wm * 32 + i * 16][ks * 16], G3_LDA);
#pragma unroll
            for (int j = 0; j < 2; j++) {
                wmma::fragment<wmma::matrix_b, 16, 16, 16, bf16, wmma::row_major> bh, bl;
                wmma::load_matrix_sync(bh, &Bh[buf][ks * 16][wn * 32 + j * 16], G3_LDB);
                wmma::load_matrix_sync(bl, &Bl[buf][ks * 16][wn * 32 + j * 16], G3_LDB);
#pragma unroll
                for (int i = 0; i < 2; i++) {
                    wmma::mma_sync(acc[i][j], af[i], bh, acc[i][j]);
                    wmma::mma_sync(acc[i][j], af[i], bl, acc[i][j]);
                }
            }
        }
        __syncthreads();
    }

    // epilogue: frags -> smem, add bias, write O, fused BN2 partial stats
#pragma unroll
    for (int i = 0; i < 2; i++)
#pragma unroll
        for (int j = 0; j < 2; j++)
            wmma::store_matrix_sync(&Ct[wm * 32 + i * 16][wn * 32 + j * 16],
                                    acc[i][j], G3_LDC, wmma::mem_row_major);
    __syncthreads();

    {
        const int c    = tid & 127;
        const int half = tid >> 7;
        const float b  = bias2[c];
        float s = 0.f, q = 0.f;
#pragma unroll 8
        for (int r = half * 32; r < half * 32 + 32; r++) {
            float v = Ct[r][c] + b;
            d_O[(size_t)(p0 + r) * C1N + c] = v;
            s += v;
            q = fmaf(v, v, q);
        }
        atomicAdd(&d_sum2[c], s);
        atomicAdd(&d_sq2[c], q);
    }
}

// ============================================================================
// Small GEMM A: H = invdeg*(Rpre@K1)+b1, fused BN1 stats. 64x64, Kt=16.
// ============================================================================
__global__ void __launch_bounds__(256) k_small_h(const float* __restrict__ B,
                                                 const float* __restrict__ bias) {
    __shared__ float As[16][65];
    __shared__ float Bs[16][64];
    __shared__ float red[2][16][64];

    const int m0 = blockIdx.x * 64, n0 = blockIdx.y * 64;
    const int tid = threadIdx.x, tx = tid & 15, ty = tid >> 4;

    float acc[4][4] = {};
    const int la_m = tid >> 2, la_k = (tid & 3) * 4;
    const int lb_k = tid >> 4, lb_n = (tid & 15) * 4;

    for (int k0 = 0; k0 < FD; k0 += 16) {
        float4 a4 = *(const float4*)(d_Rpre + (size_t)(m0 + la_m) * FD + k0 + la_k);
        As[la_k + 0][la_m] = a4.x; As[la_k + 1][la_m] = a4.y;
        As[la_k + 2][la_m] = a4.z; As[la_k + 3][la_m] = a4.w;
        *(float4*)&Bs[lb_k][lb_n] = *(const float4*)(B + (size_t)(k0 + lb_k) * C0N + n0 + lb_n);
        __syncthreads();
#pragma unroll
        for (int kk = 0; kk < 16; kk++) {
            float a[4], b[4];
#pragma unroll
            for (int i = 0; i < 4; i++) a[i] = As[kk][ty + i * 16];
#pragma unroll
            for (int j = 0; j < 4; j++) b[j] = Bs[kk][tx + j * 16];
#pragma unroll
            for (int i = 0; i < 4; i++)
#pragma unroll
                for (int j = 0; j < 4; j++) acc[i][j] = fmaf(a[i], b[j], acc[i][j]);
        }
        __syncthreads();
    }

    float ps[4] = {}, pq[4] = {};
#pragma unroll
    for (int i = 0; i < 4; i++) {
        int r = m0 + ty + i * 16;
        float sc = d_invdeg[r];
#pragma unroll
        for (int j = 0; j < 4; j++) {
            int c = n0 + tx + j * 16;
            float v = acc[i][j] * sc + bias[c];
            d_H[(size_t)r * C0N + c] = v;
            ps[j] += v;
            pq[j] = fmaf(v, v, pq[j]);
        }
    }
#pragma unroll
    for (int j = 0; j < 4; j++) {
        red[0][ty][tx + j * 16] = ps[j];
        red[1][ty][tx + j * 16] = pq[j];
    }
    __syncthreads();
    if (tid < 128) {
        int chl = tid & 63, which = tid >> 6;
        float s = 0.f;
#pragma unroll
        for (int t = 0; t < 16; t++) s += red[which][t][chl];
        atomicAdd((which ? d_sq1 : d_sum1) + n0 + chl, s);
    }
}

// ============================================================================
// Small GEMM B: R2 = [invdeg ⊙ BN1(H)] @ K2, output split bf16 hi/lo.
// ============================================================================
__global__ void __launch_bounds__(256) k_small_r2(const float* __restrict__ K2) {
    __shared__ float As[16][65];
    __shared__ float Bs[16][64];

    const int m0 = blockIdx.x * 64, n0 = blockIdx.y * 64;
    const int tid = threadIdx.x, tx = tid & 15, ty = tid >> 4;

    float acc[4][4] = {};
    const int la_m = tid >> 2, la_k = (tid & 3) * 4;
    const int lb_k = tid >> 4, lb_n = (tid & 15) * 4;
    const float idg = d_invdeg[m0 + la_m];

    for (int k0 = 0; k0 < C0N; k0 += 16) {
        float4 a4 = *(const float4*)(d_H + (size_t)(m0 + la_m) * C0N + k0 + la_k);
        float4 sc = *(const float4*)(d_sc1 + k0 + la_k);
        float4 sh = *(const float4*)(d_sh1 + k0 + la_k);
        As[la_k + 0][la_m] = idg * fmaf(a4.x, sc.x, sh.x);
        As[la_k + 1][la_m] = idg * fmaf(a4.y, sc.y, sh.y);
        As[la_k + 2][la_m] = idg * fmaf(a4.z, sc.z, sh.z);
        As[la_k + 3][la_m] = idg * fmaf(a4.w, sc.w, sh.w);
        *(float4*)&Bs[lb_k][lb_n] = *(const float4*)(K2 + (size_t)(k0 + lb_k) * C1N + n0 + lb_n);
        __syncthreads();
#pragma unroll
        for (int kk = 0; kk < 16; kk++) {
            float a[4], b[4];
#pragma unroll
            for (int i = 0; i < 4; i++) a[i] = As[kk][ty + i * 16];
#pragma unroll
            for (int j = 0; j < 4; j++) b[j] = Bs[kk][tx + j * 16];
#pragma unroll
            for (int i = 0; i < 4; i++)
#pragma unroll
                for (int j = 0; j < 4; j++) acc[i][j] = fmaf(a[i], b[j], acc[i][j]);
        }
        __syncthreads();
    }

#pragma unroll
    for (int i = 0; i < 4; i++) {
        int r = m0 + ty + i * 16;
#pragma unroll
        for (int j = 0; j < 4; j++) {
            int c = n0 + tx + j * 16;
            float v = acc[i][j];
            bf16 h = __float2bfloat16_rn(v);
            d_R2h[(size_t)r * C1N + c] = h;
            d_R2l[(size_t)r * C1N + c] = __float2bfloat16_rn(v - __bfloat162float(h));
        }
    }
}

// ---------------- BN finalize + output --------------------------------------
__global__ void k_fin1(const float* __restrict__ gamma, const float* __restrict__ beta) {
    int c = threadIdx.x;  // 256
    float mean = d_sum1[c] * (1.0f / NP);
    float var  = d_sq1[c] * (1.0f / NP) - mean * mean;
    float sc   = gamma[c] * rsqrtf(var + BN_EPS);
    d_sc1[c] = sc;
    d_sh1[c] = beta[c] - mean * sc;
}

__global__ void k_fin2(const float* __restrict__ gamma, const float* __restrict__ beta) {
    int c = threadIdx.x;  // 128
    float mean = d_sum2[c] * (1.0f / NP);
    float var  = d_sq2[c] * (1.0f / NP) - mean * mean;
    float sc   = gamma[c] * rsqrtf(var + BN_EPS);
    d_sc2[c] = sc;
    d_sh2[c] = beta[c] - mean * sc;
}

__global__ void k_out(float* __restrict__ out) {
    int idx = blockIdx.x * 256 + threadIdx.x;   // NP*C1N
    int c = idx & (C1N - 1);
    out[idx] = fmaf(d_O[idx], d_sc2[c], d_sh2[c]);
}

// ---------------- launch ----------------------------------------------------
extern "C" void kernel_launch(void* const* d_in, const int* in_sizes, int n_in,
                              void* d_out, int out_size) {
    const float* features = (const float*)d_in[0];
    const int*   adj      = (const int*)d_in[1];
    const float* kernel_1 = (const float*)d_in[2];
    const float* bias_1   = (const float*)d_in[3];
    const float* gamma_1  = (const float*)d_in[4];
    const float* beta_1   = (const float*)d_in[5];
    const float* kernel_2 = (const float*)d_in[6];
    const float* bias_2   = (const float*)d_in[7];
    const float* gamma_2  = (const float*)d_in[8];
    const float* beta_2   = (const float*)d_in[9];
    float* out = (float*)d_out;

    cudaFuncSetAttribute(k_gemm1, cudaFuncAttributeMaxDynamicSharedMemorySize, G1_SMEM);
    cudaFuncSetAttribute(k_gemm3, cudaFuncAttributeMaxDynamicSharedMemorySize, G3_SMEM);

    k_prep_adj<<<(int)(((size_t)NP * NP) / (256 * 8)), 256>>>(adj);     // adj -> bf16
    k_prep_x<<<NP * FD / (256 * 4), 256>>>(features);                   // X -> hi/lo (+zero)
    k_gemm1<<<NP / 64, 256, G1_SMEM>>>();                               // Rpre + invdeg
    k_small_h<<<dim3(NP / 64, C0N / 64), 256>>>(kernel_1, bias_1);      // H + stats1
    k_fin1<<<1, C0N>>>(gamma_1, beta_1);
    k_small_r2<<<dim3(NP / 64, C1N / 64), 256>>>(kernel_2);             // R2 hi/lo
    k_gemm3<<<NP / 64, 256, G3_SMEM>>>(bias_2);                         // O + stats2
    k_fin2<<<1, C1N>>>(gamma_2, beta_2);
    k_out<<<NP * C1N / 256, 256>>>(out);
}

// round 8
// speedup vs baseline: 4.5020x; 1.0368x over previous
#include <cuda_runtime.h>
#include <cuda_bf16.h>
#include <mma.h>
#include <cstdint>

using namespace nvcuda;

#define NP   8192
#define FD   128
#define C0N  256
#define C1N  128
#define BN_EPS 1e-3f
#define KSPLIT 2
#define KHALF (NP / KSPLIT)

typedef __nv_bfloat16 bf16;

// ---------------- cp.async helpers ------------------------------------------
__device__ __forceinline__ void cp16(void* dst_smem, const void* src) {
    unsigned int d = (unsigned int)__cvta_generic_to_shared(dst_smem);
    asm volatile("cp.async.cg.shared.global [%0], [%1], 16;\n" :: "r"(d), "l"(src));
}
__device__ __forceinline__ void cp_commit() {
    asm volatile("cp.async.commit_group;\n");
}
template <int N> __device__ __forceinline__ void cp_wait() {
    asm volatile("cp.async.wait_group %0;\n" :: "n"(N));
}

// ---------------- scratch (device globals; no allocation allowed) -----------
__device__ __align__(16) bf16  d_Adjb[(size_t)NP * NP];  // bf16 copy of adj
__device__ __align__(16) bf16  d_Xh[NP * FD];            // hi(X)
__device__ __align__(16) bf16  d_Xl[NP * FD];            // lo(X)
__device__ __align__(16) float d_deg[NP];                // column degree (accum)
__device__ __align__(16) float d_Rpre0[NP * FD];         // A^T@X partial (K half 0)
__device__ __align__(16) float d_Rpre1[NP * FD];         // A^T@X partial (K half 1)
__device__ __align__(16) float d_H[NP * C0N];            // region pre-BN
__device__ __align__(16) bf16  d_R2h[NP * C1N];          // hi(Rs @ K2)
__device__ __align__(16) bf16  d_R2l[NP * C1N];          // lo(Rs @ K2)
__device__ __align__(16) float d_O0[NP * C1N];           // A@R2 partial (K half 0)
__device__ __align__(16) float d_O1[NP * C1N];           // A@R2 partial (K half 1)
__device__ __align__(16) float d_O[NP * C1N];            // combined pre-BN (+bias2)
__device__ float d_sum1[C0N], d_sq1[C0N], d_sc1[C0N], d_sh1[C0N];
__device__ float d_sum2[C1N], d_sq2[C1N], d_sc2[C1N], d_sh2[C1N];

// ---------------- prep: adj int32 -> bf16 (one pass, memory-bound) ----------
__global__ void __launch_bounds__(256) k_prep_adj(const int* __restrict__ adj) {
    size_t i = ((size_t)blockIdx.x * 256 + threadIdx.x) * 8;
    int4 a = *(const int4*)(adj + i);
    int4 b = *(const int4*)(adj + i + 4);
    bf16 o[8];
    o[0] = __float2bfloat16_rn((float)a.x);
    o[1] = __float2bfloat16_rn((float)a.y);
    o[2] = __float2bfloat16_rn((float)a.z);
    o[3] = __float2bfloat16_rn((float)a.w);
    o[4] = __float2bfloat16_rn((float)b.x);
    o[5] = __float2bfloat16_rn((float)b.y);
    o[6] = __float2bfloat16_rn((float)b.z);
    o[7] = __float2bfloat16_rn((float)b.w);
    *(uint4*)(d_Adjb + i) = *(uint4*)o;
}

// ------------ prep: X -> (Xh, Xl) bf16, fused accum zeroing ------------------
// grid = NP*FD/(256*4) = 1024 blocks; block b zeroes deg[8b..8b+8)
__global__ void __launch_bounds__(256) k_prep_x(const float* __restrict__ X) {
    if (blockIdx.x == 0) {
        int t = threadIdx.x;
        if (t < C0N) { d_sum1[t] = 0.f; d_sq1[t] = 0.f; }
        if (t < C1N) { d_sum2[t] = 0.f; d_sq2[t] = 0.f; }
    }
    if (threadIdx.x < 8) d_deg[blockIdx.x * 8 + threadIdx.x] = 0.f;
    size_t i = ((size_t)blockIdx.x * 256 + threadIdx.x) * 4;
    float4 x = *(const float4*)(X + i);
    bf16 h[4], l[4];
    h[0] = __float2bfloat16_rn(x.x); l[0] = __float2bfloat16_rn(x.x - __bfloat162float(h[0]));
    h[1] = __float2bfloat16_rn(x.y); l[1] = __float2bfloat16_rn(x.y - __bfloat162float(h[1]));
    h[2] = __float2bfloat16_rn(x.z); l[2] = __float2bfloat16_rn(x.z - __bfloat162float(h[2]));
    h[3] = __float2bfloat16_rn(x.w); l[3] = __float2bfloat16_rn(x.w - __bfloat162float(h[3]));
    *(uint2*)(d_Xh + i) = *(uint2*)h;
    *(uint2*)(d_Xl + i) = *(uint2*)l;
}

// ============================================================================
// GEMM1: Rpre_part = A^T @ X over one K half, fused degree partial.
// grid (128, 2): blockIdx.y = K half. Block 64x128, BK=64, 8 warps (2M x 4N).
// A^T[r,k] = Adjb[k*NP + r]. Dynamic smem 88KB, 2 CTAs/SM.
// ============================================================================
#define G1_LDA 72
#define G1_LDX 136
#define G1_AS_BYTES  (2 * 64 * G1_LDA * 2)
#define G1_XH_BYTES  (2 * 64 * G1_LDX * 2)
#define G1_SMEM      (G1_AS_BYTES + 2 * G1_XH_BYTES)   // 88064

__global__ void __launch_bounds__(256, 2) k_gemm1() {
    extern __shared__ __align__(16) char smem_raw[];
    bf16 (*As)[64][G1_LDA] = (bf16(*)[64][G1_LDA])smem_raw;
    bf16 (*Xh)[64][G1_LDX] = (bf16(*)[64][G1_LDX])(smem_raw + G1_AS_BYTES);
    bf16 (*Xl)[64][G1_LDX] = (bf16(*)[64][G1_LDX])(smem_raw + G1_AS_BYTES + G1_XH_BYTES);

    const int r0    = blockIdx.x * 64;
    const int kbase = blockIdx.y * KHALF;
    const int tid   = threadIdx.x;
    const int warp  = tid >> 5;
    const int wm    = warp & 1;
    const int wn    = warp >> 1;

    wmma::fragment<wmma::accumulator, 16, 16, 16, float> acc[2][2];
#pragma unroll
    for (int i = 0; i < 2; i++)
#pragma unroll
        for (int j = 0; j < 2; j++) wmma::fill_fragment(acc[i][j], 0.0f);

    const int a_k = tid >> 3, a_r = (tid & 7) * 8;
    const int x_k = tid >> 4, x_f = (tid & 15) * 8;
    const int dr = tid & 63, dq = tid >> 6;
    float degp = 0.f;

    {
#pragma unroll
        for (int t = 0; t < 2; t++)
            cp16(&As[0][a_k + t * 32][a_r], d_Adjb + (size_t)(kbase + a_k + t * 32) * NP + r0 + a_r);
#pragma unroll
        for (int t = 0; t < 4; t++) {
            cp16(&Xh[0][x_k + t * 16][x_f], d_Xh + (size_t)(kbase + x_k + t * 16) * FD + x_f);
            cp16(&Xl[0][x_k + t * 16][x_f], d_Xl + (size_t)(kbase + x_k + t * 16) * FD + x_f);
        }
        cp_commit();
    }

    const int T = KHALF / 64;
    for (int t = 0; t < T; t++) {
        const int buf = t & 1;
        if (t + 1 < T) {
            const int nb = buf ^ 1;
            const int k1 = kbase + (t + 1) * 64;
#pragma unroll
            for (int u = 0; u < 2; u++)
                cp16(&As[nb][a_k + u * 32][a_r], d_Adjb + (size_t)(k1 + a_k + u * 32) * NP + r0 + a_r);
#pragma unroll
            for (int u = 0; u < 4; u++) {
                cp16(&Xh[nb][x_k + u * 16][x_f], d_Xh + (size_t)(k1 + x_k + u * 16) * FD + x_f);
                cp16(&Xl[nb][x_k + u * 16][x_f], d_Xl + (size_t)(k1 + x_k + u * 16) * FD + x_f);
            }
            cp_commit();
            cp_wait<1>();
        } else {
            cp_wait<0>();
        }
        __syncthreads();

#pragma unroll
        for (int j = 0; j < 16; j++) degp += __bfloat162float(As[buf][dq * 16 + j][dr]);

#pragma unroll
        for (int ks = 0; ks < 4; ks++) {
            wmma::fragment<wmma::matrix_a, 16, 16, 16, bf16, wmma::col_major> af[2];
#pragma unroll
            for (int i = 0; i < 2; i++)
                wmma::load_matrix_sync(af[i], &As[buf][ks * 16][wm * 32 + i * 16], G1_LDA);
#pragma unroll
            for (int j = 0; j < 2; j++) {
                wmma::fragment<wmma::matrix_b, 16, 16, 16, bf16, wmma::row_major> bh, bl;
                wmma::load_matrix_sync(bh, &Xh[buf][ks * 16][wn * 32 + j * 16], G1_LDX);
                wmma::load_matrix_sync(bl, &Xl[buf][ks * 16][wn * 32 + j * 16], G1_LDX);
#pragma unroll
                for (int i = 0; i < 2; i++) {
                    wmma::mma_sync(acc[i][j], af[i], bh, acc[i][j]);
                    wmma::mma_sync(acc[i][j], af[i], bl, acc[i][j]);
                }
            }
        }
        __syncthreads();
    }

    float* dst = blockIdx.y ? d_Rpre1 : d_Rpre0;
#pragma unroll
    for (int i = 0; i < 2; i++)
#pragma unroll
        for (int j = 0; j < 2; j++)
            wmma::store_matrix_sync(&dst[(size_t)(r0 + wm * 32 + i * 16) * FD + wn * 32 + j * 16],
                                    acc[i][j], FD, wmma::mem_row_major);

    float* dbuf = (float*)smem_raw;
    dbuf[dq * 64 + dr] = degp;
    __syncthreads();
    if (tid < 64) {
        float d = dbuf[tid] + dbuf[64 + tid] + dbuf[128 + tid] + dbuf[192 + tid];
        atomicAdd(&d_deg[r0 + tid], d);
    }
}

// ============================================================================
// GEMM3: O_part = A @ R2 over one K half.  grid (128, 2). BK=64.
// Direct fragment store to global partial buffer (no epilogue work).
// ============================================================================
#define G3_LDA 72
#define G3_LDB 136
#define G3_AS_BYTES (2 * 64 * G3_LDA * 2)
#define G3_BH_BYTES (2 * 64 * G3_LDB * 2)
#define G3_SMEM     (G3_AS_BYTES + 2 * G3_BH_BYTES)    // 88064

__global__ void __launch_bounds__(256, 2) k_gemm3() {
    extern __shared__ __align__(16) char smem_raw[];
    bf16 (*As)[64][G3_LDA] = (bf16(*)[64][G3_LDA])smem_raw;
    bf16 (*Bh)[64][G3_LDB] = (bf16(*)[64][G3_LDB])(smem_raw + G3_AS_BYTES);
    bf16 (*Bl)[64][G3_LDB] = (bf16(*)[64][G3_LDB])(smem_raw + G3_AS_BYTES + G3_BH_BYTES);

    const int p0    = blockIdx.x * 64;
    const int kbase = blockIdx.y * KHALF;
    const int tid   = threadIdx.x;
    const int warp  = tid >> 5;
    const int wm    = warp & 1;
    const int wn    = warp >> 1;

    wmma::fragment<wmma::accumulator, 16, 16, 16, float> acc[2][2];
#pragma unroll
    for (int i = 0; i < 2; i++)
#pragma unroll
        for (int j = 0; j < 2; j++) wmma::fill_fragment(acc[i][j], 0.0f);

    const int a_m = tid >> 3, a_c = (tid & 7) * 8;
    const int b_k = tid >> 4, b_c = (tid & 15) * 8;

    {
#pragma unroll
        for (int t = 0; t < 2; t++)
            cp16(&As[0][a_m + t * 32][a_c], d_Adjb + (size_t)(p0 + a_m + t * 32) * NP + kbase + a_c);
#pragma unroll
        for (int t = 0; t < 4; t++) {
            cp16(&Bh[0][b_k + t * 16][b_c], d_R2h + (size_t)(kbase + b_k + t * 16) * C1N + b_c);
            cp16(&Bl[0][b_k + t * 16][b_c], d_R2l + (size_t)(kbase + b_k + t * 16) * C1N + b_c);
        }
        cp_commit();
    }

    const int T = KHALF / 64;
    for (int t = 0; t < T; t++) {
        const int buf = t & 1;
        if (t + 1 < T) {
            const int nb = buf ^ 1;
            const int k1 = kbase + (t + 1) * 64;
#pragma unroll
            for (int u = 0; u < 2; u++)
                cp16(&As[nb][a_m + u * 32][a_c], d_Adjb + (size_t)(p0 + a_m + u * 32) * NP + k1 + a_c);
#pragma unroll
            for (int u = 0; u < 4; u++) {
                cp16(&Bh[nb][b_k + u * 16][b_c], d_R2h + (size_t)(k1 + b_k + u * 16) * C1N + b_c);
                cp16(&Bl[nb][b_k + u * 16][b_c], d_R2l + (size_t)(k1 + b_k + u * 16) * C1N + b_c);
            }
            cp_commit();
            cp_wait<1>();
        } else {
            cp_wait<0>();
        }
        __syncthreads();

#pragma unroll
        for (int ks = 0; ks < 4; ks++) {
            wmma::fragment<wmma::matrix_a, 16, 16, 16, bf16, wmma::row_major> af[2];
#pragma unroll
            for (int i = 0; i < 2; i++)
                wmma::load_matrix_sync(af[i], &As[buf][wm * 32 + i * 16][ks * 16], G3_LDA);
#pragma unroll
            for (int j = 0; j < 2; j++) {
                wmma::fragment<wmma::matrix_b, 16, 16, 16, bf16, wmma::row_major> bh, bl;
                wmma::load_matrix_sync(bh, &Bh[buf][ks * 16][wn * 32 + j * 16], G3_LDB);
                wmma::load_matrix_sync(bl, &Bl[buf][ks * 16][wn * 32 + j * 16], G3_LDB);
#pragma unroll
                for (int i = 0; i < 2; i++) {
                    wmma::mma_sync(acc[i][j], af[i], bh, acc[i][j]);
                    wmma::mma_sync(acc[i][j], af[i], bl, acc[i][j]);
                }
            }
        }
        __syncthreads();
    }

    float* dst = blockIdx.y ? d_O1 : d_O0;
#pragma unroll
    for (int i = 0; i < 2; i++)
#pragma unroll
        for (int j = 0; j < 2; j++)
            wmma::store_matrix_sync(&dst[(size_t)(p0 + wm * 32 + i * 16) * C1N + wn * 32 + j * 16],
                                    acc[i][j], C1N, wmma::mem_row_major);
}

// ============================================================================
// Small GEMM A: H = invdeg*((Rpre0+Rpre1)@K1)+b1, fused BN1 stats.
// ============================================================================
__global__ void __launch_bounds__(256) k_small_h(const float* __restrict__ B,
                                                 const float* __restrict__ bias) {
    __shared__ float As[16][65];
    __shared__ float Bs[16][64];
    __shared__ float red[2][16][64];

    const int m0 = blockIdx.x * 64, n0 = blockIdx.y * 64;
    const int tid = threadIdx.x, tx = tid & 15, ty = tid >> 4;

    float acc[4][4] = {};
    const int la_m = tid >> 2, la_k = (tid & 3) * 4;
    const int lb_k = tid >> 4, lb_n = (tid & 15) * 4;

    for (int k0 = 0; k0 < FD; k0 += 16) {
        size_t ga = (size_t)(m0 + la_m) * FD + k0 + la_k;
        float4 a4 = *(const float4*)(d_Rpre0 + ga);
        float4 b4 = *(const float4*)(d_Rpre1 + ga);
        As[la_k + 0][la_m] = a4.x + b4.x;
        As[la_k + 1][la_m] = a4.y + b4.y;
        As[la_k + 2][la_m] = a4.z + b4.z;
        As[la_k + 3][la_m] = a4.w + b4.w;
        *(float4*)&Bs[lb_k][lb_n] = *(const float4*)(B + (size_t)(k0 + lb_k) * C0N + n0 + lb_n);
        __syncthreads();
#pragma unroll
        for (int kk = 0; kk < 16; kk++) {
            float a[4], b[4];
#pragma unroll
            for (int i = 0; i < 4; i++) a[i] = As[kk][ty + i * 16];
#pragma unroll
            for (int j = 0; j < 4; j++) b[j] = Bs[kk][tx + j * 16];
#pragma unroll
            for (int i = 0; i < 4; i++)
#pragma unroll
                for (int j = 0; j < 4; j++) acc[i][j] = fmaf(a[i], b[j], acc[i][j]);
        }
        __syncthreads();
    }

    float ps[4] = {}, pq[4] = {};
#pragma unroll
    for (int i = 0; i < 4; i++) {
        int r = m0 + ty + i * 16;
        float dg = d_deg[r];
        float sc = (dg > 0.5f) ? (1.0f / dg) : 0.0f;
#pragma unroll
        for (int j = 0; j < 4; j++) {
            int c = n0 + tx + j * 16;
            float v = acc[i][j] * sc + bias[c];
            d_H[(size_t)r * C0N + c] = v;
            ps[j] += v;
            pq[j] = fmaf(v, v, pq[j]);
        }
    }
#pragma unroll
    for (int j = 0; j < 4; j++) {
        red[0][ty][tx + j * 16] = ps[j];
        red[1][ty][tx + j * 16] = pq[j];
    }
    __syncthreads();
    if (tid < 128) {
        int chl = tid & 63, which = tid >> 6;
        float s = 0.f;
#pragma unroll
        for (int t = 0; t < 16; t++) s += red[which][t][chl];
        atomicAdd((which ? d_sq1 : d_sum1) + n0 + chl, s);
    }
}

// ============================================================================
// Small GEMM B: R2 = [invdeg ⊙ BN1(H)] @ K2, output split bf16 hi/lo.
// ============================================================================
__global__ void __launch_bounds__(256) k_small_r2(const float* __restrict__ K2) {
    __shared__ float As[16][65];
    __shared__ float Bs[16][64];

    const int m0 = blockIdx.x * 64, n0 = blockIdx.y * 64;
    const int tid = threadIdx.x, tx = tid & 15, ty = tid >> 4;

    float acc[4][4] = {};
    const int la_m = tid >> 2, la_k = (tid & 3) * 4;
    const int lb_k = tid >> 4, lb_n = (tid & 15) * 4;
    const float dg  = d_deg[m0 + la_m];
    const float idg = (dg > 0.5f) ? (1.0f / dg) : 0.0f;

    for (int k0 = 0; k0 < C0N; k0 += 16) {
        float4 a4 = *(const float4*)(d_H + (size_t)(m0 + la_m) * C0N + k0 + la_k);
        float4 sc = *(const float4*)(d_sc1 + k0 + la_k);
        float4 sh = *(const float4*)(d_sh1 + k0 + la_k);
        As[la_k + 0][la_m] = idg * fmaf(a4.x, sc.x, sh.x);
        As[la_k + 1][la_m] = idg * fmaf(a4.y, sc.y, sh.y);
        As[la_k + 2][la_m] = idg * fmaf(a4.z, sc.z, sh.z);
        As[la_k + 3][la_m] = idg * fmaf(a4.w, sc.w, sh.w);
        *(float4*)&Bs[lb_k][lb_n] = *(const float4*)(K2 + (size_t)(k0 + lb_k) * C1N + n0 + lb_n);
        __syncthreads();
#pragma unroll
        for (int kk = 0; kk < 16; kk++) {
            float a[4], b[4];
#pragma unroll
            for (int i = 0; i < 4; i++) a[i] = As[kk][ty + i * 16];
#pragma unroll
            for (int j = 0; j < 4; j++) b[j] = Bs[kk][tx + j * 16];
#pragma unroll
            for (int i = 0; i < 4; i++)
#pragma unroll
                for (int j = 0; j < 4; j++) acc[i][j] = fmaf(a[i], b[j], acc[i][j]);
        }
        __syncthreads();
    }

#pragma unroll
    for (int i = 0; i < 4; i++) {
        int r = m0 + ty + i * 16;
#pragma unroll
        for (int j = 0; j < 4; j++) {
            int c = n0 + tx + j * 16;
            float v = acc[i][j];
            bf16 h = __float2bfloat16_rn(v);
            d_R2h[(size_t)r * C1N + c] = h;
            d_R2l[(size_t)r * C1N + c] = __float2bfloat16_rn(v - __bfloat162float(h));
        }
    }
}

// ------------- combine O partials + bias, BN2 stats --------------------------
__global__ void __launch_bounds__(128) k_stats2(const float* __restrict__ bias2) {
    const int c  = threadIdx.x;            // 128 channels
    const int r0 = blockIdx.x * 64;        // grid 128
    const float b = bias2[c];
    float s = 0.f, q = 0.f;
#pragma unroll 4
    for (int r = r0; r < r0 + 64; r++) {
        size_t idx = (size_t)r * C1N + c;
        float v = d_O0[idx] + d_O1[idx] + b;
        d_O[idx] = v;
        s += v;
        q = fmaf(v, v, q);
    }
    atomicAdd(&d_sum2[c], s);
    atomicAdd(&d_sq2[c], q);
}

// ---------------- BN finalize + output --------------------------------------
__global__ void k_fin1(const float* __restrict__ gamma, const float* __restrict__ beta) {
    int c = threadIdx.x;  // 256
    float mean = d_sum1[c] * (1.0f / NP);
    float var  = d_sq1[c] * (1.0f / NP) - mean * mean;
    float sc   = gamma[c] * rsqrtf(var + BN_EPS);
    d_sc1[c] = sc;
    d_sh1[c] = beta[c] - mean * sc;
}

__global__ void k_fin2(const float* __restrict__ gamma, const float* __restrict__ beta) {
    int c = threadIdx.x;  // 128
    float mean = d_sum2[c] * (1.0f / NP);
    float var  = d_sq2[c] * (1.0f / NP) - mean * mean;
    float sc   = gamma[c] * rsqrtf(var + BN_EPS);
    d_sc2[c] = sc;
    d_sh2[c] = beta[c] - mean * sc;
}

__global__ void k_out(float* __restrict__ out) {
    int idx = blockIdx.x * 256 + threadIdx.x;   // NP*C1N
    int c = idx & (C1N - 1);
    out[idx] = fmaf(d_O[idx], d_sc2[c], d_sh2[c]);
}

// ---------------- launch ----------------------------------------------------
extern "C" void kernel_launch(void* const* d_in, const int* in_sizes, int n_in,
                              void* d_out, int out_size) {
    const float* features = (const float*)d_in[0];
    const int*   adj      = (const int*)d_in[1];
    const float* kernel_1 = (const float*)d_in[2];
    const float* bias_1   = (const float*)d_in[3];
    const float* gamma_1  = (const float*)d_in[4];
    const float* beta_1   = (const float*)d_in[5];
    const float* kernel_2 = (const float*)d_in[6];
    const float* bias_2   = (const float*)d_in[7];
    const float* gamma_2  = (const float*)d_in[8];
    const float* beta_2   = (const float*)d_in[9];
    float* out = (float*)d_out;

    cudaFuncSetAttribute(k_gemm1, cudaFuncAttributeMaxDynamicSharedMemorySize, G1_SMEM);
    cudaFuncSetAttribute(k_gemm3, cudaFuncAttributeMaxDynamicSharedMemorySize, G3_SMEM);

    k_prep_adj<<<(int)(((size_t)NP * NP) / (256 * 8)), 256>>>(adj);     // adj -> bf16
    k_prep_x<<<NP * FD / (256 * 4), 256>>>(features);                   // X hi/lo + zeroing
    k_gemm1<<<dim3(NP / 64, KSPLIT), 256, G1_SMEM>>>();                 // Rpre partials + deg
    k_small_h<<<dim3(NP / 64, C0N / 64), 256>>>(kernel_1, bias_1);      // H + stats1
    k_fin1<<<1, C0N>>>(gamma_1, beta_1);
    k_small_r2<<<dim3(NP / 64, C1N / 64), 256>>>(kernel_2);             // R2 hi/lo
    k_gemm3<<<dim3(NP / 64, KSPLIT), 256, G3_SMEM>>>();                 // O partials
    k_stats2<<<NP / 64, 128>>>(bias_2);                                 // combine + stats2
    k_fin2<<<1, C1N>>>(gamma_2, beta_2);
    k_out<<<NP * C1N / 256, 256>>>(out);
}

// round 11
// speedup vs baseline: 5.1657x; 1.1474x over previous
#include <cuda_runtime.h>
#include <cuda_bf16.h>
#include <mma.h>
#include <cstdint>

using namespace nvcuda;

#define NP   8192
#define FD   128
#define C0N  256
#define C1N  128
#define BN_EPS 1e-3f
#define KSPLIT 2
#define KHALF (NP / KSPLIT)

typedef __nv_bfloat16 bf16;

// ---------------- cp.async helpers ------------------------------------------
__device__ __forceinline__ void cp16(void* dst_smem, const void* src) {
    unsigned int d = (unsigned int)__cvta_generic_to_shared(dst_smem);
    asm volatile("cp.async.cg.shared.global [%0], [%1], 16;\n" :: "r"(d), "l"(src));
}
__device__ __forceinline__ void cp_commit() { asm volatile("cp.async.commit_group;\n"); }
template <int N> __device__ __forceinline__ void cp_wait() {
    asm volatile("cp.async.wait_group %0;\n" :: "n"(N));
}

// ---------------- scratch (device globals; no allocation allowed) -----------
__device__ __align__(16) bf16  d_Adjb[(size_t)NP * NP];  // bf16 copy of adj
__device__ __align__(16) bf16  d_Xh[NP * FD];            // hi(X)  [n][f]
__device__ __align__(16) bf16  d_Xl[NP * FD];            // lo(X)  [n][f]
__device__ __align__(16) float d_deg[NP];                // column degree (accum)
__device__ __align__(16) float d_Rpre0[NP * FD];
__device__ __align__(16) float d_Rpre1[NP * FD];
__device__ __align__(16) float d_H[NP * C0N];
__device__ __align__(16) bf16  d_R2h[NP * C1N];          // hi(Rs @ K2) [k][c]
__device__ __align__(16) bf16  d_R2l[NP * C1N];          // lo(Rs @ K2) [k][c]
__device__ __align__(16) float d_O0[NP * C1N];
__device__ __align__(16) float d_O1[NP * C1N];
__device__ __align__(16) float d_O[NP * C1N];
__device__ float d_sum1[C0N], d_sq1[C0N], d_sc1[C0N], d_sh1[C0N];
__device__ float d_sum2[C1N], d_sq2[C1N], d_sc2[C1N], d_sh2[C1N];

// ---------------- prep: adj int32 -> bf16 (one pass, memory-bound) ----------
__global__ void __launch_bounds__(256) k_prep_adj(const int* __restrict__ adj) {
    size_t i = ((size_t)blockIdx.x * 256 + threadIdx.x) * 8;
    int4 a = *(const int4*)(adj + i);
    int4 b = *(const int4*)(adj + i + 4);
    bf16 o[8];
    o[0] = __float2bfloat16_rn((float)a.x);
    o[1] = __float2bfloat16_rn((float)a.y);
    o[2] = __float2bfloat16_rn((float)a.z);
    o[3] = __float2bfloat16_rn((float)a.w);
    o[4] = __float2bfloat16_rn((float)b.x);
    o[5] = __float2bfloat16_rn((float)b.y);
    o[6] = __float2bfloat16_rn((float)b.z);
    o[7] = __float2bfloat16_rn((float)b.w);
    *(uint4*)(d_Adjb + i) = *(uint4*)o;
}

// ------------ prep: X -> (Xh, Xl) bf16, fused accum zeroing ------------------
__global__ void __launch_bounds__(256) k_prep_x(const float* __restrict__ X) {
    if (blockIdx.x == 0) {
        int t = threadIdx.x;
        if (t < C0N) { d_sum1[t] = 0.f; d_sq1[t] = 0.f; }
        if (t < C1N) { d_sum2[t] = 0.f; d_sq2[t] = 0.f; }
    }
    if (threadIdx.x < 8) d_deg[blockIdx.x * 8 + threadIdx.x] = 0.f;
    size_t i = ((size_t)blockIdx.x * 256 + threadIdx.x) * 4;
    float4 x = *(const float4*)(X + i);
    bf16 h[4], l[4];
    h[0] = __float2bfloat16_rn(x.x); l[0] = __float2bfloat16_rn(x.x - __bfloat162float(h[0]));
    h[1] = __float2bfloat16_rn(x.y); l[1] = __float2bfloat16_rn(x.y - __bfloat162float(h[1]));
    h[2] = __float2bfloat16_rn(x.z); l[2] = __float2bfloat16_rn(x.z - __bfloat162float(h[2]));
    h[3] = __float2bfloat16_rn(x.w); l[3] = __float2bfloat16_rn(x.w - __bfloat162float(h[3]));
    *(uint2*)(d_Xh + i) = *(uint2*)h;
    *(uint2*)(d_Xl + i) = *(uint2*)l;
}

// ============================================================================
// GEMM1: Rpre_part = A^T @ X over one K half, fused degree partial.
// grid (64, 2). CTA tile M=128 (r), N=FD=128, BK=64.
// 8 warps as 2M x 4N, warp tile 64x32 -> 0.5 frag/MMA.
// A^T[r,k] = Adjb[k*NP + r]: smem As[k][r] (col_major frags).
// ============================================================================
#define G1_LDA 136
#define G1_LDX 136
#define G1_AS_BYTES (2 * 64 * G1_LDA * 2)              // 34816
#define G1_XB_BYTES (2 * 64 * G1_LDX * 2)              // 34816
#define G1_SMEM     (G1_AS_BYTES + 2 * G1_XB_BYTES)    // 104448

__global__ void __launch_bounds__(256) k_gemm1() {
    extern __shared__ __align__(16) char smem_raw[];
    bf16 (*As)[64][G1_LDA] = (bf16(*)[64][G1_LDA])smem_raw;                     // [buf][k][r]
    bf16 (*Xh)[64][G1_LDX] = (bf16(*)[64][G1_LDX])(smem_raw + G1_AS_BYTES);     // [buf][k][f]
    bf16 (*Xl)[64][G1_LDX] = (bf16(*)[64][G1_LDX])(smem_raw + G1_AS_BYTES + G1_XB_BYTES);

    const int r0    = blockIdx.x * 128;
    const int kbase = blockIdx.y * KHALF;
    const int tid   = threadIdx.x;
    const int warp  = tid >> 5;
    const int wm    = warp & 1;        // 2 M-groups of 64
    const int wn    = warp >> 1;       // 4 N-groups of 32

    wmma::fragment<wmma::accumulator, 16, 16, 16, float> acc[4][2];
#pragma unroll
    for (int i = 0; i < 4; i++)
#pragma unroll
        for (int j = 0; j < 2; j++) wmma::fill_fragment(acc[i][j], 0.0f);

    const int dr = tid & 127, dq = tid >> 7;
    float degp = 0.f;

    // prefetch tile 0 (4 cp16 per thread per matrix)
    {
#pragma unroll
        for (int s = 0; s < 4; s++) {
            int u = tid + s * 256, kk = u >> 4, rr = (u & 15) * 8;
            cp16(&As[0][kk][rr], d_Adjb + (size_t)(kbase + kk) * NP + r0 + rr);
            cp16(&Xh[0][kk][rr], d_Xh + (size_t)(kbase + kk) * FD + rr);
            cp16(&Xl[0][kk][rr], d_Xl + (size_t)(kbase + kk) * FD + rr);
        }
        cp_commit();
    }

    const int T = KHALF / 64;
    for (int t = 0; t < T; t++) {
        const int buf = t & 1;
        if (t + 1 < T) {
            const int nb = buf ^ 1;
            const int k1 = kbase + (t + 1) * 64;
#pragma unroll
            for (int s = 0; s < 4; s++) {
                int u = tid + s * 256, kk = u >> 4, rr = (u & 15) * 8;
                cp16(&As[nb][kk][rr], d_Adjb + (size_t)(k1 + kk) * NP + r0 + rr);
                cp16(&Xh[nb][kk][rr], d_Xh + (size_t)(k1 + kk) * FD + rr);
                cp16(&Xl[nb][kk][rr], d_Xl + (size_t)(k1 + kk) * FD + rr);
            }
            cp_commit();
            cp_wait<1>();
        } else {
            cp_wait<0>();
        }
        __syncthreads();

        // degree partial (bf16 0/1 exact): 2 threads per r, 32 k each
#pragma unroll
        for (int j = 0; j < 32; j++) degp += __bfloat162float(As[buf][dq * 32 + j][dr]);

#pragma unroll
        for (int ks = 0; ks < 4; ks++) {
            wmma::fragment<wmma::matrix_a, 16, 16, 16, bf16, wmma::col_major> af[4];
#pragma unroll
            for (int i = 0; i < 4; i++)
                wmma::load_matrix_sync(af[i], &As[buf][ks * 16][wm * 64 + i * 16], G1_LDA);
#pragma unroll
            for (int j = 0; j < 2; j++) {
                wmma::fragment<wmma::matrix_b, 16, 16, 16, bf16, wmma::row_major> bh, bl;
                wmma::load_matrix_sync(bh, &Xh[buf][ks * 16][wn * 32 + j * 16], G1_LDX);
                wmma::load_matrix_sync(bl, &Xl[buf][ks * 16][wn * 32 + j * 16], G1_LDX);
#pragma unroll
                for (int i = 0; i < 4; i++) {
                    wmma::mma_sync(acc[i][j], af[i], bh, acc[i][j]);
                    wmma::mma_sync(acc[i][j], af[i], bl, acc[i][j]);
                }
            }
        }
        __syncthreads();
    }

    float* dst = blockIdx.y ? d_Rpre1 : d_Rpre0;
#pragma unroll
    for (int i = 0; i < 4; i++)
#pragma unroll
        for (int j = 0; j < 2; j++)
            wmma::store_matrix_sync(&dst[(size_t)(r0 + wm * 64 + i * 16) * FD + wn * 32 + j * 16],
                                    acc[i][j], FD, wmma::mem_row_major);

    float* dbuf = (float*)smem_raw;
    dbuf[tid] = degp;
    __syncthreads();
    if (tid < 128) atomicAdd(&d_deg[r0 + tid], dbuf[tid] + dbuf[128 + tid]);
}

// ============================================================================
// GEMM3: O_part = A @ R2 over one K half.  grid (64, 2). CTA 128x128, BK=64.
// 8 warps as 2M x 4N, warp tile 64x32. A[p,k] = Adjb[p*NP+k] row-major.
// ============================================================================
#define G3_LDA 72
#define G3_LDB 136
#define G3_AS_BYTES (2 * 128 * G3_LDA * 2)             // 36864
#define G3_BB_BYTES (2 * 64 * G3_LDB * 2)              // 34816
#define G3_SMEM     (G3_AS_BYTES + 2 * G3_BB_BYTES)    // 106496

__global__ void __launch_bounds__(256) k_gemm3() {
    extern __shared__ __align__(16) char smem_raw[];
    bf16 (*As)[128][G3_LDA] = (bf16(*)[128][G3_LDA])smem_raw;                   // [buf][p][k]
    bf16 (*Bh)[64][G3_LDB]  = (bf16(*)[64][G3_LDB])(smem_raw + G3_AS_BYTES);    // [buf][k][c]
    bf16 (*Bl)[64][G3_LDB]  = (bf16(*)[64][G3_LDB])(smem_raw + G3_AS_BYTES + G3_BB_BYTES);

    const int p0    = blockIdx.x * 128;
    const int kbase = blockIdx.y * KHALF;
    const int tid   = threadIdx.x;
    const int warp  = tid >> 5;
    const int wm    = warp & 1;
    const int wn    = warp >> 1;

    wmma::fragment<wmma::accumulator, 16, 16, 16, float> acc[4][2];
#pragma unroll
    for (int i = 0; i < 4; i++)
#pragma unroll
        for (int j = 0; j < 2; j++) wmma::fill_fragment(acc[i][j], 0.0f);

    {
#pragma unroll
        for (int s = 0; s < 4; s++) {
            int u = tid + s * 256;
            int pp = u >> 3, kc = (u & 7) * 8;
            cp16(&As[0][pp][kc], d_Adjb + (size_t)(p0 + pp) * NP + kbase + kc);
            int kk = u >> 4, cc = (u & 15) * 8;
            cp16(&Bh[0][kk][cc], d_R2h + (size_t)(kbase + kk) * C1N + cc);
            cp16(&Bl[0][kk][cc], d_R2l + (size_t)(kbase + kk) * C1N + cc);
        }
        cp_commit();
    }

    const int T = KHALF / 64;
    for (int t = 0; t < T; t++) {
        const int buf = t & 1;
        if (t + 1 < T) {
            const int nb = buf ^ 1;
            const int k1 = kbase + (t + 1) * 64;
#pragma unroll
            for (int s = 0; s < 4; s++) {
                int u = tid + s * 256;
                int pp = u >> 3, kc = (u & 7) * 8;
                cp16(&As[nb][pp][kc], d_Adjb + (size_t)(p0 + pp) * NP + k1 + kc);
                int kk = u >> 4, cc = (u & 15) * 8;
                cp16(&Bh[nb][kk][cc], d_R2h + (size_t)(k1 + kk) * C1N + cc);
                cp16(&Bl[nb][kk][cc], d_R2l + (size_t)(k1 + kk) * C1N + cc);
            }
            cp_commit();
            cp_wait<1>();
        } else {
            cp_wait<0>();
        }
        __syncthreads();

#pragma unroll
        for (int ks = 0; ks < 4; ks++) {
            wmma::fragment<wmma::matrix_a, 16, 16, 16, bf16, wmma::row_major> af[4];
#pragma unroll
            for (int i = 0; i < 4; i++)
                wmma::load_matrix_sync(af[i], &As[buf][wm * 64 + i * 16][ks * 16], G3_LDA);
#pragma unroll
            for (int j = 0; j < 2; j++) {
                wmma::fragment<wmma::matrix_b, 16, 16, 16, bf16, wmma::row_major> bh, bl;
                wmma::load_matrix_sync(bh, &Bh[buf][ks * 16][wn * 32 + j * 16], G3_LDB);
                wmma::load_matrix_sync(bl, &Bl[buf][ks * 16][wn * 32 + j * 16], G3_LDB);
#pragma unroll
                for (int i = 0; i < 4; i++) {
                    wmma::mma_sync(acc[i][j], af[i], bh, acc[i][j]);
                    wmma::mma_sync(acc[i][j], af[i], bl, acc[i][j]);
                }
            }
        }
        __syncthreads();
    }

    float* dst = blockIdx.y ? d_O1 : d_O0;
#pragma unroll
    for (int i = 0; i < 4; i++)
#pragma unroll
        for (int j = 0; j < 2; j++)
            wmma::store_matrix_sync(&dst[(size_t)(p0 + wm * 64 + i * 16) * C1N + wn * 32 + j * 16],
                                    acc[i][j], C1N, wmma::mem_row_major);
}

// ============================================================================
// Small GEMM A: H = invdeg*((Rpre0+Rpre1)@K1)+b1, fused BN1 stats.
// ============================================================================
__global__ void __launch_bounds__(256) k_small_h(const float* __restrict__ B,
                                                 const float* __restrict__ bias) {
    __shared__ float As[16][65];
    __shared__ float Bs[16][64];
    __shared__ float red[2][16][64];

    const int m0 = blockIdx.x * 64, n0 = blockIdx.y * 64;
    const int tid = threadIdx.x, tx = tid & 15, ty = tid >> 4;

    float acc[4][4] = {};
    const int la_m = tid >> 2, la_k = (tid & 3) * 4;
    const int lb_k = tid >> 4, lb_n = (tid & 15) * 4;

    for (int k0 = 0; k0 < FD; k0 += 16) {
        size_t ga = (size_t)(m0 + la_m) * FD + k0 + la_k;
        float4 a4 = *(const float4*)(d_Rpre0 + ga);
        float4 b4 = *(const float4*)(d_Rpre1 + ga);
        As[la_k + 0][la_m] = a4.x + b4.x;
        As[la_k + 1][la_m] = a4.y + b4.y;
        As[la_k + 2][la_m] = a4.z + b4.z;
        As[la_k + 3][la_m] = a4.w + b4.w;
        *(float4*)&Bs[lb_k][lb_n] = *(const float4*)(B + (size_t)(k0 + lb_k) * C0N + n0 + lb_n);
        __syncthreads();
#pragma unroll
        for (int kk = 0; kk < 16; kk++) {
            float a[4], b[4];
#pragma unroll
            for (int i = 0; i < 4; i++) a[i] = As[kk][ty + i * 16];
#pragma unroll
            for (int j = 0; j < 4; j++) b[j] = Bs[kk][tx + j * 16];
#pragma unroll
            for (int i = 0; i < 4; i++)
#pragma unroll
                for (int j = 0; j < 4; j++) acc[i][j] = fmaf(a[i], b[j], acc[i][j]);
        }
        __syncthreads();
    }

    float ps[4] = {}, pq[4] = {};
#pragma unroll
    for (int i = 0; i < 4; i++) {
        int r = m0 + ty + i * 16;
        float dg = d_deg[r];
        float sc = (dg > 0.5f) ? (1.0f / dg) : 0.0f;
#pragma unroll
        for (int j = 0; j < 4; j++) {
            int c = n0 + tx + j * 16;
            float v = acc[i][j] * sc + bias[c];
            d_H[(size_t)r * C0N + c] = v;
            ps[j] += v;
            pq[j] = fmaf(v, v, pq[j]);
        }
    }
#pragma unroll
    for (int j = 0; j < 4; j++) {
        red[0][ty][tx + j * 16] = ps[j];
        red[1][ty][tx + j * 16] = pq[j];
    }
    __syncthreads();
    if (tid < 128) {
        int chl = tid & 63, which = tid >> 6;
        float s = 0.f;
#pragma unroll
        for (int t = 0; t < 16; t++) s += red[which][t][chl];
        atomicAdd((which ? d_sq1 : d_sum1) + n0 + chl, s);
    }
}

// ============================================================================
// Small GEMM B: R2 = [invdeg ⊙ BN1(H)] @ K2, output split bf16 hi/lo.
// ============================================================================
__global__ void __launch_bounds__(256) k_small_r2(const float* __restrict__ K2) {
    __shared__ float As[16][65];
    __shared__ float Bs[16][64];

    const int m0 = blockIdx.x * 64, n0 = blockIdx.y * 64;
    const int tid = threadIdx.x, tx = tid & 15, ty = tid >> 4;

    float acc[4][4] = {};
    const int la_m = tid >> 2, la_k = (tid & 3) * 4;
    const int lb_k = tid >> 4, lb_n = (tid & 15) * 4;
    const float dg  = d_deg[m0 + la_m];
    const float idg = (dg > 0.5f) ? (1.0f / dg) : 0.0f;

    for (int k0 = 0; k0 < C0N; k0 += 16) {
        float4 a4 = *(const float4*)(d_H + (size_t)(m0 + la_m) * C0N + k0 + la_k);
        float4 sc = *(const float4*)(d_sc1 + k0 + la_k);
        float4 sh = *(const float4*)(d_sh1 + k0 + la_k);
        As[la_k + 0][la_m] = idg * fmaf(a4.x, sc.x, sh.x);
        As[la_k + 1][la_m] = idg * fmaf(a4.y, sc.y, sh.y);
        As[la_k + 2][la_m] = idg * fmaf(a4.z, sc.z, sh.z);
        As[la_k + 3][la_m] = idg * fmaf(a4.w, sc.w, sh.w);
        *(float4*)&Bs[lb_k][lb_n] = *(const float4*)(K2 + (size_t)(k0 + lb_k) * C1N + n0 + lb_n);
        __syncthreads();
#pragma unroll
        for (int kk = 0; kk < 16; kk++) {
            float a[4], b[4];
#pragma unroll
            for (int i = 0; i < 4; i++) a[i] = As[kk][ty + i * 16];
#pragma unroll
            for (int j = 0; j < 4; j++) b[j] = Bs[kk][tx + j * 16];
#pragma unroll
            for (int i = 0; i < 4; i++)
#pragma unroll
                for (int j = 0; j < 4; j++) acc[i][j] = fmaf(a[i], b[j], acc[i][j]);
        }
        __syncthreads();
    }

#pragma unroll
    for (int i = 0; i < 4; i++) {
        int r = m0 + ty + i * 16;
#pragma unroll
        for (int j = 0; j < 4; j++) {
            int c = n0 + tx + j * 16;
            float v = acc[i][j];
            bf16 h = __float2bfloat16_rn(v);
            d_R2h[(size_t)r * C1N + c] = h;
            d_R2l[(size_t)r * C1N + c] = __float2bfloat16_rn(v - __bfloat162float(h));
        }
    }
}

// ------------- combine O partials + bias, BN2 stats --------------------------
__global__ void __launch_bounds__(128) k_stats2(const float* __restrict__ bias2) {
    const int c  = threadIdx.x;
    const int r0 = blockIdx.x * 64;
    const float b = bias2[c];
    float s = 0.f, q = 0.f;
#pragma unroll 4
    for (int r = r0; r < r0 + 64; r++) {
        size_t idx = (size_t)r * C1N + c;
        float v = d_O0[idx] + d_O1[idx] + b;
        d_O[idx] = v;
        s += v;
        q = fmaf(v, v, q);
    }
    atomicAdd(&d_sum2[c], s);
    atomicAdd(&d_sq2[c], q);
}

// ---------------- BN finalize + output --------------------------------------
__global__ void k_fin1(const float* __restrict__ gamma, const float* __restrict__ beta) {
    int c = threadIdx.x;  // 256
    float mean = d_sum1[c] * (1.0f / NP);
    float var  = d_sq1[c] * (1.0f / NP) - mean * mean;
    float sc   = gamma[c] * rsqrtf(var + BN_EPS);
    d_sc1[c] = sc;
    d_sh1[c] = beta[c] - mean * sc;
}

__global__ void k_fin2(const float* __restrict__ gamma, const float* __restrict__ beta) {
    int c = threadIdx.x;  // 128
    float mean = d_sum2[c] * (1.0f / NP);
    float var  = d_sq2[c] * (1.0f / NP) - mean * mean;
    float sc   = gamma[c] * rsqrtf(var + BN_EPS);
    d_sc2[c] = sc;
    d_sh2[c] = beta[c] - mean * sc;
}

__global__ void k_out(float* __restrict__ out) {
    int idx = blockIdx.x * 256 + threadIdx.x;
    int c = idx & (C1N - 1);
    out[idx] = fmaf(d_O[idx], d_sc2[c], d_sh2[c]);
}

// ---------------- launch ----------------------------------------------------
extern "C" void kernel_launch(void* const* d_in, const int* in_sizes, int n_in,
                              void* d_out, int out_size) {
    const float* features = (const float*)d_in[0];
    const int*   adj      = (const int*)d_in[1];
    const float* kernel_1 = (const float*)d_in[2];
    const float* bias_1   = (const float*)d_in[3];
    const float* gamma_1  = (const float*)d_in[4];
    const float* beta_1   = (const float*)d_in[5];
    const float* kernel_2 = (const float*)d_in[6];
    const float* bias_2   = (const float*)d_in[7];
    const float* gamma_2  = (const float*)d_in[8];
    const float* beta_2   = (const float*)d_in[9];
    float* out = (float*)d_out;

    cudaFuncSetAttribute(k_gemm1, cudaFuncAttributeMaxDynamicSharedMemorySize, G1_SMEM);
    cudaFuncSetAttribute(k_gemm3, cudaFuncAttributeMaxDynamicSharedMemorySize, G3_SMEM);

    k_prep_adj<<<(int)(((size_t)NP * NP) / (256 * 8)), 256>>>(adj);     // adj -> bf16
    k_prep_x<<<NP * FD / (256 * 4), 256>>>(features);                   // X hi/lo + zeroing
    k_gemm1<<<dim3(NP / 128, KSPLIT), 256, G1_SMEM>>>();                // Rpre partials + deg
    k_small_h<<<dim3(NP / 64, C0N / 64), 256>>>(kernel_1, bias_1);      // H + stats1
    k_fin1<<<1, C0N>>>(gamma_1, beta_1);
    k_small_r2<<<dim3(NP / 64, C1N / 64), 256>>>(kernel_2);             // R2 hi/lo
    k_gemm3<<<dim3(NP / 128, KSPLIT), 256, G3_SMEM>>>();                // O partials
    k_stats2<<<NP / 64, 128>>>(bias_2);                                 // combine + stats2
    k_fin2<<<1, C1N>>>(gamma_2, beta_2);
    k_out<<<NP * C1N / 256, 256>>>(out);
}

// round 12
// speedup vs baseline: 5.1944x; 1.0055x over previous
#include <cuda_runtime.h>
#include <cuda_bf16.h>
#include <mma.h>
#include <cstdint>

using namespace nvcuda;

#define NP   8192
#define FD   128
#define C0N  256
#define C1N  128
#define BN_EPS 1e-3f
#define KSPLIT 2
#define KHALF (NP / KSPLIT)

typedef __nv_bfloat16 bf16;

// ---------------- cp.async helpers ------------------------------------------
__device__ __forceinline__ void cp16(void* dst_smem, const void* src) {
    unsigned int d = (unsigned int)__cvta_generic_to_shared(dst_smem);
    asm volatile("cp.async.cg.shared.global [%0], [%1], 16;\n" :: "r"(d), "l"(src));
}
__device__ __forceinline__ void cp_commit() { asm volatile("cp.async.commit_group;\n"); }
template <int N> __device__ __forceinline__ void cp_wait() {
    asm volatile("cp.async.wait_group %0;\n" :: "n"(N));
}

// ---------------- scratch (device globals; no allocation allowed) -----------
__device__ __align__(16) bf16  d_Adjb[(size_t)NP * NP];  // bf16 copy of adj
__device__ __align__(16) bf16  d_Xh[NP * FD];            // hi(X)  [n][f]
__device__ __align__(16) bf16  d_Xl[NP * FD];            // lo(X)  [n][f]
__device__ __align__(16) float d_deg[NP];                // column degree (accum)
__device__ __align__(16) float d_Rpre0[NP * FD];
__device__ __align__(16) float d_Rpre1[NP * FD];
__device__ __align__(16) float d_H[NP * C0N];
__device__ __align__(16) bf16  d_R2h[NP * C1N];          // hi(Rs @ K2) [k][c]
__device__ __align__(16) bf16  d_R2l[NP * C1N];          // lo(Rs @ K2) [k][c]
__device__ __align__(16) float d_O0[NP * C1N];
__device__ __align__(16) float d_O1[NP * C1N];
__device__ __align__(16) float d_O[NP * C1N];
__device__ float d_sum1[C0N], d_sq1[C0N], d_sc1[C0N], d_sh1[C0N];
__device__ float d_sum2[C1N], d_sq2[C1N], d_sc2[C1N], d_sh2[C1N];

// ---- prep: adj int32 -> bf16, FUSED column-degree (128x128 tiles) ----------
// grid (64, 64): r-tile (columns), k-tile (rows). d_deg must be zeroed first.
__global__ void __launch_bounds__(256) k_prep_adj(const int* __restrict__ adj) {
    __shared__ float dred[8][128];
    const int r0 = blockIdx.x * 128;
    const int k0 = blockIdx.y * 128;
    const int tid = threadIdx.x;
    const int c4 = (tid & 31) * 4;     // fixed 4 columns per thread
    const int rb = tid >> 5;           // row group 0..7

    float dreg[4] = {0.f, 0.f, 0.f, 0.f};
#pragma unroll
    for (int s = 0; s < 16; s++) {
        int kl = rb + s * 8;
        const int* src = adj + (size_t)(k0 + kl) * NP + r0 + c4;
        int4 a = *(const int4*)src;
        bf16 o[4];
        o[0] = __float2bfloat16_rn((float)a.x);
        o[1] = __float2bfloat16_rn((float)a.y);
        o[2] = __float2bfloat16_rn((float)a.z);
        o[3] = __float2bfloat16_rn((float)a.w);
        *(uint2*)(d_Adjb + (size_t)(k0 + kl) * NP + r0 + c4) = *(uint2*)o;
        dreg[0] += (float)a.x;
        dreg[1] += (float)a.y;
        dreg[2] += (float)a.z;
        dreg[3] += (float)a.w;
    }
#pragma unroll
    for (int j = 0; j < 4; j++) dred[rb][c4 + j] = dreg[j];
    __syncthreads();
    if (tid < 128) {
        float s = 0.f;
#pragma unroll
        for (int g = 0; g < 8; g++) s += dred[g][tid];
        atomicAdd(&d_deg[r0 + tid], s);
    }
}

// ------------ prep: X -> (Xh, Xl) bf16, fused accum zeroing ------------------
__global__ void __launch_bounds__(256) k_prep_x(const float* __restrict__ X) {
    if (blockIdx.x == 0) {
        int t = threadIdx.x;
        if (t < C0N) { d_sum1[t] = 0.f; d_sq1[t] = 0.f; }
        if (t < C1N) { d_sum2[t] = 0.f; d_sq2[t] = 0.f; }
    }
    if (threadIdx.x < 8) d_deg[blockIdx.x * 8 + threadIdx.x] = 0.f;
    size_t i = ((size_t)blockIdx.x * 256 + threadIdx.x) * 4;
    float4 x = *(const float4*)(X + i);
    bf16 h[4], l[4];
    h[0] = __float2bfloat16_rn(x.x); l[0] = __float2bfloat16_rn(x.x - __bfloat162float(h[0]));
    h[1] = __float2bfloat16_rn(x.y); l[1] = __float2bfloat16_rn(x.y - __bfloat162float(h[1]));
    h[2] = __float2bfloat16_rn(x.z); l[2] = __float2bfloat16_rn(x.z - __bfloat162float(h[2]));
    h[3] = __float2bfloat16_rn(x.w); l[3] = __float2bfloat16_rn(x.w - __bfloat162float(h[3]));
    *(uint2*)(d_Xh + i) = *(uint2*)h;
    *(uint2*)(d_Xl + i) = *(uint2*)l;
}

// ============================================================================
// GEMM1: Rpre_part = A^T @ X over one K half (pure GEMM now).
// grid (64, 2). CTA 128x128, BK=64. 8 warps 2M x 4N, warp 64x32.
// A^T[r,k] = Adjb[k*NP + r]: smem As[k][r] (col_major frags).
// hi/lo reordered: all-hi pass then all-lo pass (dep distance 8).
// ============================================================================
#define G1_LDA 136
#define G1_LDX 136
#define G1_AS_BYTES (2 * 64 * G1_LDA * 2)
#define G1_XB_BYTES (2 * 64 * G1_LDX * 2)
#define G1_SMEM     (G1_AS_BYTES + 2 * G1_XB_BYTES)    // 104448

__global__ void __launch_bounds__(256) k_gemm1() {
    extern __shared__ __align__(16) char smem_raw[];
    bf16 (*As)[64][G1_LDA] = (bf16(*)[64][G1_LDA])smem_raw;                     // [buf][k][r]
    bf16 (*Xh)[64][G1_LDX] = (bf16(*)[64][G1_LDX])(smem_raw + G1_AS_BYTES);     // [buf][k][f]
    bf16 (*Xl)[64][G1_LDX] = (bf16(*)[64][G1_LDX])(smem_raw + G1_AS_BYTES + G1_XB_BYTES);

    const int r0    = blockIdx.x * 128;
    const int kbase = blockIdx.y * KHALF;
    const int tid   = threadIdx.x;
    const int warp  = tid >> 5;
    const int wm    = warp & 1;
    const int wn    = warp >> 1;

    wmma::fragment<wmma::accumulator, 16, 16, 16, float> acc[4][2];
#pragma unroll
    for (int i = 0; i < 4; i++)
#pragma unroll
        for (int j = 0; j < 2; j++) wmma::fill_fragment(acc[i][j], 0.0f);

    {
#pragma unroll
        for (int s = 0; s < 4; s++) {
            int u = tid + s * 256, kk = u >> 4, rr = (u & 15) * 8;
            cp16(&As[0][kk][rr], d_Adjb + (size_t)(kbase + kk) * NP + r0 + rr);
            cp16(&Xh[0][kk][rr], d_Xh + (size_t)(kbase + kk) * FD + rr);
            cp16(&Xl[0][kk][rr], d_Xl + (size_t)(kbase + kk) * FD + rr);
        }
        cp_commit();
    }

    const int T = KHALF / 64;
    for (int t = 0; t < T; t++) {
        const int buf = t & 1;
        if (t + 1 < T) {
            const int nb = buf ^ 1;
            const int k1 = kbase + (t + 1) * 64;
#pragma unroll
            for (int s = 0; s < 4; s++) {
                int u = tid + s * 256, kk = u >> 4, rr = (u & 15) * 8;
                cp16(&As[nb][kk][rr], d_Adjb + (size_t)(k1 + kk) * NP + r0 + rr);
                cp16(&Xh[nb][kk][rr], d_Xh + (size_t)(k1 + kk) * FD + rr);
                cp16(&Xl[nb][kk][rr], d_Xl + (size_t)(k1 + kk) * FD + rr);
            }
            cp_commit();
            cp_wait<1>();
        } else {
            cp_wait<0>();
        }
        __syncthreads();

#pragma unroll
        for (int ks = 0; ks < 4; ks++) {
            wmma::fragment<wmma::matrix_a, 16, 16, 16, bf16, wmma::col_major> af[4];
#pragma unroll
            for (int i = 0; i < 4; i++)
                wmma::load_matrix_sync(af[i], &As[buf][ks * 16][wm * 64 + i * 16], G1_LDA);
            wmma::fragment<wmma::matrix_b, 16, 16, 16, bf16, wmma::row_major> bh[2], bl[2];
#pragma unroll
            for (int j = 0; j < 2; j++) {
                wmma::load_matrix_sync(bh[j], &Xh[buf][ks * 16][wn * 32 + j * 16], G1_LDX);
                wmma::load_matrix_sync(bl[j], &Xl[buf][ks * 16][wn * 32 + j * 16], G1_LDX);
            }
#pragma unroll
            for (int j = 0; j < 2; j++)
#pragma unroll
                for (int i = 0; i < 4; i++) wmma::mma_sync(acc[i][j], af[i], bh[j], acc[i][j]);
#pragma unroll
            for (int j = 0; j < 2; j++)
#pragma unroll
                for (int i = 0; i < 4; i++) wmma::mma_sync(acc[i][j], af[i], bl[j], acc[i][j]);
        }
        __syncthreads();
    }

    float* dst = blockIdx.y ? d_Rpre1 : d_Rpre0;
#pragma unroll
    for (int i = 0; i < 4; i++)
#pragma unroll
        for (int j = 0; j < 2; j++)
            wmma::store_matrix_sync(&dst[(size_t)(r0 + wm * 64 + i * 16) * FD + wn * 32 + j * 16],
                                    acc[i][j], FD, wmma::mem_row_major);
}

// ============================================================================
// GEMM3: O_part = A @ R2 over one K half.  grid (64, 2). CTA 128x128, BK=64.
// 8 warps 2M x 4N, warp 64x32. A[p,k] = Adjb[p*NP+k] row-major. hi/lo reordered.
// ============================================================================
#define G3_LDA 72
#define G3_LDB 136
#define G3_AS_BYTES (2 * 128 * G3_LDA * 2)             // 36864
#define G3_BB_BYTES (2 * 64 * G3_LDB * 2)              // 34816
#define G3_SMEM     (G3_AS_BYTES + 2 * G3_BB_BYTES)    // 106496

__global__ void __launch_bounds__(256) k_gemm3() {
    extern __shared__ __align__(16) char smem_raw[];
    bf16 (*As)[128][G3_LDA] = (bf16(*)[128][G3_LDA])smem_raw;                   // [buf][p][k]
    bf16 (*Bh)[64][G3_LDB]  = (bf16(*)[64][G3_LDB])(smem_raw + G3_AS_BYTES);    // [buf][k][c]
    bf16 (*Bl)[64][G3_LDB]  = (bf16(*)[64][G3_LDB])(smem_raw + G3_AS_BYTES + G3_BB_BYTES);

    const int p0    = blockIdx.x * 128;
    const int kbase = blockIdx.y * KHALF;
    const int tid   = threadIdx.x;
    const int warp  = tid >> 5;
    const int wm    = warp & 1;
    const int wn    = warp >> 1;

    wmma::fragment<wmma::accumulator, 16, 16, 16, float> acc[4][2];
#pragma unroll
    for (int i = 0; i < 4; i++)
#pragma unroll
        for (int j = 0; j < 2; j++) wmma::fill_fragment(acc[i][j], 0.0f);

    {
#pragma unroll
        for (int s = 0; s < 4; s++) {
            int u = tid + s * 256;
            int pp = u >> 3, kc = (u & 7) * 8;
            cp16(&As[0][pp][kc], d_Adjb + (size_t)(p0 + pp) * NP + kbase + kc);
            int kk = u >> 4, cc = (u & 15) * 8;
            cp16(&Bh[0][kk][cc], d_R2h + (size_t)(kbase + kk) * C1N + cc);
            cp16(&Bl[0][kk][cc], d_R2l + (size_t)(kbase + kk) * C1N + cc);
        }
        cp_commit();
    }

    const int T = KHALF / 64;
    for (int t = 0; t < T; t++) {
        const int buf = t & 1;
        if (t + 1 < T) {
            const int nb = buf ^ 1;
            const int k1 = kbase + (t + 1) * 64;
#pragma unroll
            for (int s = 0; s < 4; s++) {
                int u = tid + s * 256;
                int pp = u >> 3, kc = (u & 7) * 8;
                cp16(&As[nb][pp][kc], d_Adjb + (size_t)(p0 + pp) * NP + k1 + kc);
                int kk = u >> 4, cc = (u & 15) * 8;
                cp16(&Bh[nb][kk][cc], d_R2h + (size_t)(k1 + kk) * C1N + cc);
                cp16(&Bl[nb][kk][cc], d_R2l + (size_t)(k1 + kk) * C1N + cc);
            }
            cp_commit();
            cp_wait<1>();
        } else {
            cp_wait<0>();
        }
        __syncthreads();

#pragma unroll
        for (int ks = 0; ks < 4; ks++) {
            wmma::fragment<wmma::matrix_a, 16, 16, 16, bf16, wmma::row_major> af[4];
#pragma unroll
            for (int i = 0; i < 4; i++)
                wmma::load_matrix_sync(af[i], &As[buf][wm * 64 + i * 16][ks * 16], G3_LDA);
            wmma::fragment<wmma::matrix_b, 16, 16, 16, bf16, wmma::row_major> bh[2], bl[2];
#pragma unroll
            for (int j = 0; j < 2; j++) {
                wmma::load_matrix_sync(bh[j], &Bh[buf][ks * 16][wn * 32 + j * 16], G3_LDB);
                wmma::load_matrix_sync(bl[j], &Bl[buf][ks * 16][wn * 32 + j * 16], G3_LDB);
            }
#pragma unroll
            for (int j = 0; j < 2; j++)
#pragma unroll
                for (int i = 0; i < 4; i++) wmma::mma_sync(acc[i][j], af[i], bh[j], acc[i][j]);
#pragma unroll
            for (int j = 0; j < 2; j++)
#pragma unroll
                for (int i = 0; i < 4; i++) wmma::mma_sync(acc[i][j], af[i], bl[j], acc[i][j]);
        }
        __syncthreads();
    }

    float* dst = blockIdx.y ? d_O1 : d_O0;
#pragma unroll
    for (int i = 0; i < 4; i++)
#pragma unroll
        for (int j = 0; j < 2; j++)
            wmma::store_matrix_sync(&dst[(size_t)(p0 + wm * 64 + i * 16) * C1N + wn * 32 + j * 16],
                                    acc[i][j], C1N, wmma::mem_row_major);
}

// ============================================================================
// Small GEMM A: H = invdeg*((Rpre0+Rpre1)@K1)+b1, fused BN1 stats.
// ============================================================================
__global__ void __launch_bounds__(256) k_small_h(const float* __restrict__ B,
                                                 const float* __restrict__ bias) {
    __shared__ float As[16][65];
    __shared__ float Bs[16][64];
    __shared__ float red[2][16][64];

    const int m0 = blockIdx.x * 64, n0 = blockIdx.y * 64;
    const int tid = threadIdx.x, tx = tid & 15, ty = tid >> 4;

    float acc[4][4] = {};
    const int la_m = tid >> 2, la_k = (tid & 3) * 4;
    const int lb_k = tid >> 4, lb_n = (tid & 15) * 4;

    for (int k0 = 0; k0 < FD; k0 += 16) {
        size_t ga = (size_t)(m0 + la_m) * FD + k0 + la_k;
        float4 a4 = *(const float4*)(d_Rpre0 + ga);
        float4 b4 = *(const float4*)(d_Rpre1 + ga);
        As[la_k + 0][la_m] = a4.x + b4.x;
        As[la_k + 1][la_m] = a4.y + b4.y;
        As[la_k + 2][la_m] = a4.z + b4.z;
        As[la_k + 3][la_m] = a4.w + b4.w;
        *(float4*)&Bs[lb_k][lb_n] = *(const float4*)(B + (size_t)(k0 + lb_k) * C0N + n0 + lb_n);
        __syncthreads();
#pragma unroll
        for (int kk = 0; kk < 16; kk++) {
            float a[4], b[4];
#pragma unroll
            for (int i = 0; i < 4; i++) a[i] = As[kk][ty + i * 16];
#pragma unroll
            for (int j = 0; j < 4; j++) b[j] = Bs[kk][tx + j * 16];
#pragma unroll
            for (int i = 0; i < 4; i++)
#pragma unroll
                for (int j = 0; j < 4; j++) acc[i][j] = fmaf(a[i], b[j], acc[i][j]);
        }
        __syncthreads();
    }

    float ps[4] = {}, pq[4] = {};
#pragma unroll
    for (int i = 0; i < 4; i++) {
        int r = m0 + ty + i * 16;
        float dg = d_deg[r];
        float sc = (dg > 0.5f) ? (1.0f / dg) : 0.0f;
#pragma unroll
        for (int j = 0; j < 4; j++) {
            int c = n0 + tx + j * 16;
            float v = acc[i][j] * sc + bias[c];
            d_H[(size_t)r * C0N + c] = v;
            ps[j] += v;
            pq[j] = fmaf(v, v, pq[j]);
        }
    }
#pragma unroll
    for (int j = 0; j < 4; j++) {
        red[0][ty][tx + j * 16] = ps[j];
        red[1][ty][tx + j * 16] = pq[j];
    }
    __syncthreads();
    if (tid < 128) {
        int chl = tid & 63, which = tid >> 6;
        float s = 0.f;
#pragma unroll
        for (int t = 0; t < 16; t++) s += red[which][t][chl];
        atomicAdd((which ? d_sq1 : d_sum1) + n0 + chl, s);
    }
}

// ============================================================================
// Small GEMM B: R2 = [invdeg ⊙ BN1(H)] @ K2, output split bf16 hi/lo.
// ============================================================================
__global__ void __launch_bounds__(256) k_small_r2(const float* __restrict__ K2) {
    __shared__ float As[16][65];
    __shared__ float Bs[16][64];

    const int m0 = blockIdx.x * 64, n0 = blockIdx.y * 64;
    const int tid = threadIdx.x, tx = tid & 15, ty = tid >> 4;

    float acc[4][4] = {};
    const int la_m = tid >> 2, la_k = (tid & 3) * 4;
    const int lb_k = tid >> 4, lb_n = (tid & 15) * 4;
    const float dg  = d_deg[m0 + la_m];
    const float idg = (dg > 0.5f) ? (1.0f / dg) : 0.0f;

    for (int k0 = 0; k0 < C0N; k0 += 16) {
        float4 a4 = *(const float4*)(d_H + (size_t)(m0 + la_m) * C0N + k0 + la_k);
        float4 sc = *(const float4*)(d_sc1 + k0 + la_k);
        float4 sh = *(const float4*)(d_sh1 + k0 + la_k);
        As[la_k + 0][la_m] = idg * fmaf(a4.x, sc.x, sh.x);
        As[la_k + 1][la_m] = idg * fmaf(a4.y, sc.y, sh.y);
        As[la_k + 2][la_m] = idg * fmaf(a4.z, sc.z, sh.z);
        As[la_k + 3][la_m] = idg * fmaf(a4.w, sc.w, sh.w);
        *(float4*)&Bs[lb_k][lb_n] = *(const float4*)(K2 + (size_t)(k0 + lb_k) * C1N + n0 + lb_n);
        __syncthreads();
#pragma unroll
        for (int kk = 0; kk < 16; kk++) {
            float a[4], b[4];
#pragma unroll
            for (int i = 0; i < 4; i++) a[i] = As[kk][ty + i * 16];
#pragma unroll
            for (int j = 0; j < 4; j++) b[j] = Bs[kk][tx + j * 16];
#pragma unroll
            for (int i = 0; i < 4; i++)
#pragma unroll
                for (int j = 0; j < 4; j++) acc[i][j] = fmaf(a[i], b[j], acc[i][j]);
        }
        __syncthreads();
    }

#pragma unroll
    for (int i = 0; i < 4; i++) {
        int r = m0 + ty + i * 16;
#pragma unroll
        for (int j = 0; j < 4; j++) {
            int c = n0 + tx + j * 16;
            float v = acc[i][j];
            bf16 h = __float2bfloat16_rn(v);
            d_R2h[(size_t)r * C1N + c] = h;
            d_R2l[(size_t)r * C1N + c] = __float2bfloat16_rn(v - __bfloat162float(h));
        }
    }
}

// ------------- combine O partials + bias, BN2 stats --------------------------
__global__ void __launch_bounds__(128) k_stats2(const float* __restrict__ bias2) {
    const int c  = threadIdx.x;
    const int r0 = blockIdx.x * 64;
    const float b = bias2[c];
    float s = 0.f, q = 0.f;
#pragma unroll 4
    for (int r = r0; r < r0 + 64; r++) {
        size_t idx = (size_t)r * C1N + c;
        float v = d_O0[idx] + d_O1[idx] + b;
        d_O[idx] = v;
        s += v;
        q = fmaf(v, v, q);
    }
    atomicAdd(&d_sum2[c], s);
    atomicAdd(&d_sq2[c], q);
}

// ---------------- BN finalize + output --------------------------------------
__global__ void k_fin1(const float* __restrict__ gamma, const float* __restrict__ beta) {
    int c = threadIdx.x;  // 256
    float mean = d_sum1[c] * (1.0f / NP);
    float var  = d_sq1[c] * (1.0f / NP) - mean * mean;
    float sc   = gamma[c] * rsqrtf(var + BN_EPS);
    d_sc1[c] = sc;
    d_sh1[c] = beta[c] - mean * sc;
}

__global__ void k_fin2(const float* __restrict__ gamma, const float* __restrict__ beta) {
    int c = threadIdx.x;  // 128
    float mean = d_sum2[c] * (1.0f / NP);
    float var  = d_sq2[c] * (1.0f / NP) - mean * mean;
    float sc   = gamma[c] * rsqrtf(var + BN_EPS);
    d_sc2[c] = sc;
    d_sh2[c] = beta[c] - mean * sc;
}

__global__ void k_out(float* __restrict__ out) {
    int idx = blockIdx.x * 256 + threadIdx.x;
    int c = idx & (C1N - 1);
    out[idx] = fmaf(d_O[idx], d_sc2[c], d_sh2[c]);
}

// ---------------- launch ----------------------------------------------------
extern "C" void kernel_launch(void* const* d_in, const int* in_sizes, int n_in,
                              void* d_out, int out_size) {
    const float* features = (const float*)d_in[0];
    const int*   adj      = (const int*)d_in[1];
    const float* kernel_1 = (const float*)d_in[2];
    const float* bias_1   = (const float*)d_in[3];
    const float* gamma_1  = (const float*)d_in[4];
    const float* beta_1   = (const float*)d_in[5];
    const float* kernel_2 = (const float*)d_in[6];
    const float* bias_2   = (const float*)d_in[7];
    const float* gamma_2  = (const float*)d_in[8];
    const float* beta_2   = (const float*)d_in[9];
    float* out = (float*)d_out;

    cudaFuncSetAttribute(k_gemm1, cudaFuncAttributeMaxDynamicSharedMemorySize, G1_SMEM);
    cudaFuncSetAttribute(k_gemm3, cudaFuncAttributeMaxDynamicSharedMemorySize, G3_SMEM);

    k_prep_x<<<NP * FD / (256 * 4), 256>>>(features);                   // X hi/lo + zero deg/sums
    k_prep_adj<<<dim3(NP / 128, NP / 128), 256>>>(adj);                 // adj -> bf16 + degree
    k_gemm1<<<dim3(NP / 128, KSPLIT), 256, G1_SMEM>>>();                // Rpre partials
    k_small_h<<<dim3(NP / 64, C0N / 64), 256>>>(kernel_1, bias_1);      // H + stats1
    k_fin1<<<1, C0N>>>(gamma_1, beta_1);
    k_small_r2<<<dim3(NP / 64, C1N / 64), 256>>>(kernel_2);             // R2 hi/lo
    k_gemm3<<<dim3(NP / 128, KSPLIT), 256, G3_SMEM>>>();                // O partials
    k_stats2<<<NP / 64, 128>>>(bias_2);                                 // combine + stats2
    k_fin2<<<1, C1N>>>(gamma_2, beta_2);
    k_out<<<NP * C1N / 256, 256>>>(out);
}

// round 13
// speedup vs baseline: 7.8838x; 1.5178x over previous
#include <cuda_runtime.h>
#include <cuda_bf16.h>
#include <cuda_fp16.h>
#include <mma.h>
#include <cstdint>

using namespace nvcuda;

#define NP   8192
#define FD   128
#define C0N  256
#define C1N  128
#define BN_EPS 1e-3f
#define KSPLIT 2
#define KHALF (NP / KSPLIT)

// ---------------- cp.async helpers ------------------------------------------
__device__ __forceinline__ void cp16(void* dst_smem, const void* src) {
    unsigned int d = (unsigned int)__cvta_generic_to_shared(dst_smem);
    asm volatile("cp.async.cg.shared.global [%0], [%1], 16;\n" :: "r"(d), "l"(src));
}
__device__ __forceinline__ void cp_commit() { asm volatile("cp.async.commit_group;\n"); }
template <int N> __device__ __forceinline__ void cp_wait() {
    asm volatile("cp.async.wait_group %0;\n" :: "n"(N));
}

// ---------------- scratch (device globals; no allocation allowed) -----------
__device__ __align__(16) __half d_Adjh[(size_t)NP * NP]; // fp16 copy of adj (exact 0/1)
__device__ __align__(16) __half d_Xf[NP * FD];           // fp16(X) [n][f]
__device__ __align__(16) float  d_deg[NP];               // column degree (accum)
__device__ __align__(16) float  d_Rpre0[NP * FD];
__device__ __align__(16) float  d_Rpre1[NP * FD];
__device__ __align__(16) float  d_H[NP * C0N];
__device__ __align__(16) __half d_R2f[NP * C1N];         // fp16(4096*invdeg*BN1(H) @ K2) [k][c]
__device__ __align__(16) float  d_O0[NP * C1N];
__device__ __align__(16) float  d_O1[NP * C1N];
__device__ __align__(16) float  d_O[NP * C1N];
__device__ float d_sum1[C0N], d_sq1[C0N], d_sc1[C0N], d_sh1[C0N];
__device__ float d_sum2[C1N], d_sq2[C1N], d_sc2[C1N], d_sh2[C1N];

// ---- prep: adj int32 -> fp16, FUSED column-degree (128x128 tiles) ----------
__global__ void __launch_bounds__(256) k_prep_adj(const int* __restrict__ adj) {
    __shared__ float dred[8][128];
    const int r0 = blockIdx.x * 128;
    const int k0 = blockIdx.y * 128;
    const int tid = threadIdx.x;
    const int c4 = (tid & 31) * 4;
    const int rb = tid >> 5;

    float dreg[4] = {0.f, 0.f, 0.f, 0.f};
#pragma unroll
    for (int s = 0; s < 16; s++) {
        int kl = rb + s * 8;
        int4 a = *(const int4*)(adj + (size_t)(k0 + kl) * NP + r0 + c4);
        __half o[4];
        o[0] = __float2half_rn((float)a.x);
        o[1] = __float2half_rn((float)a.y);
        o[2] = __float2half_rn((float)a.z);
        o[3] = __float2half_rn((float)a.w);
        *(uint2*)(d_Adjh + (size_t)(k0 + kl) * NP + r0 + c4) = *(uint2*)o;
        dreg[0] += (float)a.x;
        dreg[1] += (float)a.y;
        dreg[2] += (float)a.z;
        dreg[3] += (float)a.w;
    }
#pragma unroll
    for (int j = 0; j < 4; j++) dred[rb][c4 + j] = dreg[j];
    __syncthreads();
    if (tid < 128) {
        float s = 0.f;
#pragma unroll
        for (int g = 0; g < 8; g++) s += dred[g][tid];
        atomicAdd(&d_deg[r0 + tid], s);
    }
}

// ------------ prep: X -> fp16, fused accum zeroing ---------------------------
__global__ void __launch_bounds__(256) k_prep_x(const float* __restrict__ X) {
    if (blockIdx.x == 0) {
        int t = threadIdx.x;
        if (t < C0N) { d_sum1[t] = 0.f; d_sq1[t] = 0.f; }
        if (t < C1N) { d_sum2[t] = 0.f; d_sq2[t] = 0.f; }
    }
    if (threadIdx.x < 8) d_deg[blockIdx.x * 8 + threadIdx.x] = 0.f;
    size_t i = ((size_t)blockIdx.x * 256 + threadIdx.x) * 4;
    float4 x = *(const float4*)(X + i);
    __half h[4];
    h[0] = __float2half_rn(x.x);
    h[1] = __float2half_rn(x.y);
    h[2] = __float2half_rn(x.z);
    h[3] = __float2half_rn(x.w);
    *(uint2*)(d_Xf + i) = *(uint2*)h;
}

// ============================================================================
// GEMM1: Rpre_part = A^T @ X over one K half (single-pass fp16).
// grid (64, 2). CTA 128x128, BK=64. 8 warps 2M x 4N, warp 64x32.
// A^T[r,k] = Adjh[k*NP + r]: smem As[k][r] (col_major frags).
// ============================================================================
#define G1_LDA 136
#define G1_LDX 136
#define G1_AS_BYTES (2 * 64 * G1_LDA * 2)              // 34816
#define G1_SMEM     (G1_AS_BYTES + 2 * 64 * G1_LDX * 2) // 69632

__global__ void __launch_bounds__(256) k_gemm1() {
    extern __shared__ __align__(16) char smem_raw[];
    __half (*As)[64][G1_LDA] = (__half(*)[64][G1_LDA])smem_raw;                  // [buf][k][r]
    __half (*Xs)[64][G1_LDX] = (__half(*)[64][G1_LDX])(smem_raw + G1_AS_BYTES);  // [buf][k][f]

    const int r0    = blockIdx.x * 128;
    const int kbase = blockIdx.y * KHALF;
    const int tid   = threadIdx.x;
    const int warp  = tid >> 5;
    const int wm    = warp & 1;
    const int wn    = warp >> 1;

    wmma::fragment<wmma::accumulator, 16, 16, 16, float> acc[4][2];
#pragma unroll
    for (int i = 0; i < 4; i++)
#pragma unroll
        for (int j = 0; j < 2; j++) wmma::fill_fragment(acc[i][j], 0.0f);

    {
#pragma unroll
        for (int s = 0; s < 4; s++) {
            int u = tid + s * 256, kk = u >> 4, rr = (u & 15) * 8;
            cp16(&As[0][kk][rr], d_Adjh + (size_t)(kbase + kk) * NP + r0 + rr);
            cp16(&Xs[0][kk][rr], d_Xf + (size_t)(kbase + kk) * FD + rr);
        }
        cp_commit();
    }

    const int T = KHALF / 64;
    for (int t = 0; t < T; t++) {
        const int buf = t & 1;
        if (t + 1 < T) {
            const int nb = buf ^ 1;
            const int k1 = kbase + (t + 1) * 64;
#pragma unroll
            for (int s = 0; s < 4; s++) {
                int u = tid + s * 256, kk = u >> 4, rr = (u & 15) * 8;
                cp16(&As[nb][kk][rr], d_Adjh + (size_t)(k1 + kk) * NP + r0 + rr);
                cp16(&Xs[nb][kk][rr], d_Xf + (size_t)(k1 + kk) * FD + rr);
            }
            cp_commit();
            cp_wait<1>();
        } else {
            cp_wait<0>();
        }
        __syncthreads();

#pragma unroll
        for (int ks = 0; ks < 4; ks++) {
            wmma::fragment<wmma::matrix_a, 16, 16, 16, __half, wmma::col_major> af[4];
#pragma unroll
            for (int i = 0; i < 4; i++)
                wmma::load_matrix_sync(af[i], &As[buf][ks * 16][wm * 64 + i * 16], G1_LDA);
            wmma::fragment<wmma::matrix_b, 16, 16, 16, __half, wmma::row_major> bf[2];
#pragma unroll
            for (int j = 0; j < 2; j++)
                wmma::load_matrix_sync(bf[j], &Xs[buf][ks * 16][wn * 32 + j * 16], G1_LDX);
#pragma unroll
            for (int j = 0; j < 2; j++)
#pragma unroll
                for (int i = 0; i < 4; i++) wmma::mma_sync(acc[i][j], af[i], bf[j], acc[i][j]);
        }
        __syncthreads();
    }

    float* dst = blockIdx.y ? d_Rpre1 : d_Rpre0;
#pragma unroll
    for (int i = 0; i < 4; i++)
#pragma unroll
        for (int j = 0; j < 2; j++)
            wmma::store_matrix_sync(&dst[(size_t)(r0 + wm * 64 + i * 16) * FD + wn * 32 + j * 16],
                                    acc[i][j], FD, wmma::mem_row_major);
}

// ============================================================================
// GEMM3: O_part = A @ R2f over one K half (single-pass fp16).
// grid (64, 2). CTA 128x128, BK=64. A[p,k] = Adjh[p*NP+k] row-major.
// ============================================================================
#define G3_LDA 72
#define G3_LDB 136
#define G3_AS_BYTES (2 * 128 * G3_LDA * 2)             // 36864
#define G3_SMEM     (G3_AS_BYTES + 2 * 64 * G3_LDB * 2) // 71680

__global__ void __launch_bounds__(256) k_gemm3() {
    extern __shared__ __align__(16) char smem_raw[];
    __half (*As)[128][G3_LDA] = (__half(*)[128][G3_LDA])smem_raw;                 // [buf][p][k]
    __half (*Bs)[64][G3_LDB]  = (__half(*)[64][G3_LDB])(smem_raw + G3_AS_BYTES);  // [buf][k][c]

    const int p0    = blockIdx.x * 128;
    const int kbase = blockIdx.y * KHALF;
    const int tid   = threadIdx.x;
    const int warp  = tid >> 5;
    const int wm    = warp & 1;
    const int wn    = warp >> 1;

    wmma::fragment<wmma::accumulator, 16, 16, 16, float> acc[4][2];
#pragma unroll
    for (int i = 0; i < 4; i++)
#pragma unroll
        for (int j = 0; j < 2; j++) wmma::fill_fragment(acc[i][j], 0.0f);

    {
#pragma unroll
        for (int s = 0; s < 4; s++) {
            int u = tid + s * 256;
            int pp = u >> 3, kc = (u & 7) * 8;
            cp16(&As[0][pp][kc], d_Adjh + (size_t)(p0 + pp) * NP + kbase + kc);
            int kk = u >> 4, cc = (u & 15) * 8;
            cp16(&Bs[0][kk][cc], d_R2f + (size_t)(kbase + kk) * C1N + cc);
        }
        cp_commit();
    }

    const int T = KHALF / 64;
    for (int t = 0; t < T; t++) {
        const int buf = t & 1;
        if (t + 1 < T) {
            const int nb = buf ^ 1;
            const int k1 = kbase + (t + 1) * 64;
#pragma unroll
            for (int s = 0; s < 4; s++) {
                int u = tid + s * 256;
                int pp = u >> 3, kc = (u & 7) * 8;
                cp16(&As[nb][pp][kc], d_Adjh + (size_t)(p0 + pp) * NP + k1 + kc);
                int kk = u >> 4, cc = (u & 15) * 8;
                cp16(&Bs[nb][kk][cc], d_R2f + (size_t)(k1 + kk) * C1N + cc);
            }
            cp_commit();
            cp_wait<1>();
        } else {
            cp_wait<0>();
        }
        __syncthreads();

#pragma unroll
        for (int ks = 0; ks < 4; ks++) {
            wmma::fragment<wmma::matrix_a, 16, 16, 16, __half, wmma::row_major> af[4];
#pragma unroll
            for (int i = 0; i < 4; i++)
                wmma::load_matrix_sync(af[i], &As[buf][wm * 64 + i * 16][ks * 16], G3_LDA);
            wmma::fragment<wmma::matrix_b, 16, 16, 16, __half, wmma::row_major> bf[2];
#pragma unroll
            for (int j = 0; j < 2; j++)
                wmma::load_matrix_sync(bf[j], &Bs[buf][ks * 16][wn * 32 + j * 16], G3_LDB);
#pragma unroll
            for (int j = 0; j < 2; j++)
#pragma unroll
                for (int i = 0; i < 4; i++) wmma::mma_sync(acc[i][j], af[i], bf[j], acc[i][j]);
        }
        __syncthreads();
    }

    float* dst = blockIdx.y ? d_O1 : d_O0;
#pragma unroll
    for (int i = 0; i < 4; i++)
#pragma unroll
        for (int j = 0; j < 2; j++)
            wmma::store_matrix_sync(&dst[(size_t)(p0 + wm * 64 + i * 16) * C1N + wn * 32 + j * 16],
                                    acc[i][j], C1N, wmma::mem_row_major);
}

// ============================================================================
// Small GEMM A: H = invdeg*((Rpre0+Rpre1)@K1)+b1, fused BN1 stats.
// ============================================================================
__global__ void __launch_bounds__(256) k_small_h(const float* __restrict__ B,
                                                 const float* __restrict__ bias) {
    __shared__ float As[16][65];
    __shared__ float Bs[16][64];
    __shared__ float red[2][16][64];

    const int m0 = blockIdx.x * 64, n0 = blockIdx.y * 64;
    const int tid = threadIdx.x, tx = tid & 15, ty = tid >> 4;

    float acc[4][4] = {};
    const int la_m = tid >> 2, la_k = (tid & 3) * 4;
    const int lb_k = tid >> 4, lb_n = (tid & 15) * 4;

    for (int k0 = 0; k0 < FD; k0 += 16) {
        size_t ga = (size_t)(m0 + la_m) * FD + k0 + la_k;
        float4 a4 = *(const float4*)(d_Rpre0 + ga);
        float4 b4 = *(const float4*)(d_Rpre1 + ga);
        As[la_k + 0][la_m] = a4.x + b4.x;
        As[la_k + 1][la_m] = a4.y + b4.y;
        As[la_k + 2][la_m] = a4.z + b4.z;
        As[la_k + 3][la_m] = a4.w + b4.w;
        *(float4*)&Bs[lb_k][lb_n] = *(const float4*)(B + (size_t)(k0 + lb_k) * C0N + n0 + lb_n);
        __syncthreads();
#pragma unroll
        for (int kk = 0; kk < 16; kk++) {
            float a[4], b[4];
#pragma unroll
            for (int i = 0; i < 4; i++) a[i] = As[kk][ty + i * 16];
#pragma unroll
            for (int j = 0; j < 4; j++) b[j] = Bs[kk][tx + j * 16];
#pragma unroll
            for (int i = 0; i < 4; i++)
#pragma unroll
                for (int j = 0; j < 4; j++) acc[i][j] = fmaf(a[i], b[j], acc[i][j]);
        }
        __syncthreads();
    }

    float ps[4] = {}, pq[4] = {};
#pragma unroll
    for (int i = 0; i < 4; i++) {
        int r = m0 + ty + i * 16;
        float dg = d_deg[r];
        float sc = (dg > 0.5f) ? (1.0f / dg) : 0.0f;
#pragma unroll
        for (int j = 0; j < 4; j++) {
            int c = n0 + tx + j * 16;
            float v = acc[i][j] * sc + bias[c];
            d_H[(size_t)r * C0N + c] = v;
            ps[j] += v;
            pq[j] = fmaf(v, v, pq[j]);
        }
    }
#pragma unroll
    for (int j = 0; j < 4; j++) {
        red[0][ty][tx + j * 16] = ps[j];
        red[1][ty][tx + j * 16] = pq[j];
    }
    __syncthreads();
    if (tid < 128) {
        int chl = tid & 63, which = tid >> 6;
        float s = 0.f;
#pragma unroll
        for (int t = 0; t < 16; t++) s += red[which][t][chl];
        atomicAdd((which ? d_sq1 : d_sum1) + n0 + chl, s);
    }
}

// ============================================================================
// Small GEMM B: R2f = fp16( (4096*invdeg) ⊙ BN1(H) @ K2 )  — O(1)-scaled rows.
// ============================================================================
__global__ void __launch_bounds__(256) k_small_r2(const float* __restrict__ K2) {
    __shared__ float As[16][65];
    __shared__ float Bs[16][64];

    const int m0 = blockIdx.x * 64, n0 = blockIdx.y * 64;
    const int tid = threadIdx.x, tx = tid & 15, ty = tid >> 4;

    float acc[4][4] = {};
    const int la_m = tid >> 2, la_k = (tid & 3) * 4;
    const int lb_k = tid >> 4, lb_n = (tid & 15) * 4;
    const float dg  = d_deg[m0 + la_m];
    const float idg = (dg > 0.5f) ? (4096.0f / dg) : 0.0f;   // scaled invdeg

    for (int k0 = 0; k0 < C0N; k0 += 16) {
        float4 a4 = *(const float4*)(d_H + (size_t)(m0 + la_m) * C0N + k0 + la_k);
        float4 sc = *(const float4*)(d_sc1 + k0 + la_k);
        float4 sh = *(const float4*)(d_sh1 + k0 + la_k);
        As[la_k + 0][la_m] = idg * fmaf(a4.x, sc.x, sh.x);
        As[la_k + 1][la_m] = idg * fmaf(a4.y, sc.y, sh.y);
        As[la_k + 2][la_m] = idg * fmaf(a4.z, sc.z, sh.z);
        As[la_k + 3][la_m] = idg * fmaf(a4.w, sc.w, sh.w);
        *(float4*)&Bs[lb_k][lb_n] = *(const float4*)(K2 + (size_t)(k0 + lb_k) * C1N + n0 + lb_n);
        __syncthreads();
#pragma unroll
        for (int kk = 0; kk < 16; kk++) {
            float a[4], b[4];
#pragma unroll
            for (int i = 0; i < 4; i++) a[i] = As[kk][ty + i * 16];
#pragma unroll
            for (int j = 0; j < 4; j++) b[j] = Bs[kk][tx + j * 16];
#pragma unroll
            for (int i = 0; i < 4; i++)
#pragma unroll
                for (int j = 0; j < 4; j++) acc[i][j] = fmaf(a[i], b[j], acc[i][j]);
        }
        __syncthreads();
    }

#pragma unroll
    for (int i = 0; i < 4; i++) {
        int r = m0 + ty + i * 16;
#pragma unroll
        for (int j = 0; j < 4; j++) {
            int c = n0 + tx + j * 16;
            d_R2f[(size_t)r * C1N + c] = __float2half_rn(acc[i][j]);
        }
    }
}

// ------------- combine O partials (undo 4096 scale) + bias, BN2 stats --------
__global__ void __launch_bounds__(128) k_stats2(const float* __restrict__ bias2) {
    const int c  = threadIdx.x;
    const int r0 = blockIdx.x * 64;
    const float b = bias2[c];
    const float inv = 1.0f / 4096.0f;
    float s = 0.f, q = 0.f;
#pragma unroll 4
    for (int r = r0; r < r0 + 64; r++) {
        size_t idx = (size_t)r * C1N + c;
        float v = (d_O0[idx] + d_O1[idx]) * inv + b;
        d_O[idx] = v;
        s += v;
        q = fmaf(v, v, q);
    }
    atomicAdd(&d_sum2[c], s);
    atomicAdd(&d_sq2[c], q);
}

// ---------------- BN finalize + output --------------------------------------
__global__ void k_fin1(const float* __restrict__ gamma, const float* __restrict__ beta) {
    int c = threadIdx.x;  // 256
    float mean = d_sum1[c] * (1.0f / NP);
    float var  = d_sq1[c] * (1.0f / NP) - mean * mean;
    float sc   = gamma[c] * rsqrtf(var + BN_EPS);
    d_sc1[c] = sc;
    d_sh1[c] = beta[c] - mean * sc;
}

__global__ void k_fin2(const float* __restrict__ gamma, const float* __restrict__ beta) {
    int c = threadIdx.x;  // 128
    float mean = d_sum2[c] * (1.0f / NP);
    float var  = d_sq2[c] * (1.0f / NP) - mean * mean;
    float sc   = gamma[c] * rsqrtf(var + BN_EPS);
    d_sc2[c] = sc;
    d_sh2[c] = beta[c] - mean * sc;
}

__global__ void k_out(float* __restrict__ out) {
    int idx = blockIdx.x * 256 + threadIdx.x;
    int c = idx & (C1N - 1);
    out[idx] = fmaf(d_O[idx], d_sc2[c], d_sh2[c]);
}

// ---------------- launch ----------------------------------------------------
extern "C" void kernel_launch(void* const* d_in, const int* in_sizes, int n_in,
                              void* d_out, int out_size) {
    const float* features = (const float*)d_in[0];
    const int*   adj      = (const int*)d_in[1];
    const float* kernel_1 = (const float*)d_in[2];
    const float* bias_1   = (const float*)d_in[3];
    const float* gamma_1  = (const float*)d_in[4];
    const float* beta_1   = (const float*)d_in[5];
    const float* kernel_2 = (const float*)d_in[6];
    const float* bias_2   = (const float*)d_in[7];
    const float* gamma_2  = (const float*)d_in[8];
    const float* beta_2   = (const float*)d_in[9];
    float* out = (float*)d_out;

    cudaFuncSetAttribute(k_gemm1, cudaFuncAttributeMaxDynamicSharedMemorySize, G1_SMEM);
    cudaFuncSetAttribute(k_gemm3, cudaFuncAttributeMaxDynamicSharedMemorySize, G3_SMEM);

    k_prep_x<<<NP * FD / (256 * 4), 256>>>(features);                   // X fp16 + zero deg/sums
    k_prep_adj<<<dim3(NP / 128, NP / 128), 256>>>(adj);                 // adj -> fp16 + degree
    k_gemm1<<<dim3(NP / 128, KSPLIT), 256, G1_SMEM>>>();                // Rpre partials
    k_small_h<<<dim3(NP / 64, C0N / 64), 256>>>(kernel_1, bias_1);      // H + stats1
    k_fin1<<<1, C0N>>>(gamma_1, beta_1);
    k_small_r2<<<dim3(NP / 64, C1N / 64), 256>>>(kernel_2);             // R2f (scaled)
    k_gemm3<<<dim3(NP / 128, KSPLIT), 256, G3_SMEM>>>();                // O partials
    k_stats2<<<NP / 64, 128>>>(bias_2);                                 // combine + stats2
    k_fin2<<<1, C1N>>>(gamma_2, beta_2);
    k_out<<<NP * C1N / 256, 256>>>(out);
}

// round 14
// speedup vs baseline: 8.9884x; 1.1401x over previous
#include <cuda_runtime.h>
#include <cuda_bf16.h>
#include <cuda_fp16.h>
#include <mma.h>
#include <cstdint>

using namespace nvcuda;

#define NP   8192
#define FD   128
#define C0N  256
#define C1N  128
#define BN_EPS 1e-3f
#define KSPLIT 2
#define KHALF (NP / KSPLIT)

// ---------------- cp.async helpers ------------------------------------------
__device__ __forceinline__ void cp16(void* dst_smem, const void* src) {
    unsigned int d = (unsigned int)__cvta_generic_to_shared(dst_smem);
    asm volatile("cp.async.cg.shared.global [%0], [%1], 16;\n" :: "r"(d), "l"(src));
}
__device__ __forceinline__ void cp_commit() { asm volatile("cp.async.commit_group;\n"); }
template <int N> __device__ __forceinline__ void cp_wait() {
    asm volatile("cp.async.wait_group %0;\n" :: "n"(N));
}

// ---------------- scratch (device globals; no allocation allowed) -----------
__device__ __align__(16) __half d_Adjh[(size_t)NP * NP]; // fp16 adj (exact 0/1)
__device__ __align__(16) __half d_Xf[NP * FD];           // fp16(X) [n][f]
__device__ __align__(16) float  d_deg[NP];
__device__ __align__(16) float  d_Rpre0[NP * FD];
__device__ __align__(16) float  d_Rpre1[NP * FD];
__device__ __align__(16) __half d_RpH[NP * FD];          // hi(Rpre0+Rpre1)
__device__ __align__(16) __half d_RpL[NP * FD];          // lo(...)
__device__ __align__(16) __half d_K1h[FD * C0N];         // hi(K1)
__device__ __align__(16) __half d_K1l[FD * C0N];         // lo(K1)
__device__ __align__(16) __half d_K2f[C0N * C1N];        // fp16(K2)
__device__ __align__(16) float  d_H[NP * C0N];
__device__ __align__(16) __half d_Rs16[NP * C0N];        // fp16(4096*invdeg*BN1(H))
__device__ __align__(16) __half d_R2f[NP * C1N];         // fp16(Rs @ K2), 4096-scaled
__device__ __align__(16) float  d_O0[NP * C1N];
__device__ __align__(16) float  d_O1[NP * C1N];
__device__ __align__(16) float  d_O[NP * C1N];
__device__ float d_sum1[C0N], d_sq1[C0N], d_sc1[C0N], d_sh1[C0N];
__device__ float d_sum2[C1N], d_sq2[C1N], d_sc2[C1N], d_sh2[C1N];

// ---- prep: adj int32 -> fp16, FUSED column-degree (128x128 tiles) ----------
__global__ void __launch_bounds__(256) k_prep_adj(const int* __restrict__ adj) {
    __shared__ float dred[8][128];
    const int r0 = blockIdx.x * 128;
    const int k0 = blockIdx.y * 128;
    const int tid = threadIdx.x;
    const int c4 = (tid & 31) * 4;
    const int rb = tid >> 5;

    float dreg[4] = {0.f, 0.f, 0.f, 0.f};
#pragma unroll
    for (int s = 0; s < 16; s++) {
        int kl = rb + s * 8;
        int4 a = *(const int4*)(adj + (size_t)(k0 + kl) * NP + r0 + c4);
        __half o[4];
        o[0] = __float2half_rn((float)a.x);
        o[1] = __float2half_rn((float)a.y);
        o[2] = __float2half_rn((float)a.z);
        o[3] = __float2half_rn((float)a.w);
        *(uint2*)(d_Adjh + (size_t)(k0 + kl) * NP + r0 + c4) = *(uint2*)o;
        dreg[0] += (float)a.x;
        dreg[1] += (float)a.y;
        dreg[2] += (float)a.z;
        dreg[3] += (float)a.w;
    }
#pragma unroll
    for (int j = 0; j < 4; j++) dred[rb][c4 + j] = dreg[j];
    __syncthreads();
    if (tid < 128) {
        float s = 0.f;
#pragma unroll
        for (int g = 0; g < 8; g++) s += dred[g][tid];
        atomicAdd(&d_deg[r0 + tid], s);
    }
}

// ------------ prep: X -> fp16, fused accum zeroing ---------------------------
__global__ void __launch_bounds__(256) k_prep_x(const float* __restrict__ X) {
    if (blockIdx.x == 0) {
        int t = threadIdx.x;
        if (t < C0N) { d_sum1[t] = 0.f; d_sq1[t] = 0.f; }
        if (t < C1N) { d_sum2[t] = 0.f; d_sq2[t] = 0.f; }
    }
    if (threadIdx.x < 8) d_deg[blockIdx.x * 8 + threadIdx.x] = 0.f;
    size_t i = ((size_t)blockIdx.x * 256 + threadIdx.x) * 4;
    float4 x = *(const float4*)(X + i);
    __half h[4];
    h[0] = __float2half_rn(x.x);
    h[1] = __float2half_rn(x.y);
    h[2] = __float2half_rn(x.z);
    h[3] = __float2half_rn(x.w);
    *(uint2*)(d_Xf + i) = *(uint2*)h;
}

// ============================================================================
// GEMM1: Rpre_part = A^T @ X over one K half (single-pass fp16).
// grid (64, 2). CTA 128x128, BK=64. 8 warps 2M x 4N, warp 64x32.
// ============================================================================
#define G1_LDA 136
#define G1_LDX 136
#define G1_AS_BYTES (2 * 64 * G1_LDA * 2)
#define G1_SMEM     (G1_AS_BYTES + 2 * 64 * G1_LDX * 2) // 69632

__global__ void __launch_bounds__(256) k_gemm1() {
    extern __shared__ __align__(16) char smem_raw[];
    __half (*As)[64][G1_LDA] = (__half(*)[64][G1_LDA])smem_raw;
    __half (*Xs)[64][G1_LDX] = (__half(*)[64][G1_LDX])(smem_raw + G1_AS_BYTES);

    const int r0    = blockIdx.x * 128;
    const int kbase = blockIdx.y * KHALF;
    const int tid   = threadIdx.x;
    const int warp  = tid >> 5;
    const int wm    = warp & 1;
    const int wn    = warp >> 1;

    wmma::fragment<wmma::accumulator, 16, 16, 16, float> acc[4][2];
#pragma unroll
    for (int i = 0; i < 4; i++)
#pragma unroll
        for (int j = 0; j < 2; j++) wmma::fill_fragment(acc[i][j], 0.0f);

    {
#pragma unroll
        for (int s = 0; s < 4; s++) {
            int u = tid + s * 256, kk = u >> 4, rr = (u & 15) * 8;
            cp16(&As[0][kk][rr], d_Adjh + (size_t)(kbase + kk) * NP + r0 + rr);
            cp16(&Xs[0][kk][rr], d_Xf + (size_t)(kbase + kk) * FD + rr);
        }
        cp_commit();
    }

    const int T = KHALF / 64;
    for (int t = 0; t < T; t++) {
        const int buf = t & 1;
        if (t + 1 < T) {
            const int nb = buf ^ 1;
            const int k1 = kbase + (t + 1) * 64;
#pragma unroll
            for (int s = 0; s < 4; s++) {
                int u = tid + s * 256, kk = u >> 4, rr = (u & 15) * 8;
                cp16(&As[nb][kk][rr], d_Adjh + (size_t)(k1 + kk) * NP + r0 + rr);
                cp16(&Xs[nb][kk][rr], d_Xf + (size_t)(k1 + kk) * FD + rr);
            }
            cp_commit();
            cp_wait<1>();
        } else {
            cp_wait<0>();
        }
        __syncthreads();

#pragma unroll
        for (int ks = 0; ks < 4; ks++) {
            wmma::fragment<wmma::matrix_a, 16, 16, 16, __half, wmma::col_major> af[4];
#pragma unroll
            for (int i = 0; i < 4; i++)
                wmma::load_matrix_sync(af[i], &As[buf][ks * 16][wm * 64 + i * 16], G1_LDA);
            wmma::fragment<wmma::matrix_b, 16, 16, 16, __half, wmma::row_major> bf[2];
#pragma unroll
            for (int j = 0; j < 2; j++)
                wmma::load_matrix_sync(bf[j], &Xs[buf][ks * 16][wn * 32 + j * 16], G1_LDX);
#pragma unroll
            for (int j = 0; j < 2; j++)
#pragma unroll
                for (int i = 0; i < 4; i++) wmma::mma_sync(acc[i][j], af[i], bf[j], acc[i][j]);
        }
        __syncthreads();
    }

    float* dst = blockIdx.y ? d_Rpre1 : d_Rpre0;
#pragma unroll
    for (int i = 0; i < 4; i++)
#pragma unroll
        for (int j = 0; j < 2; j++)
            wmma::store_matrix_sync(&dst[(size_t)(r0 + wm * 64 + i * 16) * FD + wn * 32 + j * 16],
                                    acc[i][j], FD, wmma::mem_row_major);
}

// ============================================================================
// GEMM3: O_part = A @ R2f over one K half (single-pass fp16).
// ============================================================================
#define G3_LDA 72
#define G3_LDB 136
#define G3_AS_BYTES (2 * 128 * G3_LDA * 2)
#define G3_SMEM     (G3_AS_BYTES + 2 * 64 * G3_LDB * 2) // 71680

__global__ void __launch_bounds__(256) k_gemm3() {
    extern __shared__ __align__(16) char smem_raw[];
    __half (*As)[128][G3_LDA] = (__half(*)[128][G3_LDA])smem_raw;
    __half (*Bs)[64][G3_LDB]  = (__half(*)[64][G3_LDB])(smem_raw + G3_AS_BYTES);

    const int p0    = blockIdx.x * 128;
    const int kbase = blockIdx.y * KHALF;
    const int tid   = threadIdx.x;
    const int warp  = tid >> 5;
    const int wm    = warp & 1;
    const int wn    = warp >> 1;

    wmma::fragment<wmma::accumulator, 16, 16, 16, float> acc[4][2];
#pragma unroll
    for (int i = 0; i < 4; i++)
#pragma unroll
        for (int j = 0; j < 2; j++) wmma::fill_fragment(acc[i][j], 0.0f);

    {
#pragma unroll
        for (int s = 0; s < 4; s++) {
            int u = tid + s * 256;
            int pp = u >> 3, kc = (u & 7) * 8;
            cp16(&As[0][pp][kc], d_Adjh + (size_t)(p0 + pp) * NP + kbase + kc);
            int kk = u >> 4, cc = (u & 15) * 8;
            cp16(&Bs[0][kk][cc], d_R2f + (size_t)(kbase + kk) * C1N + cc);
        }
        cp_commit();
    }

    const int T = KHALF / 64;
    for (int t = 0; t < T; t++) {
        const int buf = t & 1;
        if (t + 1 < T) {
            const int nb = buf ^ 1;
            const int k1 = kbase + (t + 1) * 64;
#pragma unroll
            for (int s = 0; s < 4; s++) {
                int u = tid + s * 256;
                int pp = u >> 3, kc = (u & 7) * 8;
                cp16(&As[nb][pp][kc], d_Adjh + (size_t)(p0 + pp) * NP + k1 + kc);
                int kk = u >> 4, cc = (u & 15) * 8;
                cp16(&Bs[nb][kk][cc], d_R2f + (size_t)(k1 + kk) * C1N + cc);
            }
            cp_commit();
            cp_wait<1>();
        } else {
            cp_wait<0>();
        }
        __syncthreads();

#pragma unroll
        for (int ks = 0; ks < 4; ks++) {
            wmma::fragment<wmma::matrix_a, 16, 16, 16, __half, wmma::row_major> af[4];
#pragma unroll
            for (int i = 0; i < 4; i++)
                wmma::load_matrix_sync(af[i], &As[buf][wm * 64 + i * 16][ks * 16], G3_LDA);
            wmma::fragment<wmma::matrix_b, 16, 16, 16, __half, wmma::row_major> bf[2];
#pragma unroll
            for (int j = 0; j < 2; j++)
                wmma::load_matrix_sync(bf[j], &Bs[buf][ks * 16][wn * 32 + j * 16], G3_LDB);
#pragma unroll
            for (int j = 0; j < 2; j++)
#pragma unroll
                for (int i = 0; i < 4; i++) wmma::mma_sync(acc[i][j], af[i], bf[j], acc[i][j]);
        }
        __syncthreads();
    }

    float* dst = blockIdx.y ? d_O1 : d_O0;
#pragma unroll
    for (int i = 0; i < 4; i++)
#pragma unroll
        for (int j = 0; j < 2; j++)
            wmma::store_matrix_sync(&dst[(size_t)(p0 + wm * 64 + i * 16) * C1N + wn * 32 + j * 16],
                                    acc[i][j], C1N, wmma::mem_row_major);
}

// --------- prep: (Rpre0+Rpre1) -> hi/lo fp16; K1 -> hi/lo; K2 -> fp16 --------
// grid 1024 (Rpre). Blocks 0..31 also convert K1; 32..63 also K2 (1024 elems ea).
__global__ void __launch_bounds__(256) k_prep_rpre(const float* __restrict__ K1,
                                                   const float* __restrict__ K2) {
    const int tid = threadIdx.x;
    if (blockIdx.x < 32) {
        size_t i = ((size_t)blockIdx.x * 256 + tid) * 4;   // K1: 32768 elems
        float4 v = *(const float4*)(K1 + i);
        __half h[4], l[4];
        float vv[4] = {v.x, v.y, v.z, v.w};
#pragma unroll
        for (int j = 0; j < 4; j++) {
            h[j] = __float2half_rn(vv[j]);
            l[j] = __float2half_rn(vv[j] - __half2float(h[j]));
        }
        *(uint2*)(d_K1h + i) = *(uint2*)h;
        *(uint2*)(d_K1l + i) = *(uint2*)l;
    } else if (blockIdx.x < 64) {
        size_t i = ((size_t)(blockIdx.x - 32) * 256 + tid) * 4;   // K2: 32768 elems
        float4 v = *(const float4*)(K2 + i);
        __half h[4];
        h[0] = __float2half_rn(v.x);
        h[1] = __float2half_rn(v.y);
        h[2] = __float2half_rn(v.z);
        h[3] = __float2half_rn(v.w);
        *(uint2*)(d_K2f + i) = *(uint2*)h;
    }
    size_t i = ((size_t)blockIdx.x * 256 + tid) * 4;              // Rpre: NP*FD
    float4 a = *(const float4*)(d_Rpre0 + i);
    float4 b = *(const float4*)(d_Rpre1 + i);
    float vv[4] = {a.x + b.x, a.y + b.y, a.z + b.z, a.w + b.w};
    __half h[4], l[4];
#pragma unroll
    for (int j = 0; j < 4; j++) {
        h[j] = __float2half_rn(vv[j]);
        l[j] = __float2half_rn(vv[j] - __half2float(h[j]));
    }
    *(uint2*)(d_RpH + i) = *(uint2*)h;
    *(uint2*)(d_RpL + i) = *(uint2*)l;
}

// ============================================================================
// small_h (tensor, 3-term hi/lo): H = invdeg*(Rp@K1)+b1, fused BN1 stats.
// grid (128, 2): M-tile 64, N-tile 128, K=128 single shot.
// ============================================================================
#define SH_LDA 136
#define SH_LDB 136
#define SH_A_BYTES (64 * SH_LDA * 2)    // 17408
#define SH_B_BYTES (128 * SH_LDB * 2)   // 34816
#define SH_SMEM    (2 * SH_A_BYTES + 2 * SH_B_BYTES)   // 104448
#define SH_LDC 132

__global__ void __launch_bounds__(256) k_small_h_tc(const float* __restrict__ bias) {
    extern __shared__ __align__(16) char sm[];
    __half (*Ah)[SH_LDA] = (__half(*)[SH_LDA])sm;
    __half (*Al)[SH_LDA] = (__half(*)[SH_LDA])(sm + SH_A_BYTES);
    __half (*Bh)[SH_LDB] = (__half(*)[SH_LDB])(sm + 2 * SH_A_BYTES);
    __half (*Bl)[SH_LDB] = (__half(*)[SH_LDB])(sm + 2 * SH_A_BYTES + SH_B_BYTES);
    float  (*Ct)[SH_LDC] = (float(*)[SH_LDC])sm;   // epilogue reuse (33792 B)

    const int m0  = blockIdx.x * 64;
    const int n0  = blockIdx.y * 128;
    const int tid = threadIdx.x;
    const int warp = tid >> 5;
    const int wm   = warp & 1;
    const int wn   = warp >> 1;

    // A: 64 rows x 16 cp16 -> 4/thread per matrix
#pragma unroll
    for (int s = 0; s < 4; s++) {
        int u = tid + s * 256, row = u >> 4, col = (u & 15) * 8;
        cp16(&Ah[row][col], d_RpH + (size_t)(m0 + row) * FD + col);
        cp16(&Al[row][col], d_RpL + (size_t)(m0 + row) * FD + col);
    }
    // B: 128 rows x 16 cp16 -> 8/thread per matrix
#pragma unroll
    for (int s = 0; s < 8; s++) {
        int u = tid + s * 256, kk = u >> 4, cc = (u & 15) * 8;
        cp16(&Bh[kk][cc], d_K1h + (size_t)kk * C0N + n0 + cc);
        cp16(&Bl[kk][cc], d_K1l + (size_t)kk * C0N + n0 + cc);
    }
    cp_commit();
    cp_wait<0>();
    __syncthreads();

    wmma::fragment<wmma::accumulator, 16, 16, 16, float> acc[2][2];
#pragma unroll
    for (int i = 0; i < 2; i++)
#pragma unroll
        for (int j = 0; j < 2; j++) wmma::fill_fragment(acc[i][j], 0.0f);

#pragma unroll
    for (int ks = 0; ks < 8; ks++) {
        wmma::fragment<wmma::matrix_a, 16, 16, 16, __half, wmma::row_major> afh[2], afl[2];
#pragma unroll
        for (int i = 0; i < 2; i++) {
            wmma::load_matrix_sync(afh[i], &Ah[wm * 32 + i * 16][ks * 16], SH_LDA);
            wmma::load_matrix_sync(afl[i], &Al[wm * 32 + i * 16][ks * 16], SH_LDA);
        }
        wmma::fragment<wmma::matrix_b, 16, 16, 16, __half, wmma::row_major> bfh[2], bfl[2];
#pragma unroll
        for (int j = 0; j < 2; j++) {
            wmma::load_matrix_sync(bfh[j], &Bh[ks * 16][wn * 32 + j * 16], SH_LDB);
            wmma::load_matrix_sync(bfl[j], &Bl[ks * 16][wn * 32 + j * 16], SH_LDB);
        }
#pragma unroll
        for (int j = 0; j < 2; j++)
#pragma unroll
            for (int i = 0; i < 2; i++) {
                wmma::mma_sync(acc[i][j], afh[i], bfh[j], acc[i][j]);
                wmma::mma_sync(acc[i][j], afh[i], bfl[j], acc[i][j]);
                wmma::mma_sync(acc[i][j], afl[i], bfh[j], acc[i][j]);
            }
    }
    __syncthreads();   // done reading Ah/Al/Bh before Ct overwrite

#pragma unroll
    for (int i = 0; i < 2; i++)
#pragma unroll
        for (int j = 0; j < 2; j++)
            wmma::store_matrix_sync(&Ct[wm * 32 + i * 16][wn * 32 + j * 16],
                                    acc[i][j], SH_LDC, wmma::mem_row_major);
    __syncthreads();

    {
        const int c    = tid & 127;
        const int half = tid >> 7;        // 32 rows each
        const float b  = bias[n0 + c];
        float s = 0.f, q = 0.f;
#pragma unroll 8
        for (int r = half * 32; r < half * 32 + 32; r++) {
            int gr = m0 + r;
            float dg = d_deg[gr];
            float idg = (dg > 0.5f) ? (1.0f / dg) : 0.0f;
            float v = Ct[r][c] * idg + b;
            d_H[(size_t)gr * C0N + n0 + c] = v;
            s += v;
            q = fmaf(v, v, q);
        }
        atomicAdd(&d_sum1[n0 + c], s);
        atomicAdd(&d_sq1[n0 + c], q);
    }
}

// ------------- prep: H -> Rs16 = fp16(4096*invdeg*BN1(H)) --------------------
__global__ void __launch_bounds__(256) k_prep_rs() {
    size_t i = ((size_t)blockIdx.x * 256 + threadIdx.x) * 4;   // NP*C0N
    int c = (int)(i & (C0N - 1));
    int r = (int)(i >> 8);
    float4 h4 = *(const float4*)(d_H + i);
    float4 sc = *(const float4*)(d_sc1 + c);
    float4 sh = *(const float4*)(d_sh1 + c);
    float dg = d_deg[r];
    float idg = (dg > 0.5f) ? (4096.0f / dg) : 0.0f;
    __half o[4];
    o[0] = __float2half_rn(idg * fmaf(h4.x, sc.x, sh.x));
    o[1] = __float2half_rn(idg * fmaf(h4.y, sc.y, sh.y));
    o[2] = __float2half_rn(idg * fmaf(h4.z, sc.z, sh.z));
    o[3] = __float2half_rn(idg * fmaf(h4.w, sc.w, sh.w));
    *(uint2*)(d_Rs16 + i) = *(uint2*)o;
}

// ============================================================================
// small_r2 (tensor, single fp16): R2f = Rs16 @ K2f.  grid 128: M-tile 64,
// N=128 full, K=256 single shot.
// ============================================================================
#define SR_LDA 264
#define SR_LDB 136
#define SR_A_BYTES (64 * SR_LDA * 2)    // 33792
#define SR_B_BYTES (256 * SR_LDB * 2)   // 69632
#define SR_SMEM    (SR_A_BYTES + SR_B_BYTES)   // 103424
#define SR_LDC 132

__global__ void __launch_bounds__(256) k_small_r2_tc() {
    extern __shared__ __align__(16) char sm[];
    __half (*As)[SR_LDA] = (__half(*)[SR_LDA])sm;
    __half (*Bs)[SR_LDB] = (__half(*)[SR_LDB])(sm + SR_A_BYTES);
    float  (*Ct)[SR_LDC] = (float(*)[SR_LDC])sm;   // 33792 B, aliases As

    const int m0  = blockIdx.x * 64;
    const int tid = threadIdx.x;
    const int warp = tid >> 5;
    const int wm   = warp & 1;
    const int wn   = warp >> 1;

    // A: 64 rows x 32 cp16 -> 8/thread
#pragma unroll
    for (int s = 0; s < 8; s++) {
        int u = tid + s * 256, row = u >> 5, col = (u & 31) * 8;
        cp16(&As[row][col], d_Rs16 + (size_t)(m0 + row) * C0N + col);
    }
    // B: 256 rows x 16 cp16 -> 16/thread
#pragma unroll
    for (int s = 0; s < 16; s++) {
        int u = tid + s * 256, kk = u >> 4, cc = (u & 15) * 8;
        cp16(&Bs[kk][cc], d_K2f + (size_t)kk * C1N + cc);
    }
    cp_commit();
    cp_wait<0>();
    __syncthreads();

    wmma::fragment<wmma::accumulator, 16, 16, 16, float> acc[2][2];
#pragma unroll
    for (int i = 0; i < 2; i++)
#pragma unroll
        for (int j = 0; j < 2; j++) wmma::fill_fragment(acc[i][j], 0.0f);

#pragma unroll
    for (int ks = 0; ks < 16; ks++) {
        wmma::fragment<wmma::matrix_a, 16, 16, 16, __half, wmma::row_major> af[2];
#pragma unroll
        for (int i = 0; i < 2; i++)
            wmma::load_matrix_sync(af[i], &As[wm * 32 + i * 16][ks * 16], SR_LDA);
        wmma::fragment<wmma::matrix_b, 16, 16, 16, __half, wmma::row_major> bf[2];
#pragma unroll
        for (int j = 0; j < 2; j++)
            wmma::load_matrix_sync(bf[j], &Bs[ks * 16][wn * 32 + j * 16], SR_LDB);
#pragma unroll
        for (int j = 0; j < 2; j++)
#pragma unroll
            for (int i = 0; i < 2; i++) wmma::mma_sync(acc[i][j], af[i], bf[j], acc[i][j]);
    }
    __syncthreads();

#pragma unroll
    for (int i = 0; i < 2; i++)
#pragma unroll
        for (int j = 0; j < 2; j++)
            wmma::store_matrix_sync(&Ct[wm * 32 + i * 16][wn * 32 + j * 16],
                                    acc[i][j], SR_LDC, wmma::mem_row_major);
    __syncthreads();

    {
        const int c    = tid & 127;
        const int half = tid >> 7;
#pragma unroll 8
        for (int r = half * 32; r < half * 32 + 32; r++)
            d_R2f[(size_t)(m0 + r) * C1N + c] = __float2half_rn(Ct[r][c]);
    }
}

// ------------- combine O partials (undo 4096 scale) + bias, BN2 stats --------
__global__ void __launch_bounds__(128) k_stats2(const float* __restrict__ bias2) {
    const int c  = threadIdx.x;
    const int r0 = blockIdx.x * 64;
    const float b = bias2[c];
    const float inv = 1.0f / 4096.0f;
    float s = 0.f, q = 0.f;
#pragma unroll 4
    for (int r = r0; r < r0 + 64; r++) {
        size_t idx = (size_t)r * C1N + c;
        float v = (d_O0[idx] + d_O1[idx]) * inv + b;
        d_O[idx] = v;
        s += v;
        q = fmaf(v, v, q);
    }
    atomicAdd(&d_sum2[c], s);
    atomicAdd(&d_sq2[c], q);
}

// ---------------- BN finalize + output --------------------------------------
__global__ void k_fin1(const float* __restrict__ gamma, const float* __restrict__ beta) {
    int c = threadIdx.x;  // 256
    float mean = d_sum1[c] * (1.0f / NP);
    float var  = d_sq1[c] * (1.0f / NP) - mean * mean;
    float sc   = gamma[c] * rsqrtf(var + BN_EPS);
    d_sc1[c] = sc;
    d_sh1[c] = beta[c] - mean * sc;
}

__global__ void k_fin2(const float* __restrict__ gamma, const float* __restrict__ beta) {
    int c = threadIdx.x;  // 128
    float mean = d_sum2[c] * (1.0f / NP);
    float var  = d_sq2[c] * (1.0f / NP) - mean * mean;
    float sc   = gamma[c] * rsqrtf(var + BN_EPS);
    d_sc2[c] = sc;
    d_sh2[c] = beta[c] - mean * sc;
}

__global__ void k_out(float* __restrict__ out) {
    int idx = blockIdx.x * 256 + threadIdx.x;
    int c = idx & (C1N - 1);
    out[idx] = fmaf(d_O[idx], d_sc2[c], d_sh2[c]);
}

// ---------------- launch ----------------------------------------------------
extern "C" void kernel_launch(void* const* d_in, const int* in_sizes, int n_in,
                              void* d_out, int out_size) {
    const float* features = (const float*)d_in[0];
    const int*   adj      = (const int*)d_in[1];
    const float* kernel_1 = (const float*)d_in[2];
    const float* bias_1   = (const float*)d_in[3];
    const float* gamma_1  = (const float*)d_in[4];
    const float* beta_1   = (const float*)d_in[5];
    const float* kernel_2 = (const float*)d_in[6];
    const float* bias_2   = (const float*)d_in[7];
    const float* gamma_2  = (const float*)d_in[8];
    const float* beta_2   = (const float*)d_in[9];
    float* out = (float*)d_out;

    cudaFuncSetAttribute(k_gemm1, cudaFuncAttributeMaxDynamicSharedMemorySize, G1_SMEM);
    cudaFuncSetAttribute(k_gemm3, cudaFuncAttributeMaxDynamicSharedMemorySize, G3_SMEM);
    cudaFuncSetAttribute(k_small_h_tc, cudaFuncAttributeMaxDynamicSharedMemorySize, SH_SMEM);
    cudaFuncSetAttribute(k_small_r2_tc, cudaFuncAttributeMaxDynamicSharedMemorySize, SR_SMEM);

    k_prep_x<<<NP * FD / (256 * 4), 256>>>(features);                   // X fp16 + zero
    k_prep_adj<<<dim3(NP / 128, NP / 128), 256>>>(adj);                 // adj fp16 + degree
    k_gemm1<<<dim3(NP / 128, KSPLIT), 256, G1_SMEM>>>();                // Rpre partials
    k_prep_rpre<<<NP * FD / (256 * 4), 256>>>(kernel_1, kernel_2);      // Rp hi/lo + K1/K2
    k_small_h_tc<<<dim3(NP / 64, C0N / 128), 256, SH_SMEM>>>(bias_1);   // H + stats1
    k_fin1<<<1, C0N>>>(gamma_1, beta_1);
    k_prep_rs<<<NP * C0N / (256 * 4), 256>>>();                         // Rs16
    k_small_r2_tc<<<NP / 64, 256, SR_SMEM>>>();                         // R2f
    k_gemm3<<<dim3(NP / 128, KSPLIT), 256, G3_SMEM>>>();                // O partials
    k_stats2<<<NP / 64, 128>>>(bias_2);                                 // combine + stats2
    k_fin2<<<1, C1N>>>(gamma_2, beta_2);
    k_out<<<NP * C1N / 256, 256>>>(out);
}

// round 15
// speedup vs baseline: 9.2814x; 1.0326x over previous
#include <cuda_runtime.h>
#include <cuda_bf16.h>
#include <cuda_fp16.h>
#include <mma.h>
#include <cstdint>

using namespace nvcuda;

#define NP   8192
#define FD   128
#define C0N  256
#define C1N  128
#define BN_EPS 1e-3f
#define KSPLIT 4
#define KQ (NP / KSPLIT)   // 2048

// ---------------- cp.async helpers ------------------------------------------
__device__ __forceinline__ void cp16(void* dst_smem, const void* src) {
    unsigned int d = (unsigned int)__cvta_generic_to_shared(dst_smem);
    asm volatile("cp.async.cg.shared.global [%0], [%1], 16;\n" :: "r"(d), "l"(src));
}
__device__ __forceinline__ void cp_commit() { asm volatile("cp.async.commit_group;\n"); }
template <int N> __device__ __forceinline__ void cp_wait() {
    asm volatile("cp.async.wait_group %0;\n" :: "n"(N));
}

// ---------------- scratch (device globals; no allocation allowed) -----------
__device__ __align__(16) __half d_Adjh[(size_t)NP * NP]; // fp16 adj (exact 0/1)
__device__ __align__(16) __half d_Xf[NP * FD];           // fp16(X)
__device__ __align__(16) float  d_deg[NP];
__device__ __align__(16) float  d_Rp[KSPLIT][NP * FD];   // Rpre partials
__device__ __align__(16) __half d_RpH[NP * FD];          // hi(sum Rp)
__device__ __align__(16) __half d_RpL[NP * FD];          // lo(...)
__device__ __align__(16) __half d_K1h[FD * C0N];
__device__ __align__(16) __half d_K1l[FD * C0N];
__device__ __align__(16) __half d_K2f[C0N * C1N];
__device__ __align__(16) float  d_H[NP * C0N];
__device__ __align__(16) __half d_Rs16[NP * C0N];        // fp16(4096*invdeg*BN1(H))
__device__ __align__(16) __half d_R2f[NP * C1N];         // fp16(Rs@K2), 4096-scaled
__device__ __align__(16) float  d_Op[KSPLIT][NP * C1N];  // O partials
__device__ __align__(16) float  d_O[NP * C1N];
__device__ float d_sum1[C0N], d_sq1[C0N];
__device__ float d_sum2[C1N], d_sq2[C1N];

// ---- prep: adj int32 -> fp16, FUSED column-degree (128x128 tiles) ----------
__global__ void __launch_bounds__(256) k_prep_adj(const int* __restrict__ adj) {
    __shared__ float dred[8][128];
    const int r0 = blockIdx.x * 128;
    const int k0 = blockIdx.y * 128;
    const int tid = threadIdx.x;
    const int c4 = (tid & 31) * 4;
    const int rb = tid >> 5;

    float dreg[4] = {0.f, 0.f, 0.f, 0.f};
#pragma unroll
    for (int s = 0; s < 16; s++) {
        int kl = rb + s * 8;
        int4 a = *(const int4*)(adj + (size_t)(k0 + kl) * NP + r0 + c4);
        __half o[4];
        o[0] = __float2half_rn((float)a.x);
        o[1] = __float2half_rn((float)a.y);
        o[2] = __float2half_rn((float)a.z);
        o[3] = __float2half_rn((float)a.w);
        *(uint2*)(d_Adjh + (size_t)(k0 + kl) * NP + r0 + c4) = *(uint2*)o;
        dreg[0] += (float)a.x;
        dreg[1] += (float)a.y;
        dreg[2] += (float)a.z;
        dreg[3] += (float)a.w;
    }
#pragma unroll
    for (int j = 0; j < 4; j++) dred[rb][c4 + j] = dreg[j];
    __syncthreads();
    if (tid < 128) {
        float s = 0.f;
#pragma unroll
        for (int g = 0; g < 8; g++) s += dred[g][tid];
        atomicAdd(&d_deg[r0 + tid], s);
    }
}

// ------------ prep: X -> fp16, fused accum zeroing ---------------------------
__global__ void __launch_bounds__(256) k_prep_x(const float* __restrict__ X) {
    if (blockIdx.x == 0) {
        int t = threadIdx.x;
        if (t < C0N) { d_sum1[t] = 0.f; d_sq1[t] = 0.f; }
        if (t < C1N) { d_sum2[t] = 0.f; d_sq2[t] = 0.f; }
    }
    if (threadIdx.x < 8) d_deg[blockIdx.x * 8 + threadIdx.x] = 0.f;
    size_t i = ((size_t)blockIdx.x * 256 + threadIdx.x) * 4;
    float4 x = *(const float4*)(X + i);
    __half h[4];
    h[0] = __float2half_rn(x.x);
    h[1] = __float2half_rn(x.y);
    h[2] = __float2half_rn(x.z);
    h[3] = __float2half_rn(x.w);
    *(uint2*)(d_Xf + i) = *(uint2*)h;
}

// ============================================================================
// GEMM1: Rp[q] = A^T @ X over K quarter q.  grid (32, 4).
// CTA M=256 (r) x N=128, BK=64. 8 warps 4M x 2N, warp 64x64 (0.5 frag/MMA).
// A^T[r,k] = Adjh[k*NP + r]: smem As[k][r], col_major frags.
// ============================================================================
#define G1_LDA 264
#define G1_LDX 136
#define G1_AS_BYTES (2 * 64 * G1_LDA * 2)              // 67584
#define G1_SMEM     (G1_AS_BYTES + 2 * 64 * G1_LDX * 2) // 102400

__global__ void __launch_bounds__(256) k_gemm1() {
    extern __shared__ __align__(16) char smem_raw[];
    __half (*As)[64][G1_LDA] = (__half(*)[64][G1_LDA])smem_raw;
    __half (*Xs)[64][G1_LDX] = (__half(*)[64][G1_LDX])(smem_raw + G1_AS_BYTES);

    const int r0    = blockIdx.x * 256;
    const int kbase = blockIdx.y * KQ;
    const int tid   = threadIdx.x;
    const int warp  = tid >> 5;
    const int wm    = warp & 3;     // 4 M-groups of 64
    const int wn    = warp >> 2;    // 2 N-groups of 64

    wmma::fragment<wmma::accumulator, 16, 16, 16, float> acc[4][4];
#pragma unroll
    for (int i = 0; i < 4; i++)
#pragma unroll
        for (int j = 0; j < 4; j++) wmma::fill_fragment(acc[i][j], 0.0f);

    // A: 64 k-rows x 256 r = 2048 cp16 -> 8/thread. X: 1024 cp16 -> 4/thread.
    {
#pragma unroll
        for (int s = 0; s < 8; s++) {
            int u = tid + s * 256, kk = u >> 5, rr = (u & 31) * 8;
            cp16(&As[0][kk][rr], d_Adjh + (size_t)(kbase + kk) * NP + r0 + rr);
        }
#pragma unroll
        for (int s = 0; s < 4; s++) {
            int u = tid + s * 256, kk = u >> 4, cc = (u & 15) * 8;
            cp16(&Xs[0][kk][cc], d_Xf + (size_t)(kbase + kk) * FD + cc);
        }
        cp_commit();
    }

    const int T = KQ / 64;   // 32
    for (int t = 0; t < T; t++) {
        const int buf = t & 1;
        if (t + 1 < T) {
            const int nb = buf ^ 1;
            const int k1 = kbase + (t + 1) * 64;
#pragma unroll
            for (int s = 0; s < 8; s++) {
                int u = tid + s * 256, kk = u >> 5, rr = (u & 31) * 8;
                cp16(&As[nb][kk][rr], d_Adjh + (size_t)(k1 + kk) * NP + r0 + rr);
            }
#pragma unroll
            for (int s = 0; s < 4; s++) {
                int u = tid + s * 256, kk = u >> 4, cc = (u & 15) * 8;
                cp16(&Xs[nb][kk][cc], d_Xf + (size_t)(k1 + kk) * FD + cc);
            }
            cp_commit();
            cp_wait<1>();
        } else {
            cp_wait<0>();
        }
        __syncthreads();

#pragma unroll
        for (int ks = 0; ks < 4; ks++) {
            wmma::fragment<wmma::matrix_a, 16, 16, 16, __half, wmma::col_major> af[4];
#pragma unroll
            for (int i = 0; i < 4; i++)
                wmma::load_matrix_sync(af[i], &As[buf][ks * 16][wm * 64 + i * 16], G1_LDA);
#pragma unroll
            for (int j = 0; j < 4; j++) {
                wmma::fragment<wmma::matrix_b, 16, 16, 16, __half, wmma::row_major> bf;
                wmma::load_matrix_sync(bf, &Xs[buf][ks * 16][wn * 64 + j * 16], G1_LDX);
#pragma unroll
                for (int i = 0; i < 4; i++) wmma::mma_sync(acc[i][j], af[i], bf, acc[i][j]);
            }
        }
        __syncthreads();
    }

    float* dst = d_Rp[blockIdx.y];
#pragma unroll
    for (int i = 0; i < 4; i++)
#pragma unroll
        for (int j = 0; j < 4; j++)
            wmma::store_matrix_sync(&dst[(size_t)(r0 + wm * 64 + i * 16) * FD + wn * 64 + j * 16],
                                    acc[i][j], FD, wmma::mem_row_major);
}

// ============================================================================
// GEMM3: Op[q] = A @ R2f over K quarter q.  grid (32, 4).
// CTA 256x128, BK=64. 8 warps 4M x 2N, warp 64x64. A row-major.
// ============================================================================
#define G3_LDA 72
#define G3_LDB 136
#define G3_AS_BYTES (2 * 256 * G3_LDA * 2)             // 73728
#define G3_SMEM     (G3_AS_BYTES + 2 * 64 * G3_LDB * 2) // 108544

__global__ void __launch_bounds__(256) k_gemm3() {
    extern __shared__ __align__(16) char smem_raw[];
    __half (*As)[256][G3_LDA] = (__half(*)[256][G3_LDA])smem_raw;
    __half (*Bs)[64][G3_LDB]  = (__half(*)[64][G3_LDB])(smem_raw + G3_AS_BYTES);

    const int p0    = blockIdx.x * 256;
    const int kbase = blockIdx.y * KQ;
    const int tid   = threadIdx.x;
    const int warp  = tid >> 5;
    const int wm    = warp & 3;
    const int wn    = warp >> 2;

    wmma::fragment<wmma::accumulator, 16, 16, 16, float> acc[4][4];
#pragma unroll
    for (int i = 0; i < 4; i++)
#pragma unroll
        for (int j = 0; j < 4; j++) wmma::fill_fragment(acc[i][j], 0.0f);

    {
#pragma unroll
        for (int s = 0; s < 8; s++) {
            int u = tid + s * 256, pp = u >> 3, kc = (u & 7) * 8;
            cp16(&As[0][pp][kc], d_Adjh + (size_t)(p0 + pp) * NP + kbase + kc);
        }
#pragma unroll
        for (int s = 0; s < 4; s++) {
            int u = tid + s * 256, kk = u >> 4, cc = (u & 15) * 8;
            cp16(&Bs[0][kk][cc], d_R2f + (size_t)(kbase + kk) * C1N + cc);
        }
        cp_commit();
    }

    const int T = KQ / 64;
    for (int t = 0; t < T; t++) {
        const int buf = t & 1;
        if (t + 1 < T) {
            const int nb = buf ^ 1;
            const int k1 = kbase + (t + 1) * 64;
#pragma unroll
            for (int s = 0; s < 8; s++) {
                int u = tid + s * 256, pp = u >> 3, kc = (u & 7) * 8;
                cp16(&As[nb][pp][kc], d_Adjh + (size_t)(p0 + pp) * NP + k1 + kc);
            }
#pragma unroll
            for (int s = 0; s < 4; s++) {
                int u = tid + s * 256, kk = u >> 4, cc = (u & 15) * 8;
                cp16(&Bs[nb][kk][cc], d_R2f + (size_t)(k1 + kk) * C1N + cc);
            }
            cp_commit();
            cp_wait<1>();
        } else {
            cp_wait<0>();
        }
        __syncthreads();

#pragma unroll
        for (int ks = 0; ks < 4; ks++) {
            wmma::fragment<wmma::matrix_a, 16, 16, 16, __half, wmma::row_major> af[4];
#pragma unroll
            for (int i = 0; i < 4; i++)
                wmma::load_matrix_sync(af[i], &As[buf][wm * 64 + i * 16][ks * 16], G3_LDA);
#pragma unroll
            for (int j = 0; j < 4; j++) {
                wmma::fragment<wmma::matrix_b, 16, 16, 16, __half, wmma::row_major> bf;
                wmma::load_matrix_sync(bf, &Bs[buf][ks * 16][wn * 64 + j * 16], G3_LDB);
#pragma unroll
                for (int i = 0; i < 4; i++) wmma::mma_sync(acc[i][j], af[i], bf, acc[i][j]);
            }
        }
        __syncthreads();
    }

    float* dst = d_Op[blockIdx.y];
#pragma unroll
    for (int i = 0; i < 4; i++)
#pragma unroll
        for (int j = 0; j < 4; j++)
            wmma::store_matrix_sync(&dst[(size_t)(p0 + wm * 64 + i * 16) * C1N + wn * 64 + j * 16],
                                    acc[i][j], C1N, wmma::mem_row_major);
}

// --------- prep: sum(Rp) -> hi/lo fp16; K1 -> hi/lo; K2 -> fp16 --------------
__global__ void __launch_bounds__(256) k_prep_rpre(const float* __restrict__ K1,
                                                   const float* __restrict__ K2) {
    const int tid = threadIdx.x;
    if (blockIdx.x < 32) {
        size_t i = ((size_t)blockIdx.x * 256 + tid) * 4;
        float4 v = *(const float4*)(K1 + i);
        __half h[4], l[4];
        float vv[4] = {v.x, v.y, v.z, v.w};
#pragma unroll
        for (int j = 0; j < 4; j++) {
            h[j] = __float2half_rn(vv[j]);
            l[j] = __float2half_rn(vv[j] - __half2float(h[j]));
        }
        *(uint2*)(d_K1h + i) = *(uint2*)h;
        *(uint2*)(d_K1l + i) = *(uint2*)l;
    } else if (blockIdx.x < 64) {
        size_t i = ((size_t)(blockIdx.x - 32) * 256 + tid) * 4;
        float4 v = *(const float4*)(K2 + i);
        __half h[4];
        h[0] = __float2half_rn(v.x);
        h[1] = __float2half_rn(v.y);
        h[2] = __float2half_rn(v.z);
        h[3] = __float2half_rn(v.w);
        *(uint2*)(d_K2f + i) = *(uint2*)h;
    }
    size_t i = ((size_t)blockIdx.x * 256 + tid) * 4;
    float4 a = *(const float4*)(d_Rp[0] + i);
    float4 b = *(const float4*)(d_Rp[1] + i);
    float4 c = *(const float4*)(d_Rp[2] + i);
    float4 d = *(const float4*)(d_Rp[3] + i);
    float vv[4] = {a.x + b.x + c.x + d.x, a.y + b.y + c.y + d.y,
                   a.z + b.z + c.z + d.z, a.w + b.w + c.w + d.w};
    __half h[4], l[4];
#pragma unroll
    for (int j = 0; j < 4; j++) {
        h[j] = __float2half_rn(vv[j]);
        l[j] = __float2half_rn(vv[j] - __half2float(h[j]));
    }
    *(uint2*)(d_RpH + i) = *(uint2*)h;
    *(uint2*)(d_RpL + i) = *(uint2*)l;
}

// ============================================================================
// small_h (tensor, 3-term hi/lo): H = invdeg*(Rp@K1)+b1, fused BN1 stats.
// grid (128, 2): M-tile 64, N-tile 128, K=128 single shot.
// ============================================================================
#define SH_LDA 136
#define SH_LDB 136
#define SH_A_BYTES (64 * SH_LDA * 2)
#define SH_B_BYTES (128 * SH_LDB * 2)
#define SH_SMEM    (2 * SH_A_BYTES + 2 * SH_B_BYTES)   // 104448
#define SH_LDC 132

__global__ void __launch_bounds__(256) k_small_h_tc(const float* __restrict__ bias) {
    extern __shared__ __align__(16) char sm[];
    __half (*Ah)[SH_LDA] = (__half(*)[SH_LDA])sm;
    __half (*Al)[SH_LDA] = (__half(*)[SH_LDA])(sm + SH_A_BYTES);
    __half (*Bh)[SH_LDB] = (__half(*)[SH_LDB])(sm + 2 * SH_A_BYTES);
    __half (*Bl)[SH_LDB] = (__half(*)[SH_LDB])(sm + 2 * SH_A_BYTES + SH_B_BYTES);
    float  (*Ct)[SH_LDC] = (float(*)[SH_LDC])sm;

    const int m0  = blockIdx.x * 64;
    const int n0  = blockIdx.y * 128;
    const int tid = threadIdx.x;
    const int warp = tid >> 5;
    const int wm   = warp & 1;
    const int wn   = warp >> 1;

#pragma unroll
    for (int s = 0; s < 4; s++) {
        int u = tid + s * 256, row = u >> 4, col = (u & 15) * 8;
        cp16(&Ah[row][col], d_RpH + (size_t)(m0 + row) * FD + col);
        cp16(&Al[row][col], d_RpL + (size_t)(m0 + row) * FD + col);
    }
#pragma unroll
    for (int s = 0; s < 8; s++) {
        int u = tid + s * 256, kk = u >> 4, cc = (u & 15) * 8;
        cp16(&Bh[kk][cc], d_K1h + (size_t)kk * C0N + n0 + cc);
        cp16(&Bl[kk][cc], d_K1l + (size_t)kk * C0N + n0 + cc);
    }
    cp_commit();
    cp_wait<0>();
    __syncthreads();

    wmma::fragment<wmma::accumulator, 16, 16, 16, float> acc[2][2];
#pragma unroll
    for (int i = 0; i < 2; i++)
#pragma unroll
        for (int j = 0; j < 2; j++) wmma::fill_fragment(acc[i][j], 0.0f);

#pragma unroll
    for (int ks = 0; ks < 8; ks++) {
        wmma::fragment<wmma::matrix_a, 16, 16, 16, __half, wmma::row_major> afh[2], afl[2];
#pragma unroll
        for (int i = 0; i < 2; i++) {
            wmma::load_matrix_sync(afh[i], &Ah[wm * 32 + i * 16][ks * 16], SH_LDA);
            wmma::load_matrix_sync(afl[i], &Al[wm * 32 + i * 16][ks * 16], SH_LDA);
        }
        wmma::fragment<wmma::matrix_b, 16, 16, 16, __half, wmma::row_major> bfh[2], bfl[2];
#pragma unroll
        for (int j = 0; j < 2; j++) {
            wmma::load_matrix_sync(bfh[j], &Bh[ks * 16][wn * 32 + j * 16], SH_LDB);
            wmma::load_matrix_sync(bfl[j], &Bl[ks * 16][wn * 32 + j * 16], SH_LDB);
        }
#pragma unroll
        for (int j = 0; j < 2; j++)
#pragma unroll
            for (int i = 0; i < 2; i++) {
                wmma::mma_sync(acc[i][j], afh[i], bfh[j], acc[i][j]);
                wmma::mma_sync(acc[i][j], afh[i], bfl[j], acc[i][j]);
                wmma::mma_sync(acc[i][j], afl[i], bfh[j], acc[i][j]);
            }
    }
    __syncthreads();

#pragma unroll
    for (int i = 0; i < 2; i++)
#pragma unroll
        for (int j = 0; j < 2; j++)
            wmma::store_matrix_sync(&Ct[wm * 32 + i * 16][wn * 32 + j * 16],
                                    acc[i][j], SH_LDC, wmma::mem_row_major);
    __syncthreads();

    {
        const int c    = tid & 127;
        const int half = tid >> 7;
        const float b  = bias[n0 + c];
        float s = 0.f, q = 0.f;
#pragma unroll 8
        for (int r = half * 32; r < half * 32 + 32; r++) {
            int gr = m0 + r;
            float dg = d_deg[gr];
            float idg = (dg > 0.5f) ? (1.0f / dg) : 0.0f;
            float v = Ct[r][c] * idg + b;
            d_H[(size_t)gr * C0N + n0 + c] = v;
            s += v;
            q = fmaf(v, v, q);
        }
        atomicAdd(&d_sum1[n0 + c], s);
        atomicAdd(&d_sq1[n0 + c], q);
    }
}

// ----- prep: H -> Rs16 = fp16(4096*invdeg*BN1(H)); fin1 inlined per block ----
__global__ void __launch_bounds__(256) k_prep_rs(const float* __restrict__ gamma,
                                                 const float* __restrict__ beta) {
    __shared__ float ssc[C0N], ssh[C0N];
    const int tid = threadIdx.x;
    {
        float mean = d_sum1[tid] * (1.0f / NP);
        float var  = d_sq1[tid] * (1.0f / NP) - mean * mean;
        float sc   = gamma[tid] * rsqrtf(var + BN_EPS);
        ssc[tid] = sc;
        ssh[tid] = beta[tid] - mean * sc;
    }
    __syncthreads();
    size_t i = ((size_t)blockIdx.x * 256 + tid) * 4;
    int c = (int)(i & (C0N - 1));
    int r = (int)(i >> 8);
    float4 h4 = *(const float4*)(d_H + i);
    float dg = d_deg[r];
    float idg = (dg > 0.5f) ? (4096.0f / dg) : 0.0f;
    __half o[4];
    o[0] = __float2half_rn(idg * fmaf(h4.x, ssc[c + 0], ssh[c + 0]));
    o[1] = __float2half_rn(idg * fmaf(h4.y, ssc[c + 1], ssh[c + 1]));
    o[2] = __float2half_rn(idg * fmaf(h4.z, ssc[c + 2], ssh[c + 2]));
    o[3] = __float2half_rn(idg * fmaf(h4.w, ssc[c + 3], ssh[c + 3]));
    *(uint2*)(d_Rs16 + i) = *(uint2*)o;
}

// ============================================================================
// small_r2 (tensor, single fp16): R2f = Rs16 @ K2f. grid 128: M-tile 64, K=256.
// ============================================================================
#define SR_LDA 264
#define SR_LDB 136
#define SR_A_BYTES (64 * SR_LDA * 2)
#define SR_B_BYTES (256 * SR_LDB * 2)
#define SR_SMEM    (SR_A_BYTES + SR_B_BYTES)   // 103424
#define SR_LDC 132

__global__ void __launch_bounds__(256) k_small_r2_tc() {
    extern __shared__ __align__(16) char sm[];
    __half (*As)[SR_LDA] = (__half(*)[SR_LDA])sm;
    __half (*Bs)[SR_LDB] = (__half(*)[SR_LDB])(sm + SR_A_BYTES);
    float  (*Ct)[SR_LDC] = (float(*)[SR_LDC])sm;

    const int m0  = blockIdx.x * 64;
    const int tid = threadIdx.x;
    const int warp = tid >> 5;
    const int wm   = warp & 1;
    const int wn   = warp >> 1;

#pragma unroll
    for (int s = 0; s < 8; s++) {
        int u = tid + s * 256, row = u >> 5, col = (u & 31) * 8;
        cp16(&As[row][col], d_Rs16 + (size_t)(m0 + row) * C0N + col);
    }
#pragma unroll
    for (int s = 0; s < 16; s++) {
        int u = tid + s * 256, kk = u >> 4, cc = (u & 15) * 8;
        cp16(&Bs[kk][cc], d_K2f + (size_t)kk * C1N + cc);
    }
    cp_commit();
    cp_wait<0>();
    __syncthreads();

    wmma::fragment<wmma::accumulator, 16, 16, 16, float> acc[2][2];
#pragma unroll
    for (int i = 0; i < 2; i++)
#pragma unroll
        for (int j = 0; j < 2; j++) wmma::fill_fragment(acc[i][j], 0.0f);

#pragma unroll
    for (int ks = 0; ks < 16; ks++) {
        wmma::fragment<wmma::matrix_a, 16, 16, 16, __half, wmma::row_major> af[2];
#pragma unroll
        for (int i = 0; i < 2; i++)
            wmma::load_matrix_sync(af[i], &As[wm * 32 + i * 16][ks * 16], SR_LDA);
        wmma::fragment<wmma::matrix_b, 16, 16, 16, __half, wmma::row_major> bf[2];
#pragma unroll
        for (int j = 0; j < 2; j++)
            wmma::load_matrix_sync(bf[j], &Bs[ks * 16][wn * 32 + j * 16], SR_LDB);
#pragma unroll
        for (int j = 0; j < 2; j++)
#pragma unroll
            for (int i = 0; i < 2; i++) wmma::mma_sync(acc[i][j], af[i], bf[j], acc[i][j]);
    }
    __syncthreads();

#pragma unroll
    for (int i = 0; i < 2; i++)
#pragma unroll
        for (int j = 0; j < 2; j++)
            wmma::store_matrix_sync(&Ct[wm * 32 + i * 16][wn * 32 + j * 16],
                                    acc[i][j], SR_LDC, wmma::mem_row_major);
    __syncthreads();

    {
        const int c    = tid & 127;
        const int half = tid >> 7;
#pragma unroll 8
        for (int r = half * 32; r < half * 32 + 32; r++)
            d_R2f[(size_t)(m0 + r) * C1N + c] = __float2half_rn(Ct[r][c]);
    }
}

// ------------- combine O partials (undo 4096 scale) + bias, BN2 stats --------
__global__ void __launch_bounds__(128) k_stats2(const float* __restrict__ bias2) {
    const int c  = threadIdx.x;
    const int r0 = blockIdx.x * 64;
    const float b = bias2[c];
    const float inv = 1.0f / 4096.0f;
    float s = 0.f, q = 0.f;
#pragma unroll 4
    for (int r = r0; r < r0 + 64; r++) {
        size_t idx = (size_t)r * C1N + c;
        float v = (d_Op[0][idx] + d_Op[1][idx] + d_Op[2][idx] + d_Op[3][idx]) * inv + b;
        d_O[idx] = v;
        s += v;
        q = fmaf(v, v, q);
    }
    atomicAdd(&d_sum2[c], s);
    atomicAdd(&d_sq2[c], q);
}

// ---------------- output with fin2 inlined -----------------------------------
__global__ void __launch_bounds__(256) k_out(const float* __restrict__ gamma,
                                             const float* __restrict__ beta,
                                             float* __restrict__ out) {
    __shared__ float ssc[C1N], ssh[C1N];
    const int tid = threadIdx.x;
    if (tid < C1N) {
        float mean = d_sum2[tid] * (1.0f / NP);
        float var  = d_sq2[tid] * (1.0f / NP) - mean * mean;
        float sc   = gamma[tid] * rsqrtf(var + BN_EPS);
        ssc[tid] = sc;
        ssh[tid] = beta[tid] - mean * sc;
    }
    __syncthreads();
    size_t i = ((size_t)blockIdx.x * 256 + tid) * 4;   // NP*C1N / 4 per thread
    int c = (int)(i & (C1N - 1));
    float4 v = *(const float4*)(d_O + i);
    float4 o;
    o.x = fmaf(v.x, ssc[c + 0], ssh[c + 0]);
    o.y = fmaf(v.y, ssc[c + 1], ssh[c + 1]);
    o.z = fmaf(v.z, ssc[c + 2], ssh[c + 2]);
    o.w = fmaf(v.w, ssc[c + 3], ssh[c + 3]);
    *(float4*)(out + i) = o;
}

// ---------------- launch ----------------------------------------------------
extern "C" void kernel_launch(void* const* d_in, const int* in_sizes, int n_in,
                              void* d_out, int out_size) {
    const float* features = (const float*)d_in[0];
    const int*   adj      = (const int*)d_in[1];
    const float* kernel_1 = (const float*)d_in[2];
    const float* bias_1   = (const float*)d_in[3];
    const float* gamma_1  = (const float*)d_in[4];
    const float* beta_1   = (const float*)d_in[5];
    const float* kernel_2 = (const float*)d_in[6];
    const float* bias_2   = (const float*)d_in[7];
    const float* gamma_2  = (const float*)d_in[8];
    const float* beta_2   = (const float*)d_in[9];
    float* out = (float*)d_out;

    cudaFuncSetAttribute(k_gemm1, cudaFuncAttributeMaxDynamicSharedMemorySize, G1_SMEM);
    cudaFuncSetAttribute(k_gemm3, cudaFuncAttributeMaxDynamicSharedMemorySize, G3_SMEM);
    cudaFuncSetAttribute(k_small_h_tc, cudaFuncAttributeMaxDynamicSharedMemorySize, SH_SMEM);
    cudaFuncSetAttribute(k_small_r2_tc, cudaFuncAttributeMaxDynamicSharedMemorySize, SR_SMEM);

    k_prep_x<<<NP * FD / (256 * 4), 256>>>(features);                   // X fp16 + zero
    k_prep_adj<<<dim3(NP / 128, NP / 128), 256>>>(adj);                 // adj fp16 + degree
    k_gemm1<<<dim3(NP / 256, KSPLIT), 256, G1_SMEM>>>();                // Rpre partials
    k_prep_rpre<<<NP * FD / (256 * 4), 256>>>(kernel_1, kernel_2);      // sum+split + K1/K2
    k_small_h_tc<<<dim3(NP / 64, C0N / 128), 256, SH_SMEM>>>(bias_1);   // H + stats1
    k_prep_rs<<<NP * C0N / (256 * 4), 256>>>(gamma_1, beta_1);          // fin1 + Rs16
    k_small_r2_tc<<<NP / 64, 256, SR_SMEM>>>();                         // R2f
    k_gemm3<<<dim3(NP / 256, KSPLIT), 256, G3_SMEM>>>();                // O partials
    k_stats2<<<NP / 64, 128>>>(bias_2);                                 // combine + stats2
    k_out<<<NP * C1N / (256 * 4), 256>>>(gamma_2, beta_2, out);         // fin2 + out
}